// round 3
// baseline (speedup 1.0000x reference)
#include <cuda_runtime.h>
#include <cuda_fp16.h>
#include <cuda_bf16.h>
#include <cuda_fp8.h>
#include <math.h>

// ---------------- problem constants ----------------
#define B_   2
#define S_   2048
#define H_   2048
#define NH   16
#define HD   128
#define H3   (3 * H_)
#define M1   (B_ * S_)
#define PLANE (B_ * NH * S_ * HD)

// ---------------- scratch ----------------
__device__ float         g_qkv[(size_t)M1 * H3];
__device__ unsigned char g_q8[(size_t)3 * PLANE];
__device__ float         g_scores[(size_t)B_ * NH * S_ * S_];
__device__ float         g_attnout[(size_t)M1 * H_];
__device__ unsigned int  g_absmax[3];
__device__ float         g_scales[3];

__device__ __forceinline__ unsigned short f8_to_h(unsigned char v) {
    __half_raw hr = __nv_cvt_fp8_to_halfraw(v, __NV_E4M3);
    return hr.x;
}

__device__ __forceinline__ void mma_f16(float& d0, float& d1, float& d2, float& d3,
                                        unsigned a0, unsigned a1, unsigned a2, unsigned a3,
                                        unsigned b0, unsigned b1) {
    asm volatile("mma.sync.aligned.m16n8k16.row.col.f32.f16.f16.f32 "
                 "{%0,%1,%2,%3}, {%4,%5,%6,%7}, {%8,%9}, {%0,%1,%2,%3};"
                 : "+f"(d0), "+f"(d1), "+f"(d2), "+f"(d3)
                 : "r"(a0), "r"(a1), "r"(a2), "r"(a3), "r"(b0), "r"(b1));
}

__device__ __forceinline__ void mma_bf16(float& d0, float& d1, float& d2, float& d3,
                                         unsigned a0, unsigned a1, unsigned a2, unsigned a3,
                                         unsigned b0, unsigned b1) {
    asm volatile("mma.sync.aligned.m16n8k16.row.col.f32.bf16.bf16.f32 "
                 "{%0,%1,%2,%3}, {%4,%5,%6,%7}, {%8,%9}, {%0,%1,%2,%3};"
                 : "+f"(d0), "+f"(d1), "+f"(d2), "+f"(d3)
                 : "r"(a0), "r"(a1), "r"(a2), "r"(a3), "r"(b0), "r"(b1));
}

__global__ void zero_kernel() {
    if (threadIdx.x < 3) g_absmax[threadIdx.x] = 0u;
}

// ============ bf16x3 GEMM: C[M,N] = A[M,K] @ B[K,N] (+bias), fp32 fidelity ======
// 128x128 block tile, K-step 16, double-buffered, 8 warps (2x4), warp = 64x32.
// Each fp32 operand split into bf16 hi + bf16 lo; 3 MMAs per logical product.
__global__ __launch_bounds__(256) void bgemm128(
    const float* __restrict__ A, const float* __restrict__ Bm,
    float* __restrict__ C, int M, int N, int K, const float* __restrict__ bias)
{
    __shared__ __nv_bfloat16 Ah[2][128][24], Al[2][128][24];   // [m][k]
    __shared__ __nv_bfloat16 Bh[2][128][24], Bl[2][128][24];   // [n][k] (transposed)

    const int tid = threadIdx.x;
    const int wid = tid >> 5, lane = tid & 31;
    const int g = lane >> 2, tig = lane & 3;
    const int m0 = blockIdx.y * 128, n0 = blockIdx.x * 128;
    const int wm = (wid & 1) * 64, wn = (wid >> 1) * 32;

    // A loader: 128x16 f32 = 512 float4; thread handles lin = tid, tid+256
    const int ar0 = tid >> 2,          ac0 = (tid & 3) << 2;
    const int ar1 = (tid + 256) >> 2,  ac1 = ((tid + 256) & 3) << 2;
    // B loader: 16x128 f32 = 512 float4; row = k, col = n
    const int br0 = tid >> 5,          bc0 = (tid & 31) << 2;
    const int br1 = (tid + 256) >> 5,  bc1 = ((tid + 256) & 31) << 2;

    float acc[4][4][4] = {};
    float4 pa0, pa1, pb0, pb1;

    auto split_store_A = [&](int buf, int r, int c, float4 v) {
        float vv[4] = {v.x, v.y, v.z, v.w};
        #pragma unroll
        for (int j = 0; j < 4; ++j) {
            __nv_bfloat16 h = __float2bfloat16_rn(vv[j]);
            __nv_bfloat16 l = __float2bfloat16_rn(vv[j] - __bfloat162float(h));
            Ah[buf][r][c + j] = h;
            Al[buf][r][c + j] = l;
        }
    };
    auto split_store_B = [&](int buf, int r, int c, float4 v) {   // transpose: [n][k]
        float vv[4] = {v.x, v.y, v.z, v.w};
        #pragma unroll
        for (int j = 0; j < 4; ++j) {
            __nv_bfloat16 h = __float2bfloat16_rn(vv[j]);
            __nv_bfloat16 l = __float2bfloat16_rn(vv[j] - __bfloat162float(h));
            Bh[buf][c + j][r] = h;
            Bl[buf][c + j][r] = l;
        }
    };

    // preload stage 0
    pa0 = *(const float4*)&A[(size_t)(m0 + ar0) * K + ac0];
    pa1 = *(const float4*)&A[(size_t)(m0 + ar1) * K + ac1];
    pb0 = *(const float4*)&Bm[(size_t)br0 * N + n0 + bc0];
    pb1 = *(const float4*)&Bm[(size_t)br1 * N + n0 + bc1];
    split_store_A(0, ar0, ac0, pa0);
    split_store_A(0, ar1, ac1, pa1);
    split_store_B(0, br0, bc0, pb0);
    split_store_B(0, br1, bc1, pb1);
    __syncthreads();

    const int T = K >> 4;
    int buf = 0;
    for (int t = 0; t < T; ++t) {
        if (t + 1 < T) {
            int k0 = (t + 1) << 4;
            pa0 = *(const float4*)&A[(size_t)(m0 + ar0) * K + k0 + ac0];
            pa1 = *(const float4*)&A[(size_t)(m0 + ar1) * K + k0 + ac1];
            pb0 = *(const float4*)&Bm[(size_t)(k0 + br0) * N + n0 + bc0];
            pb1 = *(const float4*)&Bm[(size_t)(k0 + br1) * N + n0 + bc1];
        }

        unsigned ah[4][4], al[4][4], bh[4][2], bl[4][2];
        #pragma unroll
        for (int mi = 0; mi < 4; ++mi) {
            int r = wm + mi * 16 + g;
            ah[mi][0] = *(unsigned*)&Ah[buf][r][2 * tig];
            ah[mi][1] = *(unsigned*)&Ah[buf][r + 8][2 * tig];
            ah[mi][2] = *(unsigned*)&Ah[buf][r][2 * tig + 8];
            ah[mi][3] = *(unsigned*)&Ah[buf][r + 8][2 * tig + 8];
            al[mi][0] = *(unsigned*)&Al[buf][r][2 * tig];
            al[mi][1] = *(unsigned*)&Al[buf][r + 8][2 * tig];
            al[mi][2] = *(unsigned*)&Al[buf][r][2 * tig + 8];
            al[mi][3] = *(unsigned*)&Al[buf][r + 8][2 * tig + 8];
        }
        #pragma unroll
        for (int ni = 0; ni < 4; ++ni) {
            int r = wn + ni * 8 + g;
            bh[ni][0] = *(unsigned*)&Bh[buf][r][2 * tig];
            bh[ni][1] = *(unsigned*)&Bh[buf][r][2 * tig + 8];
            bl[ni][0] = *(unsigned*)&Bl[buf][r][2 * tig];
            bl[ni][1] = *(unsigned*)&Bl[buf][r][2 * tig + 8];
        }
        #pragma unroll
        for (int mi = 0; mi < 4; ++mi)
            #pragma unroll
            for (int ni = 0; ni < 4; ++ni) {
                float* d = acc[mi][ni];
                mma_bf16(d[0], d[1], d[2], d[3],
                         ah[mi][0], ah[mi][1], ah[mi][2], ah[mi][3], bh[ni][0], bh[ni][1]);
                mma_bf16(d[0], d[1], d[2], d[3],
                         ah[mi][0], ah[mi][1], ah[mi][2], ah[mi][3], bl[ni][0], bl[ni][1]);
                mma_bf16(d[0], d[1], d[2], d[3],
                         al[mi][0], al[mi][1], al[mi][2], al[mi][3], bh[ni][0], bh[ni][1]);
            }

        if (t + 1 < T) {
            __syncthreads();
            int nb = buf ^ 1;
            split_store_A(nb, ar0, ac0, pa0);
            split_store_A(nb, ar1, ac1, pa1);
            split_store_B(nb, br0, bc0, pb0);
            split_store_B(nb, br1, bc1, pb1);
            __syncthreads();
            buf = nb;
        }
    }

    #pragma unroll
    for (int mi = 0; mi < 4; ++mi) {
        int r = m0 + wm + mi * 16 + g;
        #pragma unroll
        for (int ni = 0; ni < 4; ++ni) {
            int c = n0 + wn + ni * 8 + 2 * tig;
            float2 v0 = {acc[mi][ni][0], acc[mi][ni][1]};
            float2 v1 = {acc[mi][ni][2], acc[mi][ni][3]};
            if (bias) {
                v0.x += bias[c]; v0.y += bias[c + 1];
                v1.x += bias[c]; v1.y += bias[c + 1];
            }
            *(float2*)&C[(size_t)r * N + c] = v0;
            *(float2*)&C[(size_t)(r + 8) * N + c] = v1;
        }
    }
}

// ---------------- abs-max / scales / quant ----------------
__global__ void absmax_kernel() {
    __shared__ unsigned int sm[3];
    if (threadIdx.x < 3) sm[threadIdx.x] = 0u;
    __syncthreads();
    const int gtid = blockIdx.x * blockDim.x + threadIdx.x;
    const int stride = gridDim.x * blockDim.x;
    const int n2 = M1 * H_;
    #pragma unroll
    for (int t = 0; t < 3; ++t) {
        unsigned int lm = 0u;
        for (int i = gtid; i < n2; i += stride) {
            int r = i >> 11, c = i & 2047;
            unsigned int b = __float_as_uint(fabsf(g_qkv[(size_t)r * H3 + t * H_ + c]));
            lm = (b > lm) ? b : lm;
        }
        atomicMax(&sm[t], lm);
    }
    __syncthreads();
    if (threadIdx.x < 3) atomicMax(&g_absmax[threadIdx.x], sm[threadIdx.x]);
}

__global__ void scales_kernel() {
    if (threadIdx.x < 3)
        g_scales[threadIdx.x] = __uint_as_float(g_absmax[threadIdx.x]) / 448.0f;
}

__global__ void quant_kernel() {
    int idx = blockIdx.x * blockDim.x + threadIdx.x;
    if (idx >= 3 * PLANE) return;
    int t = idx / PLANE;
    int rem = idx - t * PLANE;
    int d = rem & 127;
    int s = (rem >> 7) & 2047;
    int bh = rem >> 18;
    int b = bh >> 4, h = bh & 15;
    float v = g_qkv[(size_t)(b * S_ + s) * H3 + t * H_ + h * HD + d];
    g_q8[idx] = __nv_cvt_float_to_fp8(v / g_scales[t], __NV_SATFINITE, __NV_E4M3);
}

// ---------------- scores via fp16 MMA (exact: e4m3 subset of fp16) --------------
__global__ __launch_bounds__(256) void scores_mma_kernel() {
    __shared__ __half qs[128][72];
    __shared__ __half ks[128][72];
    const int tid = threadIdx.x;
    const int wid = tid >> 5, lane = tid & 31;
    const int g = lane >> 2, tig = lane & 3;
    const int bh = blockIdx.z;
    const int m0 = blockIdx.y * 128, n0 = blockIdx.x * 128;
    const unsigned char* qp = g_q8 + (size_t)bh * (S_ * HD);
    const unsigned char* kp = g_q8 + (size_t)PLANE + (size_t)bh * (S_ * HD);
    const int wm = (wid & 1) * 64, wn = (wid >> 1) * 32;

    float acc[4][4][4] = {};

    for (int ch = 0; ch < 2; ++ch) {
        const int coff = ch * 64;
        #pragma unroll
        for (int p = 0; p < 8; ++p) {
            int lin = tid + p * 256;
            int r = lin >> 4, c = (lin & 15) << 2;
            unsigned int qv = *(const unsigned int*)&qp[(size_t)(m0 + r) * HD + coff + c];
            unsigned int kv = *(const unsigned int*)&kp[(size_t)(n0 + r) * HD + coff + c];
            unsigned int q01 = (unsigned)f8_to_h(qv & 0xff) | ((unsigned)f8_to_h((qv >> 8) & 0xff) << 16);
            unsigned int q23 = (unsigned)f8_to_h((qv >> 16) & 0xff) | ((unsigned)f8_to_h(qv >> 24) << 16);
            unsigned int k01 = (unsigned)f8_to_h(kv & 0xff) | ((unsigned)f8_to_h((kv >> 8) & 0xff) << 16);
            unsigned int k23 = (unsigned)f8_to_h((kv >> 16) & 0xff) | ((unsigned)f8_to_h(kv >> 24) << 16);
            *(unsigned int*)&qs[r][c + 0] = q01;
            *(unsigned int*)&qs[r][c + 2] = q23;
            *(unsigned int*)&ks[r][c + 0] = k01;
            *(unsigned int*)&ks[r][c + 2] = k23;
        }
        __syncthreads();

        #pragma unroll
        for (int kstep = 0; kstep < 4; ++kstep) {
            const int kb = kstep * 16;
            unsigned a[4][4], b[4][2];
            #pragma unroll
            for (int mi = 0; mi < 4; ++mi) {
                int r = wm + mi * 16 + g;
                a[mi][0] = *(unsigned*)&qs[r][kb + 2 * tig];
                a[mi][1] = *(unsigned*)&qs[r + 8][kb + 2 * tig];
                a[mi][2] = *(unsigned*)&qs[r][kb + 2 * tig + 8];
                a[mi][3] = *(unsigned*)&qs[r + 8][kb + 2 * tig + 8];
            }
            #pragma unroll
            for (int ni = 0; ni < 4; ++ni) {
                int r = wn + ni * 8 + g;
                b[ni][0] = *(unsigned*)&ks[r][kb + 2 * tig];
                b[ni][1] = *(unsigned*)&ks[r][kb + 2 * tig + 8];
            }
            #pragma unroll
            for (int mi = 0; mi < 4; ++mi)
                #pragma unroll
                for (int ni = 0; ni < 4; ++ni)
                    mma_f16(acc[mi][ni][0], acc[mi][ni][1], acc[mi][ni][2], acc[mi][ni][3],
                            a[mi][0], a[mi][1], a[mi][2], a[mi][3], b[ni][0], b[ni][1]);
        }
        __syncthreads();
    }

    const float f = g_scales[0] * g_scales[1] * 0.08838834764831843f;
    float* out = g_scores + (size_t)bh * S_ * S_;
    #pragma unroll
    for (int mi = 0; mi < 4; ++mi) {
        int r = m0 + wm + mi * 16 + g;
        #pragma unroll
        for (int ni = 0; ni < 4; ++ni) {
            int c = n0 + wn + ni * 8 + 2 * tig;
            float2 v0 = {acc[mi][ni][0] * f, acc[mi][ni][1] * f};
            float2 v1 = {acc[mi][ni][2] * f, acc[mi][ni][3] * f};
            *(float2*)&out[(size_t)r * S_ + c] = v0;
            *(float2*)&out[(size_t)(r + 8) * S_ + c] = v1;
        }
    }
}

// ---------------- softmax ----------------
__global__ void softmax_kernel() {
    const int row = blockIdx.x;
    float* p = g_scores + (size_t)row * S_;
    const int tid = threadIdx.x;
    float v[8];
    float mx = -INFINITY;
    #pragma unroll
    for (int e = 0; e < 8; ++e) { v[e] = p[tid + e * 256]; mx = fmaxf(mx, v[e]); }
    #pragma unroll
    for (int o = 16; o; o >>= 1) mx = fmaxf(mx, __shfl_xor_sync(0xffffffffu, mx, o));
    __shared__ float smax[8];
    if ((tid & 31) == 0) smax[tid >> 5] = mx;
    __syncthreads();
    mx = smax[0];
    #pragma unroll
    for (int w = 1; w < 8; ++w) mx = fmaxf(mx, smax[w]);
    float sum = 0.0f;
    #pragma unroll
    for (int e = 0; e < 8; ++e) { v[e] = expf(v[e] - mx); sum += v[e]; }
    #pragma unroll
    for (int o = 16; o; o >>= 1) sum += __shfl_xor_sync(0xffffffffu, sum, o);
    __shared__ float ssum[8];
    if ((tid & 31) == 0) ssum[tid >> 5] = sum;
    __syncthreads();
    sum = 0.0f;
    #pragma unroll
    for (int w = 0; w < 8; ++w) sum += ssum[w];
    #pragma unroll
    for (int e = 0; e < 8; ++e) p[tid + e * 256] = v[e] / sum;
}

// ---------------- PV via fp16 MMA ----------------
__global__ __launch_bounds__(256) void pv_mma_kernel() {
    __shared__ __half ps[64][72];
    __shared__ __half vt[128][72];
    const int tid = threadIdx.x;
    const int wid = tid >> 5, lane = tid & 31;
    const int g = lane >> 2, tig = lane & 3;
    const int bh = blockIdx.y;
    const int b = bh >> 4, h = bh & 15;
    const int i0 = blockIdx.x * 64;
    const float* ap = g_scores + (size_t)bh * S_ * S_;
    const unsigned char* vp = g_q8 + (size_t)2 * PLANE + (size_t)bh * (S_ * HD);
    const int wm = (wid & 1) * 32, wn = (wid >> 1) * 32;

    float acc[2][4][4] = {};

    for (int kc = 0; kc < S_; kc += 32) {
        #pragma unroll
        for (int p = 0; p < 2; ++p) {
            int lin = tid + p * 256;
            int r = lin >> 3, c = (lin & 7) << 2;
            float4 vv = *(const float4*)&ap[(size_t)(i0 + r) * S_ + kc + c];
            __half2 h0 = __floats2half2_rn(vv.x, vv.y);
            __half2 h1 = __floats2half2_rn(vv.z, vv.w);
            *(__half2*)&ps[r][c + 0] = h0;
            *(__half2*)&ps[r][c + 2] = h1;
        }
        #pragma unroll
        for (int p = 0; p < 4; ++p) {
            int lin = tid + p * 256;
            int r = lin >> 5, c = (lin & 31) << 2;
            unsigned int vv = *(const unsigned int*)&vp[(size_t)(kc + r) * HD + c];
            vt[c + 0][r] = __ushort_as_half(f8_to_h(vv & 0xff));
            vt[c + 1][r] = __ushort_as_half(f8_to_h((vv >> 8) & 0xff));
            vt[c + 2][r] = __ushort_as_half(f8_to_h((vv >> 16) & 0xff));
            vt[c + 3][r] = __ushort_as_half(f8_to_h(vv >> 24));
        }
        __syncthreads();

        #pragma unroll
        for (int kstep = 0; kstep < 2; ++kstep) {
            const int kb = kstep * 16;
            unsigned a[2][4], bfr[4][2];
            #pragma unroll
            for (int mi = 0; mi < 2; ++mi) {
                int r = wm + mi * 16 + g;
                a[mi][0] = *(unsigned*)&ps[r][kb + 2 * tig];
                a[mi][1] = *(unsigned*)&ps[r + 8][kb + 2 * tig];
                a[mi][2] = *(unsigned*)&ps[r][kb + 2 * tig + 8];
                a[mi][3] = *(unsigned*)&ps[r + 8][kb + 2 * tig + 8];
            }
            #pragma unroll
            for (int ni = 0; ni < 4; ++ni) {
                int r = wn + ni * 8 + g;
                bfr[ni][0] = *(unsigned*)&vt[r][kb + 2 * tig];
                bfr[ni][1] = *(unsigned*)&vt[r][kb + 2 * tig + 8];
            }
            #pragma unroll
            for (int mi = 0; mi < 2; ++mi)
                #pragma unroll
                for (int ni = 0; ni < 4; ++ni)
                    mma_f16(acc[mi][ni][0], acc[mi][ni][1], acc[mi][ni][2], acc[mi][ni][3],
                            a[mi][0], a[mi][1], a[mi][2], a[mi][3], bfr[ni][0], bfr[ni][1]);
        }
        __syncthreads();
    }

    const float vsc = g_scales[2];
    #pragma unroll
    for (int mi = 0; mi < 2; ++mi) {
        int s = i0 + wm + mi * 16 + g;
        #pragma unroll
        for (int ni = 0; ni < 4; ++ni) {
            int d = wn + ni * 8 + 2 * tig;
            float2 v0 = {acc[mi][ni][0] * vsc, acc[mi][ni][1] * vsc};
            float2 v1 = {acc[mi][ni][2] * vsc, acc[mi][ni][3] * vsc};
            *(float2*)&g_attnout[(size_t)(b * S_ + s) * H_ + h * HD + d] = v0;
            *(float2*)&g_attnout[(size_t)(b * S_ + s + 8) * H_ + h * HD + d] = v1;
        }
    }
}

// ---------------- launch ----------------
extern "C" void kernel_launch(void* const* d_in, const int* in_sizes, int n_in,
                              void* d_out, int out_size)
{
    const float* x    = (const float*)d_in[0];
    const float* Wqkv = (const float*)d_in[1];
    const float* Wout = (const float*)d_in[2];
    const float* bout = (const float*)d_in[3];
    float* y = (float*)d_out;

    float *qkv_ptr = nullptr, *ao_ptr = nullptr;
    cudaGetSymbolAddress((void**)&qkv_ptr, g_qkv);
    cudaGetSymbolAddress((void**)&ao_ptr,  g_attnout);

    zero_kernel<<<1, 32>>>();

    // 1) qkv = x @ W_qkv  (bf16x3 tensor-core, fp32 fidelity)
    bgemm128<<<dim3(H3 / 128, M1 / 128), 256>>>(x, Wqkv, qkv_ptr, M1, H3, H_, nullptr);

    // 2) per-tensor abs-max + scales
    absmax_kernel<<<1184, 256>>>();
    scales_kernel<<<1, 32>>>();

    // 3) quantize q/k/v to fp8 in head-major layout
    quant_kernel<<<(3 * PLANE) / 256, 256>>>();

    // 4) scores = q8 @ k8^T (fp16 MMA, exact)
    scores_mma_kernel<<<dim3(S_ / 128, S_ / 128, B_ * NH), 256>>>();

    // 5) softmax over keys
    softmax_kernel<<<B_ * NH * S_, 256>>>();

    // 6) out = (attn_f16 @ v8_f16) * v_scale
    pv_mma_kernel<<<dim3(S_ / 64, B_ * NH), 256>>>();

    // 7) y = out @ W_out + b_out  (bf16x3)
    bgemm128<<<dim3(H_ / 128, M1 / 128), 256>>>(ao_ptr, Wout, y, M1, H_, H_, bout);
}

// round 4
// speedup vs baseline: 2.9091x; 2.9091x over previous
#include <cuda_runtime.h>
#include <cuda_fp16.h>
#include <cuda_fp8.h>
#include <math.h>

// ---------------- problem constants ----------------
#define B_   2
#define S_   2048
#define H_   2048
#define NH   16
#define HD   128
#define H3   (3 * H_)
#define M1   (B_ * S_)
#define PLANE (B_ * NH * S_ * HD)

// ---------------- scratch ----------------
__device__ float         g_qkv[(size_t)M1 * H3];
__device__ unsigned char g_q8[(size_t)3 * PLANE];
__device__ float         g_scores[(size_t)B_ * NH * S_ * S_];
__device__ float         g_attnout[(size_t)M1 * H_];
__device__ unsigned int  g_absmax[3];
__device__ float         g_scales[3];

__device__ __forceinline__ unsigned short f8_to_h(unsigned char v) {
    __half_raw hr = __nv_cvt_fp8_to_halfraw(v, __NV_E4M3);
    return hr.x;
}

__device__ __forceinline__ void mma_f16(float& d0, float& d1, float& d2, float& d3,
                                        unsigned a0, unsigned a1, unsigned a2, unsigned a3,
                                        unsigned b0, unsigned b1) {
    asm volatile("mma.sync.aligned.m16n8k16.row.col.f32.f16.f16.f32 "
                 "{%0,%1,%2,%3}, {%4,%5,%6,%7}, {%8,%9}, {%0,%1,%2,%3};"
                 : "+f"(d0), "+f"(d1), "+f"(d2), "+f"(d3)
                 : "r"(a0), "r"(a1), "r"(a2), "r"(a3), "r"(b0), "r"(b1));
}

__global__ void zero_kernel() {
    if (threadIdx.x < 3) g_absmax[threadIdx.x] = 0u;
}

// ============ fp16x3 GEMM: C = A @ B (+bias), fp32 fidelity via hi/lo split =====
// 128x128 block tile, K-step 32, 8 warps (2x4), warp tile 64x32.
// A split into half hi/lo at smem-fill time (contiguous stores, no transpose).
// B kept fp32 in smem [k][n]; fragments read + split in registers (conflict-free).
__global__ __launch_bounds__(256) void hgemm_x3(
    const float* __restrict__ A, const float* __restrict__ Bm,
    float* __restrict__ C, int M, int N, int K, const float* __restrict__ bias)
{
    __shared__ __half Ah[128][40];   // [m][k], stride 20 words -> conflict-free frags
    __shared__ __half Al[128][40];
    __shared__ float  Bs[32][132];   // [k][n] fp32

    const int tid = threadIdx.x;
    const int wid = tid >> 5, lane = tid & 31;
    const int g = lane >> 2, tig = lane & 3;
    const int m0 = blockIdx.y * 128, n0 = blockIdx.x * 128;
    const int wm = (wid & 1) * 64, wn = (wid >> 1) * 32;

    float acc[4][4][4] = {};

    // loader indices: A tile 128x32 = 1024 float4; B tile 32x128 = 1024 float4
    int aR[4], aC[4], bR[4], bC[4];
    #pragma unroll
    for (int p = 0; p < 4; ++p) {
        int lin = tid + p * 256;
        aR[p] = lin >> 3; aC[p] = (lin & 7) << 2;
        bR[p] = lin >> 5; bC[p] = (lin & 31) << 2;
    }

    auto store_A = [&](int p, float4 v) {
        float vv[4] = {v.x, v.y, v.z, v.w};
        __half h[4], l[4];
        #pragma unroll
        for (int j = 0; j < 4; ++j) {
            h[j] = __float2half_rn(vv[j]);
            l[j] = __float2half_rn(vv[j] - __half2float(h[j]));
        }
        *(__half2*)&Ah[aR[p]][aC[p] + 0] = __halves2half2(h[0], h[1]);
        *(__half2*)&Ah[aR[p]][aC[p] + 2] = __halves2half2(h[2], h[3]);
        *(__half2*)&Al[aR[p]][aC[p] + 0] = __halves2half2(l[0], l[1]);
        *(__half2*)&Al[aR[p]][aC[p] + 2] = __halves2half2(l[2], l[3]);
    };

    float4 pa[4], pb[4];
    #pragma unroll
    for (int p = 0; p < 4; ++p) {
        pa[p] = *(const float4*)&A[(size_t)(m0 + aR[p]) * K + aC[p]];
        pb[p] = *(const float4*)&Bm[(size_t)bR[p] * N + n0 + bC[p]];
    }
    #pragma unroll
    for (int p = 0; p < 4; ++p) {
        store_A(p, pa[p]);
        *(float4*)&Bs[bR[p]][bC[p]] = pb[p];
    }
    __syncthreads();

    const int T = K >> 5;
    for (int t = 0; t < T; ++t) {
        if (t + 1 < T) {
            int k0 = (t + 1) << 5;
            #pragma unroll
            for (int p = 0; p < 4; ++p) {
                pa[p] = *(const float4*)&A[(size_t)(m0 + aR[p]) * K + k0 + aC[p]];
                pb[p] = *(const float4*)&Bm[(size_t)(k0 + bR[p]) * N + n0 + bC[p]];
            }
        }

        #pragma unroll
        for (int ks = 0; ks < 2; ++ks) {
            const int kb = ks * 16;
            unsigned ah[4][4], al[4][4], bh[4][2], bl[4][2];
            #pragma unroll
            for (int mi = 0; mi < 4; ++mi) {
                int r = wm + mi * 16 + g;
                #pragma unroll
                for (int q = 0; q < 4; ++q) {
                    int rr = r + (q & 1) * 8;
                    int kk = kb + 2 * tig + (q >> 1) * 8;
                    ah[mi][q] = *(unsigned*)&Ah[rr][kk];
                    al[mi][q] = *(unsigned*)&Al[rr][kk];
                }
            }
            #pragma unroll
            for (int ni = 0; ni < 4; ++ni) {
                int c = wn + ni * 8 + g;
                #pragma unroll
                for (int q = 0; q < 2; ++q) {
                    int kk = kb + 2 * tig + q * 8;
                    float f0 = Bs[kk][c], f1 = Bs[kk + 1][c];
                    __half h0 = __float2half_rn(f0), h1 = __float2half_rn(f1);
                    __half l0 = __float2half_rn(f0 - __half2float(h0));
                    __half l1 = __float2half_rn(f1 - __half2float(h1));
                    __half2 hh = __halves2half2(h0, h1);
                    __half2 ll = __halves2half2(l0, l1);
                    bh[ni][q] = *(unsigned*)&hh;
                    bl[ni][q] = *(unsigned*)&ll;
                }
            }
            #pragma unroll
            for (int mi = 0; mi < 4; ++mi)
                #pragma unroll
                for (int ni = 0; ni < 4; ++ni) {
                    float* d = acc[mi][ni];
                    mma_f16(d[0], d[1], d[2], d[3],
                            ah[mi][0], ah[mi][1], ah[mi][2], ah[mi][3], bh[ni][0], bh[ni][1]);
                    mma_f16(d[0], d[1], d[2], d[3],
                            ah[mi][0], ah[mi][1], ah[mi][2], ah[mi][3], bl[ni][0], bl[ni][1]);
                    mma_f16(d[0], d[1], d[2], d[3],
                            al[mi][0], al[mi][1], al[mi][2], al[mi][3], bh[ni][0], bh[ni][1]);
                }
        }

        if (t + 1 < T) {
            __syncthreads();
            #pragma unroll
            for (int p = 0; p < 4; ++p) {
                store_A(p, pa[p]);
                *(float4*)&Bs[bR[p]][bC[p]] = pb[p];
            }
            __syncthreads();
        }
    }

    #pragma unroll
    for (int mi = 0; mi < 4; ++mi) {
        int r = m0 + wm + mi * 16 + g;
        #pragma unroll
        for (int ni = 0; ni < 4; ++ni) {
            int c = n0 + wn + ni * 8 + 2 * tig;
            float2 v0 = {acc[mi][ni][0], acc[mi][ni][1]};
            float2 v1 = {acc[mi][ni][2], acc[mi][ni][3]};
            if (bias) {
                float b0 = bias[c], b1 = bias[c + 1];
                v0.x += b0; v0.y += b1;
                v1.x += b0; v1.y += b1;
            }
            *(float2*)&C[(size_t)r * N + c] = v0;
            *(float2*)&C[(size_t)(r + 8) * N + c] = v1;
        }
    }
}

// ---------------- abs-max / scales / quant ----------------
__global__ void absmax_kernel() {
    __shared__ unsigned int sm[3];
    if (threadIdx.x < 3) sm[threadIdx.x] = 0u;
    __syncthreads();
    const int gtid = blockIdx.x * blockDim.x + threadIdx.x;
    const int stride = gridDim.x * blockDim.x;
    const int n2 = M1 * H_;
    #pragma unroll
    for (int t = 0; t < 3; ++t) {
        unsigned int lm = 0u;
        for (int i = gtid; i < n2; i += stride) {
            int r = i >> 11, c = i & 2047;
            unsigned int b = __float_as_uint(fabsf(g_qkv[(size_t)r * H3 + t * H_ + c]));
            lm = (b > lm) ? b : lm;
        }
        atomicMax(&sm[t], lm);
    }
    __syncthreads();
    if (threadIdx.x < 3) atomicMax(&g_absmax[threadIdx.x], sm[threadIdx.x]);
}

__global__ void scales_kernel() {
    if (threadIdx.x < 3)
        g_scales[threadIdx.x] = __uint_as_float(g_absmax[threadIdx.x]) / 448.0f;
}

__global__ void quant_kernel() {
    int idx = blockIdx.x * blockDim.x + threadIdx.x;
    if (idx >= 3 * PLANE) return;
    int t = idx / PLANE;
    int rem = idx - t * PLANE;
    int d = rem & 127;
    int s = (rem >> 7) & 2047;
    int bh = rem >> 18;
    int b = bh >> 4, h = bh & 15;
    float v = g_qkv[(size_t)(b * S_ + s) * H3 + t * H_ + h * HD + d];
    g_q8[idx] = __nv_cvt_float_to_fp8(v / g_scales[t], __NV_SATFINITE, __NV_E4M3);
}

// ---------------- scores via fp16 MMA (exact: e4m3 subset of fp16) --------------
__global__ __launch_bounds__(256) void scores_mma_kernel() {
    __shared__ __half qs[128][72];
    __shared__ __half ks[128][72];
    const int tid = threadIdx.x;
    const int wid = tid >> 5, lane = tid & 31;
    const int g = lane >> 2, tig = lane & 3;
    const int bh = blockIdx.z;
    const int m0 = blockIdx.y * 128, n0 = blockIdx.x * 128;
    const unsigned char* qp = g_q8 + (size_t)bh * (S_ * HD);
    const unsigned char* kp = g_q8 + (size_t)PLANE + (size_t)bh * (S_ * HD);
    const int wm = (wid & 1) * 64, wn = (wid >> 1) * 32;

    float acc[4][4][4] = {};

    for (int ch = 0; ch < 2; ++ch) {
        const int coff = ch * 64;
        #pragma unroll
        for (int p = 0; p < 8; ++p) {
            int lin = tid + p * 256;
            int r = lin >> 4, c = (lin & 15) << 2;
            unsigned int qv = *(const unsigned int*)&qp[(size_t)(m0 + r) * HD + coff + c];
            unsigned int kv = *(const unsigned int*)&kp[(size_t)(n0 + r) * HD + coff + c];
            unsigned int q01 = (unsigned)f8_to_h(qv & 0xff) | ((unsigned)f8_to_h((qv >> 8) & 0xff) << 16);
            unsigned int q23 = (unsigned)f8_to_h((qv >> 16) & 0xff) | ((unsigned)f8_to_h(qv >> 24) << 16);
            unsigned int k01 = (unsigned)f8_to_h(kv & 0xff) | ((unsigned)f8_to_h((kv >> 8) & 0xff) << 16);
            unsigned int k23 = (unsigned)f8_to_h((kv >> 16) & 0xff) | ((unsigned)f8_to_h(kv >> 24) << 16);
            *(unsigned int*)&qs[r][c + 0] = q01;
            *(unsigned int*)&qs[r][c + 2] = q23;
            *(unsigned int*)&ks[r][c + 0] = k01;
            *(unsigned int*)&ks[r][c + 2] = k23;
        }
        __syncthreads();

        #pragma unroll
        for (int kstep = 0; kstep < 4; ++kstep) {
            const int kb = kstep * 16;
            unsigned a[4][4], b[4][2];
            #pragma unroll
            for (int mi = 0; mi < 4; ++mi) {
                int r = wm + mi * 16 + g;
                a[mi][0] = *(unsigned*)&qs[r][kb + 2 * tig];
                a[mi][1] = *(unsigned*)&qs[r + 8][kb + 2 * tig];
                a[mi][2] = *(unsigned*)&qs[r][kb + 2 * tig + 8];
                a[mi][3] = *(unsigned*)&qs[r + 8][kb + 2 * tig + 8];
            }
            #pragma unroll
            for (int ni = 0; ni < 4; ++ni) {
                int r = wn + ni * 8 + g;
                b[ni][0] = *(unsigned*)&ks[r][kb + 2 * tig];
                b[ni][1] = *(unsigned*)&ks[r][kb + 2 * tig + 8];
            }
            #pragma unroll
            for (int mi = 0; mi < 4; ++mi)
                #pragma unroll
                for (int ni = 0; ni < 4; ++ni)
                    mma_f16(acc[mi][ni][0], acc[mi][ni][1], acc[mi][ni][2], acc[mi][ni][3],
                            a[mi][0], a[mi][1], a[mi][2], a[mi][3], b[ni][0], b[ni][1]);
        }
        __syncthreads();
    }

    const float f = g_scales[0] * g_scales[1] * 0.08838834764831843f;
    float* out = g_scores + (size_t)bh * S_ * S_;
    #pragma unroll
    for (int mi = 0; mi < 4; ++mi) {
        int r = m0 + wm + mi * 16 + g;
        #pragma unroll
        for (int ni = 0; ni < 4; ++ni) {
            int c = n0 + wn + ni * 8 + 2 * tig;
            float2 v0 = {acc[mi][ni][0] * f, acc[mi][ni][1] * f};
            float2 v1 = {acc[mi][ni][2] * f, acc[mi][ni][3] * f};
            *(float2*)&out[(size_t)r * S_ + c] = v0;
            *(float2*)&out[(size_t)(r + 8) * S_ + c] = v1;
        }
    }
}

// ---------------- softmax ----------------
__global__ void softmax_kernel() {
    const int row = blockIdx.x;
    float* p = g_scores + (size_t)row * S_;
    const int tid = threadIdx.x;
    float v[8];
    float mx = -INFINITY;
    #pragma unroll
    for (int e = 0; e < 8; ++e) { v[e] = p[tid + e * 256]; mx = fmaxf(mx, v[e]); }
    #pragma unroll
    for (int o = 16; o; o >>= 1) mx = fmaxf(mx, __shfl_xor_sync(0xffffffffu, mx, o));
    __shared__ float smax[8];
    if ((tid & 31) == 0) smax[tid >> 5] = mx;
    __syncthreads();
    mx = smax[0];
    #pragma unroll
    for (int w = 1; w < 8; ++w) mx = fmaxf(mx, smax[w]);
    float sum = 0.0f;
    #pragma unroll
    for (int e = 0; e < 8; ++e) { v[e] = expf(v[e] - mx); sum += v[e]; }
    #pragma unroll
    for (int o = 16; o; o >>= 1) sum += __shfl_xor_sync(0xffffffffu, sum, o);
    __shared__ float ssum[8];
    if ((tid & 31) == 0) ssum[tid >> 5] = sum;
    __syncthreads();
    sum = 0.0f;
    #pragma unroll
    for (int w = 0; w < 8; ++w) sum += ssum[w];
    #pragma unroll
    for (int e = 0; e < 8; ++e) p[tid + e * 256] = v[e] / sum;
}

// ---------------- PV via fp16 MMA ----------------
__global__ __launch_bounds__(256) void pv_mma_kernel() {
    __shared__ __half ps[64][72];
    __shared__ __half vt[128][72];
    const int tid = threadIdx.x;
    const int wid = tid >> 5, lane = tid & 31;
    const int g = lane >> 2, tig = lane & 3;
    const int bh = blockIdx.y;
    const int b = bh >> 4, h = bh & 15;
    const int i0 = blockIdx.x * 64;
    const float* ap = g_scores + (size_t)bh * S_ * S_;
    const unsigned char* vp = g_q8 + (size_t)2 * PLANE + (size_t)bh * (S_ * HD);
    const int wm = (wid & 1) * 32, wn = (wid >> 1) * 32;

    float acc[2][4][4] = {};

    for (int kc = 0; kc < S_; kc += 32) {
        #pragma unroll
        for (int p = 0; p < 2; ++p) {
            int lin = tid + p * 256;
            int r = lin >> 3, c = (lin & 7) << 2;
            float4 vv = *(const float4*)&ap[(size_t)(i0 + r) * S_ + kc + c];
            __half2 h0 = __floats2half2_rn(vv.x, vv.y);
            __half2 h1 = __floats2half2_rn(vv.z, vv.w);
            *(__half2*)&ps[r][c + 0] = h0;
            *(__half2*)&ps[r][c + 2] = h1;
        }
        #pragma unroll
        for (int p = 0; p < 4; ++p) {
            int lin = tid + p * 256;
            int r = lin >> 5, c = (lin & 31) << 2;
            unsigned int vv = *(const unsigned int*)&vp[(size_t)(kc + r) * HD + c];
            vt[c + 0][r] = __ushort_as_half(f8_to_h(vv & 0xff));
            vt[c + 1][r] = __ushort_as_half(f8_to_h((vv >> 8) & 0xff));
            vt[c + 2][r] = __ushort_as_half(f8_to_h((vv >> 16) & 0xff));
            vt[c + 3][r] = __ushort_as_half(f8_to_h(vv >> 24));
        }
        __syncthreads();

        #pragma unroll
        for (int kstep = 0; kstep < 2; ++kstep) {
            const int kb = kstep * 16;
            unsigned a[2][4], bfr[4][2];
            #pragma unroll
            for (int mi = 0; mi < 2; ++mi) {
                int r = wm + mi * 16 + g;
                a[mi][0] = *(unsigned*)&ps[r][kb + 2 * tig];
                a[mi][1] = *(unsigned*)&ps[r + 8][kb + 2 * tig];
                a[mi][2] = *(unsigned*)&ps[r][kb + 2 * tig + 8];
                a[mi][3] = *(unsigned*)&ps[r + 8][kb + 2 * tig + 8];
            }
            #pragma unroll
            for (int ni = 0; ni < 4; ++ni) {
                int r = wn + ni * 8 + g;
                bfr[ni][0] = *(unsigned*)&vt[r][kb + 2 * tig];
                bfr[ni][1] = *(unsigned*)&vt[r][kb + 2 * tig + 8];
            }
            #pragma unroll
            for (int mi = 0; mi < 2; ++mi)
                #pragma unroll
                for (int ni = 0; ni < 4; ++ni)
                    mma_f16(acc[mi][ni][0], acc[mi][ni][1], acc[mi][ni][2], acc[mi][ni][3],
                            a[mi][0], a[mi][1], a[mi][2], a[mi][3], bfr[ni][0], bfr[ni][1]);
        }
        __syncthreads();
    }

    const float vsc = g_scales[2];
    #pragma unroll
    for (int mi = 0; mi < 2; ++mi) {
        int s = i0 + wm + mi * 16 + g;
        #pragma unroll
        for (int ni = 0; ni < 4; ++ni) {
            int d = wn + ni * 8 + 2 * tig;
            float2 v0 = {acc[mi][ni][0] * vsc, acc[mi][ni][1] * vsc};
            float2 v1 = {acc[mi][ni][2] * vsc, acc[mi][ni][3] * vsc};
            *(float2*)&g_attnout[(size_t)(b * S_ + s) * H_ + h * HD + d] = v0;
            *(float2*)&g_attnout[(size_t)(b * S_ + s + 8) * H_ + h * HD + d] = v1;
        }
    }
}

// ---------------- launch ----------------
extern "C" void kernel_launch(void* const* d_in, const int* in_sizes, int n_in,
                              void* d_out, int out_size)
{
    const float* x    = (const float*)d_in[0];
    const float* Wqkv = (const float*)d_in[1];
    const float* Wout = (const float*)d_in[2];
    const float* bout = (const float*)d_in[3];
    float* y = (float*)d_out;

    float *qkv_ptr = nullptr, *ao_ptr = nullptr;
    cudaGetSymbolAddress((void**)&qkv_ptr, g_qkv);
    cudaGetSymbolAddress((void**)&ao_ptr,  g_attnout);

    zero_kernel<<<1, 32>>>();

    // 1) qkv = x @ W_qkv  (fp16x3 tensor-core, fp32 fidelity)
    hgemm_x3<<<dim3(H3 / 128, M1 / 128), 256>>>(x, Wqkv, qkv_ptr, M1, H3, H_, nullptr);

    // 2) per-tensor abs-max + scales
    absmax_kernel<<<1184, 256>>>();
    scales_kernel<<<1, 32>>>();

    // 3) quantize q/k/v to fp8 in head-major layout
    quant_kernel<<<(3 * PLANE) / 256, 256>>>();

    // 4) scores = q8 @ k8^T (fp16 MMA, exact)
    scores_mma_kernel<<<dim3(S_ / 128, S_ / 128, B_ * NH), 256>>>();

    // 5) softmax over keys
    softmax_kernel<<<B_ * NH * S_, 256>>>();

    // 6) out = (attn_f16 @ v8_f16) * v_scale
    pv_mma_kernel<<<dim3(S_ / 64, B_ * NH), 256>>>();

    // 7) y = out @ W_out + b_out  (fp16x3)
    hgemm_x3<<<dim3(H_ / 128, M1 / 128), 256>>>(ao_ptr, Wout, y, M1, H_, H_, bout);
}

// round 5
// speedup vs baseline: 3.9236x; 1.3488x over previous
#include <cuda_runtime.h>
#include <cuda_fp16.h>
#include <cuda_fp8.h>
#include <math.h>

// ---------------- problem constants ----------------
#define B_   2
#define S_   2048
#define H_   2048
#define NH   16
#define HD   128
#define H3   (3 * H_)
#define M1   (B_ * S_)
#define PLANE (B_ * NH * S_ * HD)
#define BQ   128

// ---------------- scratch ----------------
__device__ float         g_qkv[(size_t)M1 * H3];
__device__ unsigned char g_q8[(size_t)3 * PLANE];
__device__ float         g_attnout[(size_t)M1 * H_];
__device__ unsigned int  g_absmax[3];
__device__ float         g_scales[3];

__device__ __forceinline__ unsigned short f8_to_h(unsigned char v) {
    __half_raw hr = __nv_cvt_fp8_to_halfraw(v, __NV_E4M3);
    return hr.x;
}
__device__ __forceinline__ unsigned f8x2_to_h2(unsigned two) {
    return (unsigned)f8_to_h(two & 0xff) | ((unsigned)f8_to_h((two >> 8) & 0xff) << 16);
}

__device__ __forceinline__ void mma_f16(float& d0, float& d1, float& d2, float& d3,
                                        unsigned a0, unsigned a1, unsigned a2, unsigned a3,
                                        unsigned b0, unsigned b1) {
    asm volatile("mma.sync.aligned.m16n8k16.row.col.f32.f16.f16.f32 "
                 "{%0,%1,%2,%3}, {%4,%5,%6,%7}, {%8,%9}, {%0,%1,%2,%3};"
                 : "+f"(d0), "+f"(d1), "+f"(d2), "+f"(d3)
                 : "r"(a0), "r"(a1), "r"(a2), "r"(a3), "r"(b0), "r"(b1));
}

__device__ __forceinline__ void ldsm_x2_trans(unsigned& r0, unsigned& r1, const void* p) {
    unsigned addr = (unsigned)__cvta_generic_to_shared(p);
    asm volatile("ldmatrix.sync.aligned.m8n8.x2.trans.shared.b16 {%0,%1}, [%2];"
                 : "=r"(r0), "=r"(r1) : "r"(addr));
}

__global__ void zero_kernel() {
    if (threadIdx.x < 3) g_absmax[threadIdx.x] = 0u;
}

// ============ fp16x3 GEMM (unchanged from R4) ============
__global__ __launch_bounds__(256) void hgemm_x3(
    const float* __restrict__ A, const float* __restrict__ Bm,
    float* __restrict__ C, int M, int N, int K, const float* __restrict__ bias)
{
    __shared__ __half Ah[128][40];
    __shared__ __half Al[128][40];
    __shared__ float  Bs[32][132];

    const int tid = threadIdx.x;
    const int wid = tid >> 5, lane = tid & 31;
    const int g = lane >> 2, tig = lane & 3;
    const int m0 = blockIdx.y * 128, n0 = blockIdx.x * 128;
    const int wm = (wid & 1) * 64, wn = (wid >> 1) * 32;

    float acc[4][4][4] = {};

    int aR[4], aC[4], bR[4], bC[4];
    #pragma unroll
    for (int p = 0; p < 4; ++p) {
        int lin = tid + p * 256;
        aR[p] = lin >> 3; aC[p] = (lin & 7) << 2;
        bR[p] = lin >> 5; bC[p] = (lin & 31) << 2;
    }

    auto store_A = [&](int p, float4 v) {
        float vv[4] = {v.x, v.y, v.z, v.w};
        __half h[4], l[4];
        #pragma unroll
        for (int j = 0; j < 4; ++j) {
            h[j] = __float2half_rn(vv[j]);
            l[j] = __float2half_rn(vv[j] - __half2float(h[j]));
        }
        *(__half2*)&Ah[aR[p]][aC[p] + 0] = __halves2half2(h[0], h[1]);
        *(__half2*)&Ah[aR[p]][aC[p] + 2] = __halves2half2(h[2], h[3]);
        *(__half2*)&Al[aR[p]][aC[p] + 0] = __halves2half2(l[0], l[1]);
        *(__half2*)&Al[aR[p]][aC[p] + 2] = __halves2half2(l[2], l[3]);
    };

    float4 pa[4], pb[4];
    #pragma unroll
    for (int p = 0; p < 4; ++p) {
        pa[p] = *(const float4*)&A[(size_t)(m0 + aR[p]) * K + aC[p]];
        pb[p] = *(const float4*)&Bm[(size_t)bR[p] * N + n0 + bC[p]];
    }
    #pragma unroll
    for (int p = 0; p < 4; ++p) {
        store_A(p, pa[p]);
        *(float4*)&Bs[bR[p]][bC[p]] = pb[p];
    }
    __syncthreads();

    const int T = K >> 5;
    for (int t = 0; t < T; ++t) {
        if (t + 1 < T) {
            int k0 = (t + 1) << 5;
            #pragma unroll
            for (int p = 0; p < 4; ++p) {
                pa[p] = *(const float4*)&A[(size_t)(m0 + aR[p]) * K + k0 + aC[p]];
                pb[p] = *(const float4*)&Bm[(size_t)(k0 + bR[p]) * N + n0 + bC[p]];
            }
        }

        #pragma unroll
        for (int ks = 0; ks < 2; ++ks) {
            const int kb = ks * 16;
            unsigned ah[4][4], al[4][4], bh[4][2], bl[4][2];
            #pragma unroll
            for (int mi = 0; mi < 4; ++mi) {
                int r = wm + mi * 16 + g;
                #pragma unroll
                for (int q = 0; q < 4; ++q) {
                    int rr = r + (q & 1) * 8;
                    int kk = kb + 2 * tig + (q >> 1) * 8;
                    ah[mi][q] = *(unsigned*)&Ah[rr][kk];
                    al[mi][q] = *(unsigned*)&Al[rr][kk];
                }
            }
            #pragma unroll
            for (int ni = 0; ni < 4; ++ni) {
                int c = wn + ni * 8 + g;
                #pragma unroll
                for (int q = 0; q < 2; ++q) {
                    int kk = kb + 2 * tig + q * 8;
                    float f0 = Bs[kk][c], f1 = Bs[kk + 1][c];
                    __half h0 = __float2half_rn(f0), h1 = __float2half_rn(f1);
                    __half l0 = __float2half_rn(f0 - __half2float(h0));
                    __half l1 = __float2half_rn(f1 - __half2float(h1));
                    __half2 hh = __halves2half2(h0, h1);
                    __half2 ll = __halves2half2(l0, l1);
                    bh[ni][q] = *(unsigned*)&hh;
                    bl[ni][q] = *(unsigned*)&ll;
                }
            }
            #pragma unroll
            for (int mi = 0; mi < 4; ++mi)
                #pragma unroll
                for (int ni = 0; ni < 4; ++ni) {
                    float* d = acc[mi][ni];
                    mma_f16(d[0], d[1], d[2], d[3],
                            ah[mi][0], ah[mi][1], ah[mi][2], ah[mi][3], bh[ni][0], bh[ni][1]);
                    mma_f16(d[0], d[1], d[2], d[3],
                            ah[mi][0], ah[mi][1], ah[mi][2], ah[mi][3], bl[ni][0], bl[ni][1]);
                    mma_f16(d[0], d[1], d[2], d[3],
                            al[mi][0], al[mi][1], al[mi][2], al[mi][3], bh[ni][0], bh[ni][1]);
                }
        }

        if (t + 1 < T) {
            __syncthreads();
            #pragma unroll
            for (int p = 0; p < 4; ++p) {
                store_A(p, pa[p]);
                *(float4*)&Bs[bR[p]][bC[p]] = pb[p];
            }
            __syncthreads();
        }
    }

    #pragma unroll
    for (int mi = 0; mi < 4; ++mi) {
        int r = m0 + wm + mi * 16 + g;
        #pragma unroll
        for (int ni = 0; ni < 4; ++ni) {
            int c = n0 + wn + ni * 8 + 2 * tig;
            float2 v0 = {acc[mi][ni][0], acc[mi][ni][1]};
            float2 v1 = {acc[mi][ni][2], acc[mi][ni][3]};
            if (bias) {
                float b0 = bias[c], b1 = bias[c + 1];
                v0.x += b0; v0.y += b1;
                v1.x += b0; v1.y += b1;
            }
            *(float2*)&C[(size_t)r * N + c] = v0;
            *(float2*)&C[(size_t)(r + 8) * N + c] = v1;
        }
    }
}

// ---------------- abs-max / scales / quant ----------------
__global__ void absmax_kernel() {
    __shared__ unsigned int sm[3];
    if (threadIdx.x < 3) sm[threadIdx.x] = 0u;
    __syncthreads();
    const int gtid = blockIdx.x * blockDim.x + threadIdx.x;
    const int stride = gridDim.x * blockDim.x;
    const int n2 = M1 * H_;
    #pragma unroll
    for (int t = 0; t < 3; ++t) {
        unsigned int lm = 0u;
        for (int i = gtid; i < n2; i += stride) {
            int r = i >> 11, c = i & 2047;
            unsigned int b = __float_as_uint(fabsf(g_qkv[(size_t)r * H3 + t * H_ + c]));
            lm = (b > lm) ? b : lm;
        }
        atomicMax(&sm[t], lm);
    }
    __syncthreads();
    if (threadIdx.x < 3) atomicMax(&g_absmax[threadIdx.x], sm[threadIdx.x]);
}

__global__ void scales_kernel() {
    if (threadIdx.x < 3)
        g_scales[threadIdx.x] = __uint_as_float(g_absmax[threadIdx.x]) / 448.0f;
}

__global__ void quant_kernel() {
    int idx = blockIdx.x * blockDim.x + threadIdx.x;
    if (idx >= 3 * PLANE) return;
    int t = idx / PLANE;
    int rem = idx - t * PLANE;
    int d = rem & 127;
    int s = (rem >> 7) & 2047;
    int bh = rem >> 18;
    int b = bh >> 4, h = bh & 15;
    float v = g_qkv[(size_t)(b * S_ + s) * H3 + t * H_ + h * HD + d];
    g_q8[idx] = __nv_cvt_float_to_fp8(v / g_scales[t], __NV_SATFINITE, __NV_E4M3);
}

// ============ fused flash attention: scores + softmax + PV ============
// grid (S/128, B*NH); 256 threads = 8 warps (2m x 4n); K-tiles of 128 keys.
__global__ __launch_bounds__(256, 1) void flash_kernel() {
    extern __shared__ char smraw[];
    typedef __half HRow[136];                  // stride 68 words == 4 mod 32
    HRow* Qs = (HRow*)smraw;                   // [128][136] fp16
    HRow* Ks = (HRow*)(smraw + 34816);
    HRow* Vs = (HRow*)(smraw + 2 * 34816);     // [k][d] natural layout
    HRow* Ps = (HRow*)(smraw + 3 * 34816);     // probs fp16 [q][k]
    float (*red)[128] = (float(*)[128])(smraw + 4 * 34816);   // [4 warp_n][128 rows]

    const int tid = threadIdx.x, lane = tid & 31, wid = tid >> 5;
    const int g = lane >> 2, tig = lane & 3;
    const int wm = (wid & 1) * 64, wn = (wid >> 1) * 32;
    const int wnid = wid >> 1;
    const int bh = blockIdx.y;
    const int b = bh >> 4, h = bh & 15;
    const int i0 = blockIdx.x * BQ;
    const unsigned char* qp = g_q8 + (size_t)bh * (S_ * HD);
    const unsigned char* kp = g_q8 + (size_t)PLANE + (size_t)bh * (S_ * HD);
    const unsigned char* vp = g_q8 + 2 * (size_t)PLANE + (size_t)bh * (S_ * HD);
    const float f = g_scales[0] * g_scales[1] * 0.08838834764831843f;   // qs*ks/sqrt(128)

    // ---- Q tile fill (fp8 -> fp16) ----
    #pragma unroll
    for (int p = 0; p < 16; ++p) {
        int lin = tid + p * 256;
        int r = lin >> 5, c = (lin & 31) << 2;
        unsigned qv = *(const unsigned*)&qp[(size_t)(i0 + r) * HD + c];
        *(unsigned*)&Qs[r][c]     = f8x2_to_h2(qv);
        *(unsigned*)&Qs[r][c + 2] = f8x2_to_h2(qv >> 16);
    }

    float o[4][4][4] = {};
    float mrow[4][2], lrow[4][2];
    #pragma unroll
    for (int mi = 0; mi < 4; ++mi) {
        mrow[mi][0] = mrow[mi][1] = -1e30f;
        lrow[mi][0] = lrow[mi][1] = 0.0f;
    }

    for (int kt = 0; kt < S_ / BQ; ++kt) {
        // ---- K and V tile fill ----
        const unsigned char* kb8 = kp + (size_t)kt * BQ * HD;
        const unsigned char* vb8 = vp + (size_t)kt * BQ * HD;
        #pragma unroll
        for (int p = 0; p < 16; ++p) {
            int lin = tid + p * 256;
            int r = lin >> 5, c = (lin & 31) << 2;
            unsigned kv = *(const unsigned*)&kb8[(size_t)r * HD + c];
            unsigned vv = *(const unsigned*)&vb8[(size_t)r * HD + c];
            *(unsigned*)&Ks[r][c]     = f8x2_to_h2(kv);
            *(unsigned*)&Ks[r][c + 2] = f8x2_to_h2(kv >> 16);
            *(unsigned*)&Vs[r][c]     = f8x2_to_h2(vv);
            *(unsigned*)&Vs[r][c + 2] = f8x2_to_h2(vv >> 16);
        }
        __syncthreads();

        // ---- S = Q @ K^T ----
        float s[4][4][4] = {};
        #pragma unroll
        for (int ks = 0; ks < 8; ++ks) {
            const int kb = ks * 16;
            unsigned a[4][4], bb[4][2];
            #pragma unroll
            for (int mi = 0; mi < 4; ++mi) {
                int r = wm + mi * 16 + g;
                a[mi][0] = *(unsigned*)&Qs[r][kb + 2 * tig];
                a[mi][1] = *(unsigned*)&Qs[r + 8][kb + 2 * tig];
                a[mi][2] = *(unsigned*)&Qs[r][kb + 2 * tig + 8];
                a[mi][3] = *(unsigned*)&Qs[r + 8][kb + 2 * tig + 8];
            }
            #pragma unroll
            for (int ni = 0; ni < 4; ++ni) {
                int r = wn + ni * 8 + g;
                bb[ni][0] = *(unsigned*)&Ks[r][kb + 2 * tig];
                bb[ni][1] = *(unsigned*)&Ks[r][kb + 2 * tig + 8];
            }
            #pragma unroll
            for (int mi = 0; mi < 4; ++mi)
                #pragma unroll
                for (int ni = 0; ni < 4; ++ni)
                    mma_f16(s[mi][ni][0], s[mi][ni][1], s[mi][ni][2], s[mi][ni][3],
                            a[mi][0], a[mi][1], a[mi][2], a[mi][3], bb[ni][0], bb[ni][1]);
        }
        #pragma unroll
        for (int mi = 0; mi < 4; ++mi)
            #pragma unroll
            for (int ni = 0; ni < 4; ++ni)
                #pragma unroll
                for (int j = 0; j < 4; ++j)
                    s[mi][ni][j] *= f;

        // ---- row max: thread partial -> quad shfl -> cross-warp via smem ----
        float tmax[4][2];
        #pragma unroll
        for (int mi = 0; mi < 4; ++mi) {
            float h0 = -1e30f, h1 = -1e30f;
            #pragma unroll
            for (int ni = 0; ni < 4; ++ni) {
                h0 = fmaxf(h0, fmaxf(s[mi][ni][0], s[mi][ni][1]));
                h1 = fmaxf(h1, fmaxf(s[mi][ni][2], s[mi][ni][3]));
            }
            tmax[mi][0] = h0; tmax[mi][1] = h1;
        }
        #pragma unroll
        for (int off = 1; off <= 2; off <<= 1)
            #pragma unroll
            for (int mi = 0; mi < 4; ++mi) {
                tmax[mi][0] = fmaxf(tmax[mi][0], __shfl_xor_sync(0xffffffffu, tmax[mi][0], off));
                tmax[mi][1] = fmaxf(tmax[mi][1], __shfl_xor_sync(0xffffffffu, tmax[mi][1], off));
            }
        if (tig == 0) {
            #pragma unroll
            for (int mi = 0; mi < 4; ++mi) {
                red[wnid][wm + mi * 16 + g]     = tmax[mi][0];
                red[wnid][wm + mi * 16 + g + 8] = tmax[mi][1];
            }
        }
        __syncthreads();

        // ---- online update: new max, rescale O and l, p = exp(s - m), store P ----
        #pragma unroll
        for (int mi = 0; mi < 4; ++mi) {
            #pragma unroll
            for (int hh = 0; hh < 2; ++hh) {
                int row = wm + mi * 16 + g + hh * 8;
                float rm = fmaxf(fmaxf(red[0][row], red[1][row]),
                                 fmaxf(red[2][row], red[3][row]));
                float mnew = fmaxf(mrow[mi][hh], rm);
                float rs = expf(mrow[mi][hh] - mnew);
                mrow[mi][hh] = mnew;
                lrow[mi][hh] *= rs;
                #pragma unroll
                for (int ni = 0; ni < 4; ++ni) {
                    o[mi][ni][2 * hh]     *= rs;
                    o[mi][ni][2 * hh + 1] *= rs;
                }
            }
            #pragma unroll
            for (int ni = 0; ni < 4; ++ni) {
                float p0 = expf(s[mi][ni][0] - mrow[mi][0]);
                float p1 = expf(s[mi][ni][1] - mrow[mi][0]);
                float p2 = expf(s[mi][ni][2] - mrow[mi][1]);
                float p3 = expf(s[mi][ni][3] - mrow[mi][1]);
                lrow[mi][0] += p0 + p1;
                lrow[mi][1] += p2 + p3;
                int c = wn + ni * 8 + 2 * tig;
                *(__half2*)&Ps[wm + mi * 16 + g][c]     = __floats2half2_rn(p0, p1);
                *(__half2*)&Ps[wm + mi * 16 + g + 8][c] = __floats2half2_rn(p2, p3);
            }
        }
        __syncthreads();

        // ---- O += P @ V  (V B-frags via ldmatrix.trans: no smem transpose) ----
        #pragma unroll
        for (int ks = 0; ks < 8; ++ks) {
            const int kb = ks * 16;
            unsigned a[4][4], bb[4][2];
            #pragma unroll
            for (int mi = 0; mi < 4; ++mi) {
                int r = wm + mi * 16 + g;
                a[mi][0] = *(unsigned*)&Ps[r][kb + 2 * tig];
                a[mi][1] = *(unsigned*)&Ps[r + 8][kb + 2 * tig];
                a[mi][2] = *(unsigned*)&Ps[r][kb + 2 * tig + 8];
                a[mi][3] = *(unsigned*)&Ps[r + 8][kb + 2 * tig + 8];
            }
            #pragma unroll
            for (int ni = 0; ni < 4; ++ni)
                ldsm_x2_trans(bb[ni][0], bb[ni][1], &Vs[kb + (lane & 15)][wn + ni * 8]);
            #pragma unroll
            for (int mi = 0; mi < 4; ++mi)
                #pragma unroll
                for (int ni = 0; ni < 4; ++ni)
                    mma_f16(o[mi][ni][0], o[mi][ni][1], o[mi][ni][2], o[mi][ni][3],
                            a[mi][0], a[mi][1], a[mi][2], a[mi][3], bb[ni][0], bb[ni][1]);
        }
        __syncthreads();
    }

    // ---- epilogue: combine l across quad + n-warps, O = O * vscale / l ----
    #pragma unroll
    for (int off = 1; off <= 2; off <<= 1)
        #pragma unroll
        for (int mi = 0; mi < 4; ++mi) {
            lrow[mi][0] += __shfl_xor_sync(0xffffffffu, lrow[mi][0], off);
            lrow[mi][1] += __shfl_xor_sync(0xffffffffu, lrow[mi][1], off);
        }
    if (tig == 0) {
        #pragma unroll
        for (int mi = 0; mi < 4; ++mi) {
            red[wnid][wm + mi * 16 + g]     = lrow[mi][0];
            red[wnid][wm + mi * 16 + g + 8] = lrow[mi][1];
        }
    }
    __syncthreads();

    const float vsc = g_scales[2];
    #pragma unroll
    for (int mi = 0; mi < 4; ++mi) {
        #pragma unroll
        for (int hh = 0; hh < 2; ++hh) {
            int row = wm + mi * 16 + g + hh * 8;
            float lt = red[0][row] + red[1][row] + red[2][row] + red[3][row];
            float inv = vsc / lt;
            int srow = i0 + row;
            #pragma unroll
            for (int ni = 0; ni < 4; ++ni) {
                int d = wn + ni * 8 + 2 * tig;
                float2 v = {o[mi][ni][2 * hh] * inv, o[mi][ni][2 * hh + 1] * inv};
                *(float2*)&g_attnout[(size_t)(b * S_ + srow) * H_ + h * HD + d] = v;
            }
        }
    }
}

// ---------------- launch ----------------
extern "C" void kernel_launch(void* const* d_in, const int* in_sizes, int n_in,
                              void* d_out, int out_size)
{
    const float* x    = (const float*)d_in[0];
    const float* Wqkv = (const float*)d_in[1];
    const float* Wout = (const float*)d_in[2];
    const float* bout = (const float*)d_in[3];
    float* y = (float*)d_out;

    float *qkv_ptr = nullptr, *ao_ptr = nullptr;
    cudaGetSymbolAddress((void**)&qkv_ptr, g_qkv);
    cudaGetSymbolAddress((void**)&ao_ptr,  g_attnout);

    static int smem_set = 0;
    const int FLASH_SMEM = 4 * 34816 + 4 * 128 * 4;   // 141312 B
    if (!smem_set) {
        cudaFuncSetAttribute(flash_kernel,
                             cudaFuncAttributeMaxDynamicSharedMemorySize, FLASH_SMEM);
        smem_set = 1;
    }

    zero_kernel<<<1, 32>>>();

    // 1) qkv = x @ W_qkv  (fp16x3)
    hgemm_x3<<<dim3(H3 / 128, M1 / 128), 256>>>(x, Wqkv, qkv_ptr, M1, H3, H_, nullptr);

    // 2) per-tensor abs-max + scales
    absmax_kernel<<<1184, 256>>>();
    scales_kernel<<<1, 32>>>();

    // 3) quantize q/k/v to fp8 in head-major layout
    quant_kernel<<<(3 * PLANE) / 256, 256>>>();

    // 4-6) fused flash attention (scores + softmax + PV)
    flash_kernel<<<dim3(S_ / BQ, B_ * NH), 256, FLASH_SMEM>>>();

    // 7) y = out @ W_out + b_out  (fp16x3)
    hgemm_x3<<<dim3(H_ / 128, M1 / 128), 256>>>(ao_ptr, Wout, y, M1, H_, H_, bout);
}

// round 7
// speedup vs baseline: 3.9703x; 1.0119x over previous
#include <cuda_runtime.h>
#include <cuda_fp16.h>
#include <cuda_fp8.h>
#include <math.h>

// ---------------- problem constants ----------------
#define B_   2
#define S_   2048
#define H_   2048
#define NH   16
#define HD   128
#define H3   (3 * H_)
#define M1   (B_ * S_)
#define PLANE (B_ * NH * S_ * HD)
#define BQ   128

// ---------------- scratch ----------------
__device__ float         g_qkv[(size_t)M1 * H3];
__device__ unsigned char g_q8[(size_t)3 * PLANE];
__device__ float         g_attnout[(size_t)M1 * H_];
__device__ unsigned int  g_absmax[3];
__device__ float         g_scales[3];
// fp16 hi/lo operands for tensor-core GEMMs
__device__ __half        g_xh[(size_t)M1 * H_],  g_xl[(size_t)M1 * H_];
__device__ __half        g_wqh[(size_t)H3 * H_], g_wql[(size_t)H3 * H_];   // W_qkv^T [N][K]
__device__ __half        g_woh[(size_t)H_ * H_], g_wol[(size_t)H_ * H_];   // W_out^T [N][K]
__device__ __half        g_aoh[(size_t)M1 * H_], g_aol[(size_t)M1 * H_];

// ---------------- helpers ----------------
__device__ __forceinline__ unsigned short f8_to_h(unsigned char v) {
    __half_raw hr = __nv_cvt_fp8_to_halfraw(v, __NV_E4M3);
    return hr.x;
}
__device__ __forceinline__ unsigned f8x2_to_h2(unsigned two) {
    return (unsigned)f8_to_h(two & 0xff) | ((unsigned)f8_to_h((two >> 8) & 0xff) << 16);
}

__device__ __forceinline__ void mma_f16(float& d0, float& d1, float& d2, float& d3,
                                        unsigned a0, unsigned a1, unsigned a2, unsigned a3,
                                        unsigned b0, unsigned b1) {
    asm volatile("mma.sync.aligned.m16n8k16.row.col.f32.f16.f16.f32 "
                 "{%0,%1,%2,%3}, {%4,%5,%6,%7}, {%8,%9}, {%0,%1,%2,%3};"
                 : "+f"(d0), "+f"(d1), "+f"(d2), "+f"(d3)
                 : "r"(a0), "r"(a1), "r"(a2), "r"(a3), "r"(b0), "r"(b1));
}
__device__ __forceinline__ void ldsm_x2_trans(unsigned& r0, unsigned& r1, const void* p) {
    unsigned addr = (unsigned)__cvta_generic_to_shared(p);
    asm volatile("ldmatrix.sync.aligned.m8n8.x2.trans.shared.b16 {%0,%1}, [%2];"
                 : "=r"(r0), "=r"(r1) : "r"(addr));
}

#define SWZ(x) ((x) ^ (((x) >> 3) & 0x70))

__device__ __forceinline__ unsigned smem_u32(const void* p) {
    return (unsigned)__cvta_generic_to_shared(p);
}
__device__ __forceinline__ void cpa16(unsigned dst, const void* src) {
    asm volatile("cp.async.cg.shared.global [%0], [%1], 16;" :: "r"(dst), "l"(src));
}
__device__ __forceinline__ void cpa_commit() { asm volatile("cp.async.commit_group;" ::: "memory"); }
__device__ __forceinline__ void cpa_waitall() { asm volatile("cp.async.wait_group 0;" ::: "memory"); }

__global__ void zero_kernel() {
    if (threadIdx.x < 3) g_absmax[threadIdx.x] = 0u;
}

// ---------------- prep: elementwise fp32 -> fp16 hi/lo split ----------------
__global__ void split_kernel(const float* __restrict__ src, __half* __restrict__ dh,
                             __half* __restrict__ dl, int n4) {
    int i = blockIdx.x * blockDim.x + threadIdx.x;
    if (i >= n4) return;
    float4 v = ((const float4*)src)[i];
    float vv[4] = {v.x, v.y, v.z, v.w};
    __half h[4], l[4];
    #pragma unroll
    for (int j = 0; j < 4; ++j) {
        h[j] = __float2half_rn(vv[j]);
        l[j] = __float2half_rn(vv[j] - __half2float(h[j]));
    }
    ((__half2*)dh)[i * 2]     = __halves2half2(h[0], h[1]);
    ((__half2*)dh)[i * 2 + 1] = __halves2half2(h[2], h[3]);
    ((__half2*)dl)[i * 2]     = __halves2half2(l[0], l[1]);
    ((__half2*)dl)[i * 2 + 1] = __halves2half2(l[2], l[3]);
}

// ---------------- prep: transpose + split  W[K][N] -> T[N][K] hi/lo ----------------
__global__ void tsplit_kernel(const float* __restrict__ W, __half* __restrict__ Th,
                              __half* __restrict__ Tl, int K, int N) {
    __shared__ float tile[32][33];
    const int n0 = blockIdx.x * 32, k0 = blockIdx.y * 32;
    const int tx = threadIdx.x, ty = threadIdx.y;   // (32, 8)
    #pragma unroll
    for (int i = ty; i < 32; i += 8)
        tile[i][tx] = W[(size_t)(k0 + i) * N + n0 + tx];
    __syncthreads();
    #pragma unroll
    for (int i = ty; i < 32; i += 8) {
        float v = tile[tx][i];
        __half h = __float2half_rn(v);
        __half l = __float2half_rn(v - __half2float(h));
        Th[(size_t)(n0 + i) * K + k0 + tx] = h;
        Tl[(size_t)(n0 + i) * K + k0 + tx] = l;
    }
}

// ============ fp16x3 GEMM v2: pre-split operands, swizzled cp.async pipeline ======
// C[M,N] = A @ B^T (+bias). 128x128 tile, K-chunks of 64, 8 warps (2m x 4n).
// Smem: stage{0,1} x {Ah,Al,Bh,Bl}, each 128 rows x 128B, SW128-swizzled.
#define RG_SZ   16384
#define ST_SZ   65536
#define G2_SMEM 131072

__global__ __launch_bounds__(256, 1) void hgemm2(
    const __half* __restrict__ Agh, const __half* __restrict__ Agl,
    const __half* __restrict__ Bgh, const __half* __restrict__ Bgl,
    float* __restrict__ C, int M, int N, int K,
    const float* __restrict__ bias, int do_absmax)
{
    extern __shared__ char smraw[];
    const unsigned sb = smem_u32(smraw);
    const int tid = threadIdx.x, wid = tid >> 5, lane = tid & 31;
    const int g = lane >> 2, tig = lane & 3;
    const int m0 = blockIdx.y * 128, n0 = blockIdx.x * 128;
    const int wm = (wid & 1) * 64, wn = (wid >> 1) * 32;

    float acc[4][4][4] = {};

    const int fr = tid >> 1;                   // fill row 0..127
    const int fg = (tid & 1) << 2;             // granule 0 or 4 (4 granules each)

    auto fill = [&](int stage, int k0) {
        const __half* s0 = Agh + (size_t)(m0 + fr) * K + k0 + fg * 8;
        const __half* s1 = Agl + (size_t)(m0 + fr) * K + k0 + fg * 8;
        const __half* s2 = Bgh + (size_t)(n0 + fr) * K + k0 + fg * 8;
        const __half* s3 = Bgl + (size_t)(n0 + fr) * K + k0 + fg * 8;
        unsigned base = sb + stage * ST_SZ;
        #pragma unroll
        for (int p = 0; p < 4; ++p) {
            unsigned d = SWZ((unsigned)(fr * 128 + (fg + p) * 16));
            cpa16(base + 0 * RG_SZ + d, s0 + p * 8);
            cpa16(base + 1 * RG_SZ + d, s1 + p * 8);
            cpa16(base + 2 * RG_SZ + d, s2 + p * 8);
            cpa16(base + 3 * RG_SZ + d, s3 + p * 8);
        }
        cpa_commit();
    };

    fill(0, 0);
    cpa_waitall(); __syncthreads();

    const int T = K >> 6;
    for (int t = 0; t < T; ++t) {
        const int stage = t & 1;
        if (t + 1 < T) fill(stage ^ 1, (t + 1) << 6);

        const char* Ah = smraw + stage * ST_SZ;
        const char* Al = Ah + RG_SZ;
        const char* Bh = Ah + 2 * RG_SZ;
        const char* Bl = Ah + 3 * RG_SZ;

        #pragma unroll
        for (int ks = 0; ks < 4; ++ks) {
            const int kb = ks * 16;            // halves
            unsigned ah[4][4], al[4][4], bh[4][2], bl[4][2];
            #pragma unroll
            for (int mi = 0; mi < 4; ++mi) {
                int r = wm + mi * 16 + g;
                #pragma unroll
                for (int q = 0; q < 4; ++q) {
                    int rr = r + (q & 1) * 8;
                    unsigned off = SWZ((unsigned)(rr * 128 + (kb + 2 * tig + (q >> 1) * 8) * 2));
                    ah[mi][q] = *(const unsigned*)(Ah + off);
                    al[mi][q] = *(const unsigned*)(Al + off);
                }
            }
            #pragma unroll
            for (int ni = 0; ni < 4; ++ni) {
                int r = wn + ni * 8 + g;
                #pragma unroll
                for (int q = 0; q < 2; ++q) {
                    unsigned off = SWZ((unsigned)(r * 128 + (kb + 2 * tig + q * 8) * 2));
                    bh[ni][q] = *(const unsigned*)(Bh + off);
                    bl[ni][q] = *(const unsigned*)(Bl + off);
                }
            }
            // term 1: Ah*Bh
            #pragma unroll
            for (int mi = 0; mi < 4; ++mi)
                #pragma unroll
                for (int ni = 0; ni < 4; ++ni)
                    mma_f16(acc[mi][ni][0], acc[mi][ni][1], acc[mi][ni][2], acc[mi][ni][3],
                            ah[mi][0], ah[mi][1], ah[mi][2], ah[mi][3], bh[ni][0], bh[ni][1]);
            // term 2: Ah*Bl
            #pragma unroll
            for (int mi = 0; mi < 4; ++mi)
                #pragma unroll
                for (int ni = 0; ni < 4; ++ni)
                    mma_f16(acc[mi][ni][0], acc[mi][ni][1], acc[mi][ni][2], acc[mi][ni][3],
                            ah[mi][0], ah[mi][1], ah[mi][2], ah[mi][3], bl[ni][0], bl[ni][1]);
            // term 3: Al*Bh
            #pragma unroll
            for (int mi = 0; mi < 4; ++mi)
                #pragma unroll
                for (int ni = 0; ni < 4; ++ni)
                    mma_f16(acc[mi][ni][0], acc[mi][ni][1], acc[mi][ni][2], acc[mi][ni][3],
                            al[mi][0], al[mi][1], al[mi][2], al[mi][3], bh[ni][0], bh[ni][1]);
        }

        if (t + 1 < T) { cpa_waitall(); __syncthreads(); }
    }

    // epilogue
    float lmax = 0.0f;
    #pragma unroll
    for (int mi = 0; mi < 4; ++mi) {
        int r = m0 + wm + mi * 16 + g;
        #pragma unroll
        for (int ni = 0; ni < 4; ++ni) {
            int c = n0 + wn + ni * 8 + 2 * tig;
            float2 v0 = {acc[mi][ni][0], acc[mi][ni][1]};
            float2 v1 = {acc[mi][ni][2], acc[mi][ni][3]};
            if (bias) {
                float b0 = bias[c], b1 = bias[c + 1];
                v0.x += b0; v0.y += b1;
                v1.x += b0; v1.y += b1;
            }
            if (do_absmax) {
                lmax = fmaxf(lmax, fmaxf(fmaxf(fabsf(v0.x), fabsf(v0.y)),
                                         fmaxf(fabsf(v1.x), fabsf(v1.y))));
            }
            *(float2*)&C[(size_t)r * N + c] = v0;
            *(float2*)&C[(size_t)(r + 8) * N + c] = v1;
        }
    }
    if (do_absmax) {
        #pragma unroll
        for (int o = 16; o; o >>= 1)
            lmax = fmaxf(lmax, __shfl_xor_sync(0xffffffffu, lmax, o));
        if (lane == 0) atomicMax(&g_absmax[n0 >> 11], __float_as_uint(lmax));
    }
}

// ---------------- scales / quant ----------------
__global__ void scales_kernel() {
    if (threadIdx.x < 3)
        g_scales[threadIdx.x] = __uint_as_float(g_absmax[threadIdx.x]) / 448.0f;
}

__global__ void quant_kernel() {
    int idx = blockIdx.x * blockDim.x + threadIdx.x;
    if (idx >= 3 * PLANE) return;
    int t = idx / PLANE;
    int rem = idx - t * PLANE;
    int d = rem & 127;
    int s = (rem >> 7) & 2047;
    int bh = rem >> 18;
    int b = bh >> 4, h = bh & 15;
    float v = g_qkv[(size_t)(b * S_ + s) * H3 + t * H_ + h * HD + d];
    g_q8[idx] = __nv_cvt_float_to_fp8(v / g_scales[t], __NV_SATFINITE, __NV_E4M3);
}

// ============ fused flash attention (unchanged from R5) ============
__global__ __launch_bounds__(256, 1) void flash_kernel() {
    extern __shared__ char smraw[];
    typedef __half HRow[136];
    HRow* Qs = (HRow*)smraw;
    HRow* Ks = (HRow*)(smraw + 34816);
    HRow* Vs = (HRow*)(smraw + 2 * 34816);
    HRow* Ps = (HRow*)(smraw + 3 * 34816);
    float (*red)[128] = (float(*)[128])(smraw + 4 * 34816);

    const int tid = threadIdx.x, lane = tid & 31, wid = tid >> 5;
    const int g = lane >> 2, tig = lane & 3;
    const int wm = (wid & 1) * 64, wn = (wid >> 1) * 32;
    const int wnid = wid >> 1;
    const int bh = blockIdx.y;
    const int b = bh >> 4, h = bh & 15;
    const int i0 = blockIdx.x * BQ;
    const unsigned char* qp = g_q8 + (size_t)bh * (S_ * HD);
    const unsigned char* kp = g_q8 + (size_t)PLANE + (size_t)bh * (S_ * HD);
    const unsigned char* vp = g_q8 + 2 * (size_t)PLANE + (size_t)bh * (S_ * HD);
    const float f = g_scales[0] * g_scales[1] * 0.08838834764831843f;

    #pragma unroll
    for (int p = 0; p < 16; ++p) {
        int lin = tid + p * 256;
        int r = lin >> 5, c = (lin & 31) << 2;
        unsigned qv = *(const unsigned*)&qp[(size_t)(i0 + r) * HD + c];
        *(unsigned*)&Qs[r][c]     = f8x2_to_h2(qv);
        *(unsigned*)&Qs[r][c + 2] = f8x2_to_h2(qv >> 16);
    }

    float o[4][4][4] = {};
    float mrow[4][2], lrow[4][2];
    #pragma unroll
    for (int mi = 0; mi < 4; ++mi) {
        mrow[mi][0] = mrow[mi][1] = -1e30f;
        lrow[mi][0] = lrow[mi][1] = 0.0f;
    }

    for (int kt = 0; kt < S_ / BQ; ++kt) {
        const unsigned char* kb8 = kp + (size_t)kt * BQ * HD;
        const unsigned char* vb8 = vp + (size_t)kt * BQ * HD;
        #pragma unroll
        for (int p = 0; p < 16; ++p) {
            int lin = tid + p * 256;
            int r = lin >> 5, c = (lin & 31) << 2;
            unsigned kv = *(const unsigned*)&kb8[(size_t)r * HD + c];
            unsigned vv = *(const unsigned*)&vb8[(size_t)r * HD + c];
            *(unsigned*)&Ks[r][c]     = f8x2_to_h2(kv);
            *(unsigned*)&Ks[r][c + 2] = f8x2_to_h2(kv >> 16);
            *(unsigned*)&Vs[r][c]     = f8x2_to_h2(vv);
            *(unsigned*)&Vs[r][c + 2] = f8x2_to_h2(vv >> 16);
        }
        __syncthreads();

        float s[4][4][4] = {};
        #pragma unroll
        for (int ks = 0; ks < 8; ++ks) {
            const int kb = ks * 16;
            unsigned a[4][4], bb[4][2];
            #pragma unroll
            for (int mi = 0; mi < 4; ++mi) {
                int r = wm + mi * 16 + g;
                a[mi][0] = *(unsigned*)&Qs[r][kb + 2 * tig];
                a[mi][1] = *(unsigned*)&Qs[r + 8][kb + 2 * tig];
                a[mi][2] = *(unsigned*)&Qs[r][kb + 2 * tig + 8];
                a[mi][3] = *(unsigned*)&Qs[r + 8][kb + 2 * tig + 8];
            }
            #pragma unroll
            for (int ni = 0; ni < 4; ++ni) {
                int r = wn + ni * 8 + g;
                bb[ni][0] = *(unsigned*)&Ks[r][kb + 2 * tig];
                bb[ni][1] = *(unsigned*)&Ks[r][kb + 2 * tig + 8];
            }
            #pragma unroll
            for (int mi = 0; mi < 4; ++mi)
                #pragma unroll
                for (int ni = 0; ni < 4; ++ni)
                    mma_f16(s[mi][ni][0], s[mi][ni][1], s[mi][ni][2], s[mi][ni][3],
                            a[mi][0], a[mi][1], a[mi][2], a[mi][3], bb[ni][0], bb[ni][1]);
        }
        #pragma unroll
        for (int mi = 0; mi < 4; ++mi)
            #pragma unroll
            for (int ni = 0; ni < 4; ++ni)
                #pragma unroll
                for (int j = 0; j < 4; ++j)
                    s[mi][ni][j] *= f;

        float tmax[4][2];
        #pragma unroll
        for (int mi = 0; mi < 4; ++mi) {
            float h0 = -1e30f, h1 = -1e30f;
            #pragma unroll
            for (int ni = 0; ni < 4; ++ni) {
                h0 = fmaxf(h0, fmaxf(s[mi][ni][0], s[mi][ni][1]));
                h1 = fmaxf(h1, fmaxf(s[mi][ni][2], s[mi][ni][3]));
            }
            tmax[mi][0] = h0; tmax[mi][1] = h1;
        }
        #pragma unroll
        for (int off = 1; off <= 2; off <<= 1)
            #pragma unroll
            for (int mi = 0; mi < 4; ++mi) {
                tmax[mi][0] = fmaxf(tmax[mi][0], __shfl_xor_sync(0xffffffffu, tmax[mi][0], off));
                tmax[mi][1] = fmaxf(tmax[mi][1], __shfl_xor_sync(0xffffffffu, tmax[mi][1], off));
            }
        if (tig == 0) {
            #pragma unroll
            for (int mi = 0; mi < 4; ++mi) {
                red[wnid][wm + mi * 16 + g]     = tmax[mi][0];
                red[wnid][wm + mi * 16 + g + 8] = tmax[mi][1];
            }
        }
        __syncthreads();

        #pragma unroll
        for (int mi = 0; mi < 4; ++mi) {
            #pragma unroll
            for (int hh = 0; hh < 2; ++hh) {
                int row = wm + mi * 16 + g + hh * 8;
                float rm = fmaxf(fmaxf(red[0][row], red[1][row]),
                                 fmaxf(red[2][row], red[3][row]));
                float mnew = fmaxf(mrow[mi][hh], rm);
                float rs = expf(mrow[mi][hh] - mnew);
                mrow[mi][hh] = mnew;
                lrow[mi][hh] *= rs;
                #pragma unroll
                for (int ni = 0; ni < 4; ++ni) {
                    o[mi][ni][2 * hh]     *= rs;
                    o[mi][ni][2 * hh + 1] *= rs;
                }
            }
            #pragma unroll
            for (int ni = 0; ni < 4; ++ni) {
                float p0 = expf(s[mi][ni][0] - mrow[mi][0]);
                float p1 = expf(s[mi][ni][1] - mrow[mi][0]);
                float p2 = expf(s[mi][ni][2] - mrow[mi][1]);
                float p3 = expf(s[mi][ni][3] - mrow[mi][1]);
                lrow[mi][0] += p0 + p1;
                lrow[mi][1] += p2 + p3;
                int c = wn + ni * 8 + 2 * tig;
                *(__half2*)&Ps[wm + mi * 16 + g][c]     = __floats2half2_rn(p0, p1);
                *(__half2*)&Ps[wm + mi * 16 + g + 8][c] = __floats2half2_rn(p2, p3);
            }
        }
        __syncthreads();

        #pragma unroll
        for (int ks = 0; ks < 8; ++ks) {
            const int kb = ks * 16;
            unsigned a[4][4], bb[4][2];
            #pragma unroll
            for (int mi = 0; mi < 4; ++mi) {
                int r = wm + mi * 16 + g;
                a[mi][0] = *(unsigned*)&Ps[r][kb + 2 * tig];
                a[mi][1] = *(unsigned*)&Ps[r + 8][kb + 2 * tig];
                a[mi][2] = *(unsigned*)&Ps[r][kb + 2 * tig + 8];
                a[mi][3] = *(unsigned*)&Ps[r + 8][kb + 2 * tig + 8];
            }
            #pragma unroll
            for (int ni = 0; ni < 4; ++ni)
                ldsm_x2_trans(bb[ni][0], bb[ni][1], &Vs[kb + (lane & 15)][wn + ni * 8]);
            #pragma unroll
            for (int mi = 0; mi < 4; ++mi)
                #pragma unroll
                for (int ni = 0; ni < 4; ++ni)
                    mma_f16(o[mi][ni][0], o[mi][ni][1], o[mi][ni][2], o[mi][ni][3],
                            a[mi][0], a[mi][1], a[mi][2], a[mi][3], bb[ni][0], bb[ni][1]);
        }
        __syncthreads();
    }

    #pragma unroll
    for (int off = 1; off <= 2; off <<= 1)
        #pragma unroll
        for (int mi = 0; mi < 4; ++mi) {
            lrow[mi][0] += __shfl_xor_sync(0xffffffffu, lrow[mi][0], off);
            lrow[mi][1] += __shfl_xor_sync(0xffffffffu, lrow[mi][1], off);
        }
    if (tig == 0) {
        #pragma unroll
        for (int mi = 0; mi < 4; ++mi) {
            red[wnid][wm + mi * 16 + g]     = lrow[mi][0];
            red[wnid][wm + mi * 16 + g + 8] = lrow[mi][1];
        }
    }
    __syncthreads();

    const float vsc = g_scales[2];
    #pragma unroll
    for (int mi = 0; mi < 4; ++mi) {
        #pragma unroll
        for (int hh = 0; hh < 2; ++hh) {
            int row = wm + mi * 16 + g + hh * 8;
            float lt = red[0][row] + red[1][row] + red[2][row] + red[3][row];
            float inv = vsc / lt;
            int srow = i0 + row;
            #pragma unroll
            for (int ni = 0; ni < 4; ++ni) {
                int d = wn + ni * 8 + 2 * tig;
                float2 v = {o[mi][ni][2 * hh] * inv, o[mi][ni][2 * hh + 1] * inv};
                *(float2*)&g_attnout[(size_t)(b * S_ + srow) * H_ + h * HD + d] = v;
            }
        }
    }
}

// ---------------- launch ----------------
extern "C" void kernel_launch(void* const* d_in, const int* in_sizes, int n_in,
                              void* d_out, int out_size)
{
    const float* x    = (const float*)d_in[0];
    const float* Wqkv = (const float*)d_in[1];
    const float* Wout = (const float*)d_in[2];
    const float* bout = (const float*)d_in[3];
    float* y = (float*)d_out;

    float *qkv_ptr = nullptr, *ao_ptr = nullptr;
    __half *xh, *xl, *wqh, *wql, *woh, *wol, *aoh, *aol;
    cudaGetSymbolAddress((void**)&qkv_ptr, g_qkv);
    cudaGetSymbolAddress((void**)&ao_ptr,  g_attnout);
    cudaGetSymbolAddress((void**)&xh, g_xh);   cudaGetSymbolAddress((void**)&xl, g_xl);
    cudaGetSymbolAddress((void**)&wqh, g_wqh); cudaGetSymbolAddress((void**)&wql, g_wql);
    cudaGetSymbolAddress((void**)&woh, g_woh); cudaGetSymbolAddress((void**)&wol, g_wol);
    cudaGetSymbolAddress((void**)&aoh, g_aoh); cudaGetSymbolAddress((void**)&aol, g_aol);

    static int attr_set = 0;
    const int FLASH_SMEM = 4 * 34816 + 4 * 128 * 4;
    if (!attr_set) {
        cudaFuncSetAttribute(flash_kernel,
                             cudaFuncAttributeMaxDynamicSharedMemorySize, FLASH_SMEM);
        cudaFuncSetAttribute(hgemm2,
                             cudaFuncAttributeMaxDynamicSharedMemorySize, G2_SMEM);
        attr_set = 1;
    }

    zero_kernel<<<1, 32>>>();

    // prep: splits + weight transposes
    split_kernel<<<(M1 * H_ / 4 + 255) / 256, 256>>>(x, xh, xl, M1 * H_ / 4);
    tsplit_kernel<<<dim3(H3 / 32, H_ / 32), dim3(32, 8)>>>(Wqkv, wqh, wql, H_, H3);
    tsplit_kernel<<<dim3(H_ / 32, H_ / 32), dim3(32, 8)>>>(Wout, woh, wol, H_, H_);

    // 1) qkv = x @ W_qkv  (fp16x3, absmax fused in epilogue)
    hgemm2<<<dim3(H3 / 128, M1 / 128), 256, G2_SMEM>>>(
        xh, xl, wqh, wql, qkv_ptr, M1, H3, H_, nullptr, 1);

    // 2) scales, 3) quantize
    scales_kernel<<<1, 32>>>();
    quant_kernel<<<(3 * PLANE) / 256, 256>>>();

    // 4-6) fused flash attention
    flash_kernel<<<dim3(S_ / BQ, B_ * NH), 256, FLASH_SMEM>>>();

    // 7) y = attnout @ W_out + b_out  (fp16x3)
    split_kernel<<<(M1 * H_ / 4 + 255) / 256, 256>>>(ao_ptr, aoh, aol, M1 * H_ / 4);
    hgemm2<<<dim3(H_ / 128, M1 / 128), 256, G2_SMEM>>>(
        aoh, aol, woh, wol, y, M1, H_, H_, bout, 0);
}

// round 8
// speedup vs baseline: 4.0003x; 1.0076x over previous
#include <cuda_runtime.h>
#include <cuda_fp16.h>
#include <cuda_fp8.h>
#include <math.h>

// ---------------- problem constants ----------------
#define B_   2
#define S_   2048
#define H_   2048
#define NH   16
#define HD   128
#define H3   (3 * H_)
#define M1   (B_ * S_)
#define PLANE (B_ * NH * S_ * HD)
#define BQ   128

// ---------------- scratch ----------------
__device__ float         g_qkv[(size_t)M1 * H3];
__device__ unsigned char g_q8[(size_t)3 * PLANE];
__device__ float         g_attnout[(size_t)M1 * H_];
__device__ unsigned int  g_absmax[3];
__device__ float         g_scales[3];
__device__ __half        g_xh[(size_t)M1 * H_],  g_xl[(size_t)M1 * H_];
__device__ __half        g_wqh[(size_t)H3 * H_], g_wql[(size_t)H3 * H_];
__device__ __half        g_woh[(size_t)H_ * H_], g_wol[(size_t)H_ * H_];
__device__ __half        g_aoh[(size_t)M1 * H_], g_aol[(size_t)M1 * H_];

// ---------------- helpers ----------------
__device__ __forceinline__ unsigned short f8_to_h(unsigned char v) {
    __half_raw hr = __nv_cvt_fp8_to_halfraw(v, __NV_E4M3);
    return hr.x;
}
__device__ __forceinline__ unsigned f8x2_to_h2(unsigned two) {
    return (unsigned)f8_to_h(two & 0xff) | ((unsigned)f8_to_h((two >> 8) & 0xff) << 16);
}

__device__ __forceinline__ void mma_f16(float& d0, float& d1, float& d2, float& d3,
                                        unsigned a0, unsigned a1, unsigned a2, unsigned a3,
                                        unsigned b0, unsigned b1) {
    asm volatile("mma.sync.aligned.m16n8k16.row.col.f32.f16.f16.f32 "
                 "{%0,%1,%2,%3}, {%4,%5,%6,%7}, {%8,%9}, {%0,%1,%2,%3};"
                 : "+f"(d0), "+f"(d1), "+f"(d2), "+f"(d3)
                 : "r"(a0), "r"(a1), "r"(a2), "r"(a3), "r"(b0), "r"(b1));
}
__device__ __forceinline__ void ldsm_x2_trans(unsigned& r0, unsigned& r1, const void* p) {
    unsigned addr = (unsigned)__cvta_generic_to_shared(p);
    asm volatile("ldmatrix.sync.aligned.m8n8.x2.trans.shared.b16 {%0,%1}, [%2];"
                 : "=r"(r0), "=r"(r1) : "r"(addr));
}
__device__ __forceinline__ void ldsm_x4(unsigned* r, const void* p) {
    unsigned addr = (unsigned)__cvta_generic_to_shared(p);
    asm volatile("ldmatrix.sync.aligned.m8n8.x4.shared.b16 {%0,%1,%2,%3}, [%4];"
                 : "=r"(r[0]), "=r"(r[1]), "=r"(r[2]), "=r"(r[3]) : "r"(addr));
}

#define SWZ(x) ((x) ^ (((x) >> 3) & 0x70))

__device__ __forceinline__ unsigned smem_u32(const void* p) {
    return (unsigned)__cvta_generic_to_shared(p);
}
__device__ __forceinline__ void cpa16(unsigned dst, const void* src) {
    asm volatile("cp.async.cg.shared.global [%0], [%1], 16;" :: "r"(dst), "l"(src));
}
__device__ __forceinline__ void cpa_commit() { asm volatile("cp.async.commit_group;" ::: "memory"); }
__device__ __forceinline__ void cpa_waitall() { asm volatile("cp.async.wait_group 0;" ::: "memory"); }

__global__ void zero_kernel() {
    if (threadIdx.x < 3) g_absmax[threadIdx.x] = 0u;
}

// ---------------- prep: elementwise fp32 -> fp16 hi/lo split ----------------
__global__ void split_kernel(const float* __restrict__ src, __half* __restrict__ dh,
                             __half* __restrict__ dl, int n4) {
    int i = blockIdx.x * blockDim.x + threadIdx.x;
    if (i >= n4) return;
    float4 v = ((const float4*)src)[i];
    float vv[4] = {v.x, v.y, v.z, v.w};
    __half h[4], l[4];
    #pragma unroll
    for (int j = 0; j < 4; ++j) {
        h[j] = __float2half_rn(vv[j]);
        l[j] = __float2half_rn(vv[j] - __half2float(h[j]));
    }
    ((__half2*)dh)[i * 2]     = __halves2half2(h[0], h[1]);
    ((__half2*)dh)[i * 2 + 1] = __halves2half2(h[2], h[3]);
    ((__half2*)dl)[i * 2]     = __halves2half2(l[0], l[1]);
    ((__half2*)dl)[i * 2 + 1] = __halves2half2(l[2], l[3]);
}

// ---------------- prep: transpose + split  W[K][N] -> T[N][K] hi/lo (vectorized) --
__global__ void tsplit_kernel(const float* __restrict__ W, __half* __restrict__ Th,
                              __half* __restrict__ Tl, int K, int N) {
    __shared__ float tile[32][33];
    const int n0 = blockIdx.x * 32, k0 = blockIdx.y * 32;
    const int tid = threadIdx.x;            // 256 threads
    const int tx = tid & 31, ty = tid >> 5;
    #pragma unroll
    for (int i = ty; i < 32; i += 8)
        tile[i][tx] = W[(size_t)(k0 + i) * N + n0 + tx];
    __syncthreads();
    // each thread: one n-row (j), 4 consecutive k (kg..kg+3)
    const int j = tid >> 3, kg = (tid & 7) << 2;
    __half h[4], l[4];
    #pragma unroll
    for (int p = 0; p < 4; ++p) {
        float v = tile[kg + p][j];
        h[p] = __float2half_rn(v);
        l[p] = __float2half_rn(v - __half2float(h[p]));
    }
    uint2 uh, ul;
    __half2 t;
    t = __halves2half2(h[0], h[1]); uh.x = *(unsigned*)&t;
    t = __halves2half2(h[2], h[3]); uh.y = *(unsigned*)&t;
    t = __halves2half2(l[0], l[1]); ul.x = *(unsigned*)&t;
    t = __halves2half2(l[2], l[3]); ul.y = *(unsigned*)&t;
    *(uint2*)&Th[(size_t)(n0 + j) * K + k0 + kg] = uh;
    *(uint2*)&Tl[(size_t)(n0 + j) * K + k0 + kg] = ul;
}

// ============ fp16x3 GEMM v3: ldmatrix frag loads, swizzled cp.async pipeline =====
#define RG_SZ   16384
#define ST_SZ   65536
#define G2_SMEM 131072

__global__ __launch_bounds__(256, 1) void hgemm2(
    const __half* __restrict__ Agh, const __half* __restrict__ Agl,
    const __half* __restrict__ Bgh, const __half* __restrict__ Bgl,
    float* __restrict__ C, int M, int N, int K,
    const float* __restrict__ bias, int do_absmax)
{
    extern __shared__ char smraw[];
    const unsigned sb = smem_u32(smraw);
    const int tid = threadIdx.x, wid = tid >> 5, lane = tid & 31;
    const int g = lane >> 2, tig = lane & 3;
    const int m0 = blockIdx.y * 128, n0 = blockIdx.x * 128;
    const int wm = (wid & 1) * 64, wn = (wid >> 1) * 32;

    // ldmatrix lane selectors (loop-invariant)
    const int rsel = (lane & 7) | (((lane >> 3) & 1) << 3);  // 0..15 row within 16-block
    const int ksel = (lane >> 4) << 3;                       // 0 or 8 (halves)
    const int brow = lane & 7;
    const int bm   = lane >> 3;                              // 0..3

    float acc[4][4][4] = {};

    const int fr = tid >> 1;
    const int fg = (tid & 1) << 2;

    auto fill = [&](int stage, int k0) {
        const __half* s0 = Agh + (size_t)(m0 + fr) * K + k0 + fg * 8;
        const __half* s1 = Agl + (size_t)(m0 + fr) * K + k0 + fg * 8;
        const __half* s2 = Bgh + (size_t)(n0 + fr) * K + k0 + fg * 8;
        const __half* s3 = Bgl + (size_t)(n0 + fr) * K + k0 + fg * 8;
        unsigned base = sb + stage * ST_SZ;
        #pragma unroll
        for (int p = 0; p < 4; ++p) {
            unsigned d = SWZ((unsigned)(fr * 128 + (fg + p) * 16));
            cpa16(base + 0 * RG_SZ + d, s0 + p * 8);
            cpa16(base + 1 * RG_SZ + d, s1 + p * 8);
            cpa16(base + 2 * RG_SZ + d, s2 + p * 8);
            cpa16(base + 3 * RG_SZ + d, s3 + p * 8);
        }
        cpa_commit();
    };

    fill(0, 0);
    cpa_waitall(); __syncthreads();

    const int T = K >> 6;
    for (int t = 0; t < T; ++t) {
        const int stage = t & 1;
        if (t + 1 < T) fill(stage ^ 1, (t + 1) << 6);

        const char* Ah = smraw + stage * ST_SZ;
        const char* Al = Ah + RG_SZ;
        const char* Bh = Ah + 2 * RG_SZ;
        const char* Bl = Ah + 3 * RG_SZ;

        #pragma unroll
        for (int ks = 0; ks < 4; ++ks) {
            const int kb = ks * 16;
            unsigned ah[4][4], al[4][4], bh[4][2], bl[4][2];
            #pragma unroll
            for (int mi = 0; mi < 4; ++mi) {
                unsigned off = SWZ((unsigned)((wm + mi * 16 + rsel) * 128 + (kb + ksel) * 2));
                ldsm_x4(ah[mi], Ah + off);
                ldsm_x4(al[mi], Al + off);
            }
            #pragma unroll
            for (int np = 0; np < 2; ++np) {
                unsigned off = SWZ((unsigned)((wn + (np * 2 + (bm >> 1)) * 8 + brow) * 128
                                              + (kb + (bm & 1) * 8) * 2));
                unsigned r[4];
                ldsm_x4(r, Bh + off);
                bh[2 * np][0] = r[0]; bh[2 * np][1] = r[1];
                bh[2 * np + 1][0] = r[2]; bh[2 * np + 1][1] = r[3];
                ldsm_x4(r, Bl + off);
                bl[2 * np][0] = r[0]; bl[2 * np][1] = r[1];
                bl[2 * np + 1][0] = r[2]; bl[2 * np + 1][1] = r[3];
            }
            #pragma unroll
            for (int mi = 0; mi < 4; ++mi)
                #pragma unroll
                for (int ni = 0; ni < 4; ++ni)
                    mma_f16(acc[mi][ni][0], acc[mi][ni][1], acc[mi][ni][2], acc[mi][ni][3],
                            ah[mi][0], ah[mi][1], ah[mi][2], ah[mi][3], bh[ni][0], bh[ni][1]);
            #pragma unroll
            for (int mi = 0; mi < 4; ++mi)
                #pragma unroll
                for (int ni = 0; ni < 4; ++ni)
                    mma_f16(acc[mi][ni][0], acc[mi][ni][1], acc[mi][ni][2], acc[mi][ni][3],
                            ah[mi][0], ah[mi][1], ah[mi][2], ah[mi][3], bl[ni][0], bl[ni][1]);
            #pragma unroll
            for (int mi = 0; mi < 4; ++mi)
                #pragma unroll
                for (int ni = 0; ni < 4; ++ni)
                    mma_f16(acc[mi][ni][0], acc[mi][ni][1], acc[mi][ni][2], acc[mi][ni][3],
                            al[mi][0], al[mi][1], al[mi][2], al[mi][3], bh[ni][0], bh[ni][1]);
        }

        if (t + 1 < T) { cpa_waitall(); __syncthreads(); }
    }

    float lmax = 0.0f;
    #pragma unroll
    for (int mi = 0; mi < 4; ++mi) {
        int r = m0 + wm + mi * 16 + g;
        #pragma unroll
        for (int ni = 0; ni < 4; ++ni) {
            int c = n0 + wn + ni * 8 + 2 * tig;
            float2 v0 = {acc[mi][ni][0], acc[mi][ni][1]};
            float2 v1 = {acc[mi][ni][2], acc[mi][ni][3]};
            if (bias) {
                float b0 = bias[c], b1 = bias[c + 1];
                v0.x += b0; v0.y += b1;
                v1.x += b0; v1.y += b1;
            }
            if (do_absmax) {
                lmax = fmaxf(lmax, fmaxf(fmaxf(fabsf(v0.x), fabsf(v0.y)),
                                         fmaxf(fabsf(v1.x), fabsf(v1.y))));
            }
            *(float2*)&C[(size_t)r * N + c] = v0;
            *(float2*)&C[(size_t)(r + 8) * N + c] = v1;
        }
    }
    if (do_absmax) {
        #pragma unroll
        for (int o = 16; o; o >>= 1)
            lmax = fmaxf(lmax, __shfl_xor_sync(0xffffffffu, lmax, o));
        if (lane == 0) atomicMax(&g_absmax[n0 >> 11], __float_as_uint(lmax));
    }
}

// ---------------- scales / quant ----------------
__global__ void scales_kernel() {
    if (threadIdx.x < 3)
        g_scales[threadIdx.x] = __uint_as_float(g_absmax[threadIdx.x]) / 448.0f;
}

__global__ void quant_kernel() {
    int idx = blockIdx.x * blockDim.x + threadIdx.x;
    if (idx >= 3 * PLANE) return;
    int t = idx / PLANE;
    int rem = idx - t * PLANE;
    int d = rem & 127;
    int s = (rem >> 7) & 2047;
    int bh = rem >> 18;
    int b = bh >> 4, h = bh & 15;
    float v = g_qkv[(size_t)(b * S_ + s) * H3 + t * H_ + h * HD + d];
    g_q8[idx] = __nv_cvt_float_to_fp8(v / g_scales[t], __NV_SATFINITE, __NV_E4M3);
}

// ============ fused flash attention (ldmatrix frag loads) ============
__global__ __launch_bounds__(256, 1) void flash_kernel() {
    extern __shared__ char smraw[];
    typedef __half HRow[136];
    HRow* Qs = (HRow*)smraw;
    HRow* Ks = (HRow*)(smraw + 34816);
    HRow* Vs = (HRow*)(smraw + 2 * 34816);
    HRow* Ps = (HRow*)(smraw + 3 * 34816);
    float (*red)[128] = (float(*)[128])(smraw + 4 * 34816);

    const int tid = threadIdx.x, lane = tid & 31, wid = tid >> 5;
    const int g = lane >> 2, tig = lane & 3;
    const int wm = (wid & 1) * 64, wn = (wid >> 1) * 32;
    const int wnid = wid >> 1;
    const int bh = blockIdx.y;
    const int b = bh >> 4, h = bh & 15;
    const int i0 = blockIdx.x * BQ;
    const unsigned char* qp = g_q8 + (size_t)bh * (S_ * HD);
    const unsigned char* kp = g_q8 + (size_t)PLANE + (size_t)bh * (S_ * HD);
    const unsigned char* vp = g_q8 + 2 * (size_t)PLANE + (size_t)bh * (S_ * HD);
    const float f = g_scales[0] * g_scales[1] * 0.08838834764831843f;

    const int rsel = (lane & 7) | (((lane >> 3) & 1) << 3);
    const int ksel = (lane >> 4) << 3;
    const int brow = lane & 7;
    const int bm   = lane >> 3;

    #pragma unroll
    for (int p = 0; p < 16; ++p) {
        int lin = tid + p * 256;
        int r = lin >> 5, c = (lin & 31) << 2;
        unsigned qv = *(const unsigned*)&qp[(size_t)(i0 + r) * HD + c];
        *(unsigned*)&Qs[r][c]     = f8x2_to_h2(qv);
        *(unsigned*)&Qs[r][c + 2] = f8x2_to_h2(qv >> 16);
    }

    float o[4][4][4] = {};
    float mrow[4][2], lrow[4][2];
    #pragma unroll
    for (int mi = 0; mi < 4; ++mi) {
        mrow[mi][0] = mrow[mi][1] = -1e30f;
        lrow[mi][0] = lrow[mi][1] = 0.0f;
    }

    for (int kt = 0; kt < S_ / BQ; ++kt) {
        const unsigned char* kb8 = kp + (size_t)kt * BQ * HD;
        const unsigned char* vb8 = vp + (size_t)kt * BQ * HD;
        #pragma unroll
        for (int p = 0; p < 16; ++p) {
            int lin = tid + p * 256;
            int r = lin >> 5, c = (lin & 31) << 2;
            unsigned kv = *(const unsigned*)&kb8[(size_t)r * HD + c];
            unsigned vv = *(const unsigned*)&vb8[(size_t)r * HD + c];
            *(unsigned*)&Ks[r][c]     = f8x2_to_h2(kv);
            *(unsigned*)&Ks[r][c + 2] = f8x2_to_h2(kv >> 16);
            *(unsigned*)&Vs[r][c]     = f8x2_to_h2(vv);
            *(unsigned*)&Vs[r][c + 2] = f8x2_to_h2(vv >> 16);
        }
        __syncthreads();

        float s[4][4][4] = {};
        #pragma unroll
        for (int ks = 0; ks < 8; ++ks) {
            const int kb = ks * 16;
            unsigned a[4][4], bb[4][2];
            #pragma unroll
            for (int mi = 0; mi < 4; ++mi)
                ldsm_x4(a[mi], &Qs[wm + mi * 16 + rsel][kb + ksel]);
            #pragma unroll
            for (int np = 0; np < 2; ++np) {
                unsigned r[4];
                ldsm_x4(r, &Ks[wn + (np * 2 + (bm >> 1)) * 8 + brow][kb + (bm & 1) * 8]);
                bb[2 * np][0] = r[0]; bb[2 * np][1] = r[1];
                bb[2 * np + 1][0] = r[2]; bb[2 * np + 1][1] = r[3];
            }
            #pragma unroll
            for (int mi = 0; mi < 4; ++mi)
                #pragma unroll
                for (int ni = 0; ni < 4; ++ni)
                    mma_f16(s[mi][ni][0], s[mi][ni][1], s[mi][ni][2], s[mi][ni][3],
                            a[mi][0], a[mi][1], a[mi][2], a[mi][3], bb[ni][0], bb[ni][1]);
        }
        #pragma unroll
        for (int mi = 0; mi < 4; ++mi)
            #pragma unroll
            for (int ni = 0; ni < 4; ++ni)
                #pragma unroll
                for (int j = 0; j < 4; ++j)
                    s[mi][ni][j] *= f;

        float tmax[4][2];
        #pragma unroll
        for (int mi = 0; mi < 4; ++mi) {
            float h0 = -1e30f, h1 = -1e30f;
            #pragma unroll
            for (int ni = 0; ni < 4; ++ni) {
                h0 = fmaxf(h0, fmaxf(s[mi][ni][0], s[mi][ni][1]));
                h1 = fmaxf(h1, fmaxf(s[mi][ni][2], s[mi][ni][3]));
            }
            tmax[mi][0] = h0; tmax[mi][1] = h1;
        }
        #pragma unroll
        for (int off = 1; off <= 2; off <<= 1)
            #pragma unroll
            for (int mi = 0; mi < 4; ++mi) {
                tmax[mi][0] = fmaxf(tmax[mi][0], __shfl_xor_sync(0xffffffffu, tmax[mi][0], off));
                tmax[mi][1] = fmaxf(tmax[mi][1], __shfl_xor_sync(0xffffffffu, tmax[mi][1], off));
            }
        if (tig == 0) {
            #pragma unroll
            for (int mi = 0; mi < 4; ++mi) {
                red[wnid][wm + mi * 16 + g]     = tmax[mi][0];
                red[wnid][wm + mi * 16 + g + 8] = tmax[mi][1];
            }
        }
        __syncthreads();

        #pragma unroll
        for (int mi = 0; mi < 4; ++mi) {
            #pragma unroll
            for (int hh = 0; hh < 2; ++hh) {
                int row = wm + mi * 16 + g + hh * 8;
                float rm = fmaxf(fmaxf(red[0][row], red[1][row]),
                                 fmaxf(red[2][row], red[3][row]));
                float mnew = fmaxf(mrow[mi][hh], rm);
                float rs = expf(mrow[mi][hh] - mnew);
                mrow[mi][hh] = mnew;
                lrow[mi][hh] *= rs;
                #pragma unroll
                for (int ni = 0; ni < 4; ++ni) {
                    o[mi][ni][2 * hh]     *= rs;
                    o[mi][ni][2 * hh + 1] *= rs;
                }
            }
            #pragma unroll
            for (int ni = 0; ni < 4; ++ni) {
                float p0 = expf(s[mi][ni][0] - mrow[mi][0]);
                float p1 = expf(s[mi][ni][1] - mrow[mi][0]);
                float p2 = expf(s[mi][ni][2] - mrow[mi][1]);
                float p3 = expf(s[mi][ni][3] - mrow[mi][1]);
                lrow[mi][0] += p0 + p1;
                lrow[mi][1] += p2 + p3;
                int c = wn + ni * 8 + 2 * tig;
                *(__half2*)&Ps[wm + mi * 16 + g][c]     = __floats2half2_rn(p0, p1);
                *(__half2*)&Ps[wm + mi * 16 + g + 8][c] = __floats2half2_rn(p2, p3);
            }
        }
        __syncthreads();

        #pragma unroll
        for (int ks = 0; ks < 8; ++ks) {
            const int kb = ks * 16;
            unsigned a[4][4], bb[4][2];
            #pragma unroll
            for (int mi = 0; mi < 4; ++mi)
                ldsm_x4(a[mi], &Ps[wm + mi * 16 + rsel][kb + ksel]);
            #pragma unroll
            for (int ni = 0; ni < 4; ++ni)
                ldsm_x2_trans(bb[ni][0], bb[ni][1], &Vs[kb + (lane & 15)][wn + ni * 8]);
            #pragma unroll
            for (int mi = 0; mi < 4; ++mi)
                #pragma unroll
                for (int ni = 0; ni < 4; ++ni)
                    mma_f16(o[mi][ni][0], o[mi][ni][1], o[mi][ni][2], o[mi][ni][3],
                            a[mi][0], a[mi][1], a[mi][2], a[mi][3], bb[ni][0], bb[ni][1]);
        }
        __syncthreads();
    }

    #pragma unroll
    for (int off = 1; off <= 2; off <<= 1)
        #pragma unroll
        for (int mi = 0; mi < 4; ++mi) {
            lrow[mi][0] += __shfl_xor_sync(0xffffffffu, lrow[mi][0], off);
            lrow[mi][1] += __shfl_xor_sync(0xffffffffu, lrow[mi][1], off);
        }
    if (tig == 0) {
        #pragma unroll
        for (int mi = 0; mi < 4; ++mi) {
            red[wnid][wm + mi * 16 + g]     = lrow[mi][0];
            red[wnid][wm + mi * 16 + g + 8] = lrow[mi][1];
        }
    }
    __syncthreads();

    const float vsc = g_scales[2];
    #pragma unroll
    for (int mi = 0; mi < 4; ++mi) {
        #pragma unroll
        for (int hh = 0; hh < 2; ++hh) {
            int row = wm + mi * 16 + g + hh * 8;
            float lt = red[0][row] + red[1][row] + red[2][row] + red[3][row];
            float inv = vsc / lt;
            int srow = i0 + row;
            #pragma unroll
            for (int ni = 0; ni < 4; ++ni) {
                int d = wn + ni * 8 + 2 * tig;
                float2 v = {o[mi][ni][2 * hh] * inv, o[mi][ni][2 * hh + 1] * inv};
                *(float2*)&g_attnout[(size_t)(b * S_ + srow) * H_ + h * HD + d] = v;
            }
        }
    }
}

// ---------------- launch ----------------
extern "C" void kernel_launch(void* const* d_in, const int* in_sizes, int n_in,
                              void* d_out, int out_size)
{
    const float* x    = (const float*)d_in[0];
    const float* Wqkv = (const float*)d_in[1];
    const float* Wout = (const float*)d_in[2];
    const float* bout = (const float*)d_in[3];
    float* y = (float*)d_out;

    float *qkv_ptr = nullptr, *ao_ptr = nullptr;
    __half *xh, *xl, *wqh, *wql, *woh, *wol, *aoh, *aol;
    cudaGetSymbolAddress((void**)&qkv_ptr, g_qkv);
    cudaGetSymbolAddress((void**)&ao_ptr,  g_attnout);
    cudaGetSymbolAddress((void**)&xh, g_xh);   cudaGetSymbolAddress((void**)&xl, g_xl);
    cudaGetSymbolAddress((void**)&wqh, g_wqh); cudaGetSymbolAddress((void**)&wql, g_wql);
    cudaGetSymbolAddress((void**)&woh, g_woh); cudaGetSymbolAddress((void**)&wol, g_wol);
    cudaGetSymbolAddress((void**)&aoh, g_aoh); cudaGetSymbolAddress((void**)&aol, g_aol);

    static int attr_set = 0;
    const int FLASH_SMEM = 4 * 34816 + 4 * 128 * 4;
    if (!attr_set) {
        cudaFuncSetAttribute(flash_kernel,
                             cudaFuncAttributeMaxDynamicSharedMemorySize, FLASH_SMEM);
        cudaFuncSetAttribute(hgemm2,
                             cudaFuncAttributeMaxDynamicSharedMemorySize, G2_SMEM);
        attr_set = 1;
    }

    zero_kernel<<<1, 32>>>();

    split_kernel<<<(M1 * H_ / 4 + 255) / 256, 256>>>(x, xh, xl, M1 * H_ / 4);
    tsplit_kernel<<<dim3(H3 / 32, H_ / 32), 256>>>(Wqkv, wqh, wql, H_, H3);
    tsplit_kernel<<<dim3(H_ / 32, H_ / 32), 256>>>(Wout, woh, wol, H_, H_);

    hgemm2<<<dim3(H3 / 128, M1 / 128), 256, G2_SMEM>>>(
        xh, xl, wqh, wql, qkv_ptr, M1, H3, H_, nullptr, 1);

    scales_kernel<<<1, 32>>>();
    quant_kernel<<<(3 * PLANE) / 256, 256>>>();

    flash_kernel<<<dim3(S_ / BQ, B_ * NH), 256, FLASH_SMEM>>>();

    split_kernel<<<(M1 * H_ / 4 + 255) / 256, 256>>>(ao_ptr, aoh, aol, M1 * H_ / 4);
    hgemm2<<<dim3(H_ / 128, M1 / 128), 256, G2_SMEM>>>(
        aoh, aol, woh, wol, y, M1, H_, H_, bout, 0);
}

// round 9
// speedup vs baseline: 4.1926x; 1.0481x over previous
#include <cuda_runtime.h>
#include <cuda_fp16.h>
#include <cuda_fp8.h>
#include <math.h>

// ---------------- problem constants ----------------
#define B_   2
#define S_   2048
#define H_   2048
#define NH   16
#define HD   128
#define H3   (3 * H_)
#define M1   (B_ * S_)
#define PLANE (B_ * NH * S_ * HD)
#define BQ   128

// ---------------- scratch ----------------
__device__ float         g_qkv[(size_t)M1 * H3];
__device__ unsigned char g_q8[(size_t)3 * PLANE];
__device__ unsigned int  g_absmax[3];
__device__ float         g_scales[3];
__device__ __half        g_xh[(size_t)M1 * H_],  g_xl[(size_t)M1 * H_];
__device__ __half        g_wqh[(size_t)H3 * H_], g_wql[(size_t)H3 * H_];
__device__ __half        g_woh[(size_t)H_ * H_], g_wol[(size_t)H_ * H_];
__device__ __half        g_aoh[(size_t)M1 * H_];          // attnout, fp16 (hi only)

// ---------------- helpers ----------------
__device__ __forceinline__ unsigned short f8_to_h(unsigned char v) {
    __half_raw hr = __nv_cvt_fp8_to_halfraw(v, __NV_E4M3);
    return hr.x;
}
__device__ __forceinline__ unsigned f8x2_to_h2(unsigned two) {
    return (unsigned)f8_to_h(two & 0xff) | ((unsigned)f8_to_h((two >> 8) & 0xff) << 16);
}

__device__ __forceinline__ void mma_f16(float& d0, float& d1, float& d2, float& d3,
                                        unsigned a0, unsigned a1, unsigned a2, unsigned a3,
                                        unsigned b0, unsigned b1) {
    asm volatile("mma.sync.aligned.m16n8k16.row.col.f32.f16.f16.f32 "
                 "{%0,%1,%2,%3}, {%4,%5,%6,%7}, {%8,%9}, {%0,%1,%2,%3};"
                 : "+f"(d0), "+f"(d1), "+f"(d2), "+f"(d3)
                 : "r"(a0), "r"(a1), "r"(a2), "r"(a3), "r"(b0), "r"(b1));
}
__device__ __forceinline__ void ldsm_x2_trans(unsigned& r0, unsigned& r1, const void* p) {
    unsigned addr = (unsigned)__cvta_generic_to_shared(p);
    asm volatile("ldmatrix.sync.aligned.m8n8.x2.trans.shared.b16 {%0,%1}, [%2];"
                 : "=r"(r0), "=r"(r1) : "r"(addr));
}
__device__ __forceinline__ void ldsm_x4(unsigned* r, const void* p) {
    unsigned addr = (unsigned)__cvta_generic_to_shared(p);
    asm volatile("ldmatrix.sync.aligned.m8n8.x4.shared.b16 {%0,%1,%2,%3}, [%4];"
                 : "=r"(r[0]), "=r"(r[1]), "=r"(r[2]), "=r"(r[3]) : "r"(addr));
}

#define SWZ(x) ((x) ^ (((x) >> 3) & 0x70))

__device__ __forceinline__ unsigned smem_u32(const void* p) {
    return (unsigned)__cvta_generic_to_shared(p);
}
__device__ __forceinline__ void cpa16(unsigned dst, const void* src) {
    asm volatile("cp.async.cg.shared.global [%0], [%1], 16;" :: "r"(dst), "l"(src));
}
__device__ __forceinline__ void cpa_commit() { asm volatile("cp.async.commit_group;" ::: "memory"); }
__device__ __forceinline__ void cpa_waitall() { asm volatile("cp.async.wait_group 0;" ::: "memory"); }

__global__ void zero_kernel() {
    if (threadIdx.x < 3) g_absmax[threadIdx.x] = 0u;
}

// ---------------- prep: elementwise fp32 -> fp16 hi/lo split ----------------
__global__ void split_kernel(const float* __restrict__ src, __half* __restrict__ dh,
                             __half* __restrict__ dl, int n4) {
    int i = blockIdx.x * blockDim.x + threadIdx.x;
    if (i >= n4) return;
    float4 v = ((const float4*)src)[i];
    float vv[4] = {v.x, v.y, v.z, v.w};
    __half h[4], l[4];
    #pragma unroll
    for (int j = 0; j < 4; ++j) {
        h[j] = __float2half_rn(vv[j]);
        l[j] = __float2half_rn(vv[j] - __half2float(h[j]));
    }
    ((__half2*)dh)[i * 2]     = __halves2half2(h[0], h[1]);
    ((__half2*)dh)[i * 2 + 1] = __halves2half2(h[2], h[3]);
    ((__half2*)dl)[i * 2]     = __halves2half2(l[0], l[1]);
    ((__half2*)dl)[i * 2 + 1] = __halves2half2(l[2], l[3]);
}

// ---------------- prep: transpose + split  W[K][N] -> T[N][K] hi/lo ----------------
__global__ void tsplit_kernel(const float* __restrict__ W, __half* __restrict__ Th,
                              __half* __restrict__ Tl, int K, int N) {
    __shared__ float tile[32][33];
    const int n0 = blockIdx.x * 32, k0 = blockIdx.y * 32;
    const int tid = threadIdx.x;
    const int tx = tid & 31, ty = tid >> 5;
    #pragma unroll
    for (int i = ty; i < 32; i += 8)
        tile[i][tx] = W[(size_t)(k0 + i) * N + n0 + tx];
    __syncthreads();
    const int j = tid >> 3, kg = (tid & 7) << 2;
    __half h[4], l[4];
    #pragma unroll
    for (int p = 0; p < 4; ++p) {
        float v = tile[kg + p][j];
        h[p] = __float2half_rn(v);
        l[p] = __float2half_rn(v - __half2float(h[p]));
    }
    uint2 uh, ul;
    __half2 t;
    t = __halves2half2(h[0], h[1]); uh.x = *(unsigned*)&t;
    t = __halves2half2(h[2], h[3]); uh.y = *(unsigned*)&t;
    t = __halves2half2(l[0], l[1]); ul.x = *(unsigned*)&t;
    t = __halves2half2(l[2], l[3]); ul.y = *(unsigned*)&t;
    *(uint2*)&Th[(size_t)(n0 + j) * K + k0 + kg] = uh;
    *(uint2*)&Tl[(size_t)(n0 + j) * K + k0 + kg] = ul;
}

// ============ fp16 split GEMM: 3-term (QKV) or 2-term (proj) ============
#define RG_SZ   16384
#define ST_SZ   65536
#define G2_SMEM 131072

__global__ __launch_bounds__(256, 1) void hgemm2(
    const __half* __restrict__ Agh, const __half* __restrict__ Agl,
    const __half* __restrict__ Bgh, const __half* __restrict__ Bgl,
    float* __restrict__ C, int M, int N, int K,
    const float* __restrict__ bias, int do_absmax, int three)
{
    extern __shared__ char smraw[];
    const unsigned sb = smem_u32(smraw);
    const int tid = threadIdx.x, wid = tid >> 5, lane = tid & 31;
    const int g = lane >> 2, tig = lane & 3;
    const int m0 = blockIdx.y * 128, n0 = blockIdx.x * 128;
    const int wm = (wid & 1) * 64, wn = (wid >> 1) * 32;

    const int rsel = (lane & 7) | (((lane >> 3) & 1) << 3);
    const int ksel = (lane >> 4) << 3;
    const int brow = lane & 7;
    const int bm   = lane >> 3;

    float acc[4][4][4] = {};

    const int fr = tid >> 1;
    const int fg = (tid & 1) << 2;

    auto fill = [&](int stage, int k0) {
        const __half* s0 = Agh + (size_t)(m0 + fr) * K + k0 + fg * 8;
        const __half* s2 = Bgh + (size_t)(n0 + fr) * K + k0 + fg * 8;
        const __half* s3 = Bgl + (size_t)(n0 + fr) * K + k0 + fg * 8;
        unsigned base = sb + stage * ST_SZ;
        #pragma unroll
        for (int p = 0; p < 4; ++p) {
            unsigned d = SWZ((unsigned)(fr * 128 + (fg + p) * 16));
            cpa16(base + 0 * RG_SZ + d, s0 + p * 8);
            cpa16(base + 2 * RG_SZ + d, s2 + p * 8);
            cpa16(base + 3 * RG_SZ + d, s3 + p * 8);
        }
        if (three) {
            const __half* s1 = Agl + (size_t)(m0 + fr) * K + k0 + fg * 8;
            #pragma unroll
            for (int p = 0; p < 4; ++p) {
                unsigned d = SWZ((unsigned)(fr * 128 + (fg + p) * 16));
                cpa16(base + 1 * RG_SZ + d, s1 + p * 8);
            }
        }
        cpa_commit();
    };

    fill(0, 0);
    cpa_waitall(); __syncthreads();

    const int T = K >> 6;
    for (int t = 0; t < T; ++t) {
        const int stage = t & 1;
        if (t + 1 < T) fill(stage ^ 1, (t + 1) << 6);

        const char* Ah = smraw + stage * ST_SZ;
        const char* Al = Ah + RG_SZ;
        const char* Bh = Ah + 2 * RG_SZ;
        const char* Bl = Ah + 3 * RG_SZ;

        #pragma unroll
        for (int ks = 0; ks < 4; ++ks) {
            const int kb = ks * 16;
            unsigned ah[4][4], al[4][4], bh[4][2], bl[4][2];
            #pragma unroll
            for (int mi = 0; mi < 4; ++mi) {
                unsigned off = SWZ((unsigned)((wm + mi * 16 + rsel) * 128 + (kb + ksel) * 2));
                ldsm_x4(ah[mi], Ah + off);
                if (three) ldsm_x4(al[mi], Al + off);
            }
            #pragma unroll
            for (int np = 0; np < 2; ++np) {
                unsigned off = SWZ((unsigned)((wn + (np * 2 + (bm >> 1)) * 8 + brow) * 128
                                              + (kb + (bm & 1) * 8) * 2));
                unsigned r[4];
                ldsm_x4(r, Bh + off);
                bh[2 * np][0] = r[0]; bh[2 * np][1] = r[1];
                bh[2 * np + 1][0] = r[2]; bh[2 * np + 1][1] = r[3];
                ldsm_x4(r, Bl + off);
                bl[2 * np][0] = r[0]; bl[2 * np][1] = r[1];
                bl[2 * np + 1][0] = r[2]; bl[2 * np + 1][1] = r[3];
            }
            #pragma unroll
            for (int mi = 0; mi < 4; ++mi)
                #pragma unroll
                for (int ni = 0; ni < 4; ++ni)
                    mma_f16(acc[mi][ni][0], acc[mi][ni][1], acc[mi][ni][2], acc[mi][ni][3],
                            ah[mi][0], ah[mi][1], ah[mi][2], ah[mi][3], bh[ni][0], bh[ni][1]);
            #pragma unroll
            for (int mi = 0; mi < 4; ++mi)
                #pragma unroll
                for (int ni = 0; ni < 4; ++ni)
                    mma_f16(acc[mi][ni][0], acc[mi][ni][1], acc[mi][ni][2], acc[mi][ni][3],
                            ah[mi][0], ah[mi][1], ah[mi][2], ah[mi][3], bl[ni][0], bl[ni][1]);
            if (three) {
                #pragma unroll
                for (int mi = 0; mi < 4; ++mi)
                    #pragma unroll
                    for (int ni = 0; ni < 4; ++ni)
                        mma_f16(acc[mi][ni][0], acc[mi][ni][1], acc[mi][ni][2], acc[mi][ni][3],
                                al[mi][0], al[mi][1], al[mi][2], al[mi][3], bh[ni][0], bh[ni][1]);
            }
        }

        if (t + 1 < T) { cpa_waitall(); __syncthreads(); }
    }

    float lmax = 0.0f;
    #pragma unroll
    for (int mi = 0; mi < 4; ++mi) {
        int r = m0 + wm + mi * 16 + g;
        #pragma unroll
        for (int ni = 0; ni < 4; ++ni) {
            int c = n0 + wn + ni * 8 + 2 * tig;
            float2 v0 = {acc[mi][ni][0], acc[mi][ni][1]};
            float2 v1 = {acc[mi][ni][2], acc[mi][ni][3]};
            if (bias) {
                float b0 = bias[c], b1 = bias[c + 1];
                v0.x += b0; v0.y += b1;
                v1.x += b0; v1.y += b1;
            }
            if (do_absmax) {
                lmax = fmaxf(lmax, fmaxf(fmaxf(fabsf(v0.x), fabsf(v0.y)),
                                         fmaxf(fabsf(v1.x), fabsf(v1.y))));
            }
            *(float2*)&C[(size_t)r * N + c] = v0;
            *(float2*)&C[(size_t)(r + 8) * N + c] = v1;
        }
    }
    if (do_absmax) {
        #pragma unroll
        for (int o = 16; o; o >>= 1)
            lmax = fmaxf(lmax, __shfl_xor_sync(0xffffffffu, lmax, o));
        if (lane == 0) atomicMax(&g_absmax[n0 >> 11], __float_as_uint(lmax));
    }
}

// ---------------- scales / quant ----------------
__global__ void scales_kernel() {
    if (threadIdx.x < 3)
        g_scales[threadIdx.x] = __uint_as_float(g_absmax[threadIdx.x]) / 448.0f;
}

__global__ void quant_kernel() {
    int idx = blockIdx.x * blockDim.x + threadIdx.x;
    if (idx >= 3 * PLANE) return;
    int t = idx / PLANE;
    int rem = idx - t * PLANE;
    int d = rem & 127;
    int s = (rem >> 7) & 2047;
    int bh = rem >> 18;
    int b = bh >> 4, h = bh & 15;
    float v = g_qkv[(size_t)(b * S_ + s) * H3 + t * H_ + h * HD + d];
    g_q8[idx] = __nv_cvt_float_to_fp8(v / g_scales[t], __NV_SATFINITE, __NV_E4M3);
}

// ============ fused flash attention; epilogue writes fp16 attnout ============
__global__ __launch_bounds__(256, 1) void flash_kernel() {
    extern __shared__ char smraw[];
    typedef __half HRow[136];
    HRow* Qs = (HRow*)smraw;
    HRow* Ks = (HRow*)(smraw + 34816);
    HRow* Vs = (HRow*)(smraw + 2 * 34816);
    HRow* Ps = (HRow*)(smraw + 3 * 34816);
    float (*red)[128] = (float(*)[128])(smraw + 4 * 34816);

    const int tid = threadIdx.x, lane = tid & 31, wid = tid >> 5;
    const int g = lane >> 2, tig = lane & 3;
    const int wm = (wid & 1) * 64, wn = (wid >> 1) * 32;
    const int wnid = wid >> 1;
    const int bh = blockIdx.y;
    const int b = bh >> 4, h = bh & 15;
    const int i0 = blockIdx.x * BQ;
    const unsigned char* qp = g_q8 + (size_t)bh * (S_ * HD);
    const unsigned char* kp = g_q8 + (size_t)PLANE + (size_t)bh * (S_ * HD);
    const unsigned char* vp = g_q8 + 2 * (size_t)PLANE + (size_t)bh * (S_ * HD);
    const float f = g_scales[0] * g_scales[1] * 0.08838834764831843f;

    const int rsel = (lane & 7) | (((lane >> 3) & 1) << 3);
    const int ksel = (lane >> 4) << 3;
    const int brow = lane & 7;
    const int bm   = lane >> 3;

    #pragma unroll
    for (int p = 0; p < 16; ++p) {
        int lin = tid + p * 256;
        int r = lin >> 5, c = (lin & 31) << 2;
        unsigned qv = *(const unsigned*)&qp[(size_t)(i0 + r) * HD + c];
        *(unsigned*)&Qs[r][c]     = f8x2_to_h2(qv);
        *(unsigned*)&Qs[r][c + 2] = f8x2_to_h2(qv >> 16);
    }

    float o[4][4][4] = {};
    float mrow[4][2], lrow[4][2];
    #pragma unroll
    for (int mi = 0; mi < 4; ++mi) {
        mrow[mi][0] = mrow[mi][1] = -1e30f;
        lrow[mi][0] = lrow[mi][1] = 0.0f;
    }

    for (int kt = 0; kt < S_ / BQ; ++kt) {
        const unsigned char* kb8 = kp + (size_t)kt * BQ * HD;
        const unsigned char* vb8 = vp + (size_t)kt * BQ * HD;
        #pragma unroll
        for (int p = 0; p < 16; ++p) {
            int lin = tid + p * 256;
            int r = lin >> 5, c = (lin & 31) << 2;
            unsigned kv = *(const unsigned*)&kb8[(size_t)r * HD + c];
            unsigned vv = *(const unsigned*)&vb8[(size_t)r * HD + c];
            *(unsigned*)&Ks[r][c]     = f8x2_to_h2(kv);
            *(unsigned*)&Ks[r][c + 2] = f8x2_to_h2(kv >> 16);
            *(unsigned*)&Vs[r][c]     = f8x2_to_h2(vv);
            *(unsigned*)&Vs[r][c + 2] = f8x2_to_h2(vv >> 16);
        }
        __syncthreads();

        float s[4][4][4] = {};
        #pragma unroll
        for (int ks = 0; ks < 8; ++ks) {
            const int kb = ks * 16;
            unsigned a[4][4], bb[4][2];
            #pragma unroll
            for (int mi = 0; mi < 4; ++mi)
                ldsm_x4(a[mi], &Qs[wm + mi * 16 + rsel][kb + ksel]);
            #pragma unroll
            for (int np = 0; np < 2; ++np) {
                unsigned r[4];
                ldsm_x4(r, &Ks[wn + (np * 2 + (bm >> 1)) * 8 + brow][kb + (bm & 1) * 8]);
                bb[2 * np][0] = r[0]; bb[2 * np][1] = r[1];
                bb[2 * np + 1][0] = r[2]; bb[2 * np + 1][1] = r[3];
            }
            #pragma unroll
            for (int mi = 0; mi < 4; ++mi)
                #pragma unroll
                for (int ni = 0; ni < 4; ++ni)
                    mma_f16(s[mi][ni][0], s[mi][ni][1], s[mi][ni][2], s[mi][ni][3],
                            a[mi][0], a[mi][1], a[mi][2], a[mi][3], bb[ni][0], bb[ni][1]);
        }
        #pragma unroll
        for (int mi = 0; mi < 4; ++mi)
            #pragma unroll
            for (int ni = 0; ni < 4; ++ni)
                #pragma unroll
                for (int j = 0; j < 4; ++j)
                    s[mi][ni][j] *= f;

        float tmax[4][2];
        #pragma unroll
        for (int mi = 0; mi < 4; ++mi) {
            float h0 = -1e30f, h1 = -1e30f;
            #pragma unroll
            for (int ni = 0; ni < 4; ++ni) {
                h0 = fmaxf(h0, fmaxf(s[mi][ni][0], s[mi][ni][1]));
                h1 = fmaxf(h1, fmaxf(s[mi][ni][2], s[mi][ni][3]));
            }
            tmax[mi][0] = h0; tmax[mi][1] = h1;
        }
        #pragma unroll
        for (int off = 1; off <= 2; off <<= 1)
            #pragma unroll
            for (int mi = 0; mi < 4; ++mi) {
                tmax[mi][0] = fmaxf(tmax[mi][0], __shfl_xor_sync(0xffffffffu, tmax[mi][0], off));
                tmax[mi][1] = fmaxf(tmax[mi][1], __shfl_xor_sync(0xffffffffu, tmax[mi][1], off));
            }
        if (tig == 0) {
            #pragma unroll
            for (int mi = 0; mi < 4; ++mi) {
                red[wnid][wm + mi * 16 + g]     = tmax[mi][0];
                red[wnid][wm + mi * 16 + g + 8] = tmax[mi][1];
            }
        }
        __syncthreads();

        #pragma unroll
        for (int mi = 0; mi < 4; ++mi) {
            #pragma unroll
            for (int hh = 0; hh < 2; ++hh) {
                int row = wm + mi * 16 + g + hh * 8;
                float rm = fmaxf(fmaxf(red[0][row], red[1][row]),
                                 fmaxf(red[2][row], red[3][row]));
                float mnew = fmaxf(mrow[mi][hh], rm);
                float rs = expf(mrow[mi][hh] - mnew);
                mrow[mi][hh] = mnew;
                lrow[mi][hh] *= rs;
                #pragma unroll
                for (int ni = 0; ni < 4; ++ni) {
                    o[mi][ni][2 * hh]     *= rs;
                    o[mi][ni][2 * hh + 1] *= rs;
                }
            }
            #pragma unroll
            for (int ni = 0; ni < 4; ++ni) {
                float p0 = expf(s[mi][ni][0] - mrow[mi][0]);
                float p1 = expf(s[mi][ni][1] - mrow[mi][0]);
                float p2 = expf(s[mi][ni][2] - mrow[mi][1]);
                float p3 = expf(s[mi][ni][3] - mrow[mi][1]);
                lrow[mi][0] += p0 + p1;
                lrow[mi][1] += p2 + p3;
                int c = wn + ni * 8 + 2 * tig;
                *(__half2*)&Ps[wm + mi * 16 + g][c]     = __floats2half2_rn(p0, p1);
                *(__half2*)&Ps[wm + mi * 16 + g + 8][c] = __floats2half2_rn(p2, p3);
            }
        }
        __syncthreads();

        #pragma unroll
        for (int ks = 0; ks < 8; ++ks) {
            const int kb = ks * 16;
            unsigned a[4][4], bb[4][2];
            #pragma unroll
            for (int mi = 0; mi < 4; ++mi)
                ldsm_x4(a[mi], &Ps[wm + mi * 16 + rsel][kb + ksel]);
            #pragma unroll
            for (int ni = 0; ni < 4; ++ni)
                ldsm_x2_trans(bb[ni][0], bb[ni][1], &Vs[kb + (lane & 15)][wn + ni * 8]);
            #pragma unroll
            for (int mi = 0; mi < 4; ++mi)
                #pragma unroll
                for (int ni = 0; ni < 4; ++ni)
                    mma_f16(o[mi][ni][0], o[mi][ni][1], o[mi][ni][2], o[mi][ni][3],
                            a[mi][0], a[mi][1], a[mi][2], a[mi][3], bb[ni][0], bb[ni][1]);
        }
        __syncthreads();
    }

    #pragma unroll
    for (int off = 1; off <= 2; off <<= 1)
        #pragma unroll
        for (int mi = 0; mi < 4; ++mi) {
            lrow[mi][0] += __shfl_xor_sync(0xffffffffu, lrow[mi][0], off);
            lrow[mi][1] += __shfl_xor_sync(0xffffffffu, lrow[mi][1], off);
        }
    if (tig == 0) {
        #pragma unroll
        for (int mi = 0; mi < 4; ++mi) {
            red[wnid][wm + mi * 16 + g]     = lrow[mi][0];
            red[wnid][wm + mi * 16 + g + 8] = lrow[mi][1];
        }
    }
    __syncthreads();

    const float vsc = g_scales[2];
    #pragma unroll
    for (int mi = 0; mi < 4; ++mi) {
        #pragma unroll
        for (int hh = 0; hh < 2; ++hh) {
            int row = wm + mi * 16 + g + hh * 8;
            float lt = red[0][row] + red[1][row] + red[2][row] + red[3][row];
            float inv = vsc / lt;
            int srow = i0 + row;
            #pragma unroll
            for (int ni = 0; ni < 4; ++ni) {
                int d = wn + ni * 8 + 2 * tig;
                __half2 hv = __floats2half2_rn(o[mi][ni][2 * hh] * inv,
                                               o[mi][ni][2 * hh + 1] * inv);
                *(__half2*)&g_aoh[(size_t)(b * S_ + srow) * H_ + h * HD + d] = hv;
            }
        }
    }
}

// ---------------- launch ----------------
extern "C" void kernel_launch(void* const* d_in, const int* in_sizes, int n_in,
                              void* d_out, int out_size)
{
    const float* x    = (const float*)d_in[0];
    const float* Wqkv = (const float*)d_in[1];
    const float* Wout = (const float*)d_in[2];
    const float* bout = (const float*)d_in[3];
    float* y = (float*)d_out;

    float* qkv_ptr = nullptr;
    __half *xh, *xl, *wqh, *wql, *woh, *wol, *aoh;
    cudaGetSymbolAddress((void**)&qkv_ptr, g_qkv);
    cudaGetSymbolAddress((void**)&xh, g_xh);   cudaGetSymbolAddress((void**)&xl, g_xl);
    cudaGetSymbolAddress((void**)&wqh, g_wqh); cudaGetSymbolAddress((void**)&wql, g_wql);
    cudaGetSymbolAddress((void**)&woh, g_woh); cudaGetSymbolAddress((void**)&wol, g_wol);
    cudaGetSymbolAddress((void**)&aoh, g_aoh);

    static int attr_set = 0;
    const int FLASH_SMEM = 4 * 34816 + 4 * 128 * 4;
    if (!attr_set) {
        cudaFuncSetAttribute(flash_kernel,
                             cudaFuncAttributeMaxDynamicSharedMemorySize, FLASH_SMEM);
        cudaFuncSetAttribute(hgemm2,
                             cudaFuncAttributeMaxDynamicSharedMemorySize, G2_SMEM);
        attr_set = 1;
    }

    zero_kernel<<<1, 32>>>();

    split_kernel<<<(M1 * H_ / 4 + 255) / 256, 256>>>(x, xh, xl, M1 * H_ / 4);
    tsplit_kernel<<<dim3(H3 / 32, H_ / 32), 256>>>(Wqkv, wqh, wql, H_, H3);
    tsplit_kernel<<<dim3(H_ / 32, H_ / 32), 256>>>(Wout, woh, wol, H_, H_);

    // 1) qkv = x @ W_qkv  (fp16x3, absmax fused)
    hgemm2<<<dim3(H3 / 128, M1 / 128), 256, G2_SMEM>>>(
        xh, xl, wqh, wql, qkv_ptr, M1, H3, H_, nullptr, 1, 1);

    scales_kernel<<<1, 32>>>();
    quant_kernel<<<(3 * PLANE) / 256, 256>>>();

    // 4-6) fused flash attention; writes fp16 attnout directly
    flash_kernel<<<dim3(S_ / BQ, B_ * NH), 256, FLASH_SMEM>>>();

    // 7) y = attnout @ W_out + b_out  (fp16x2: Ah*(Bh+Bl))
    hgemm2<<<dim3(H_ / 128, M1 / 128), 256, G2_SMEM>>>(
        aoh, nullptr, woh, wol, y, M1, H_, H_, bout, 0, 0);
}

// round 10
// speedup vs baseline: 4.3157x; 1.0294x over previous
#include <cuda_runtime.h>
#include <cuda_fp16.h>
#include <cuda_fp8.h>
#include <math.h>

// ---------------- problem constants ----------------
#define B_   2
#define S_   2048
#define H_   2048
#define NH   16
#define HD   128
#define H3   (3 * H_)
#define M1   (B_ * S_)
#define PLANE (B_ * NH * S_ * HD)
#define BQ   128

// ---------------- scratch ----------------
__device__ float         g_qkv[(size_t)M1 * H3];
__device__ unsigned char g_q8[(size_t)3 * PLANE];
__device__ unsigned int  g_absmax[3];
__device__ float         g_scales[3];
__device__ __half        g_xh[(size_t)M1 * H_],  g_xl[(size_t)M1 * H_];
__device__ __half        g_wqh[(size_t)H3 * H_], g_wql[(size_t)H3 * H_];
__device__ __half        g_woh[(size_t)H_ * H_], g_wol[(size_t)H_ * H_];
__device__ __half        g_aoh[(size_t)M1 * H_];

// ---------------- helpers ----------------
__device__ __forceinline__ unsigned short f8_to_h(unsigned char v) {
    __half_raw hr = __nv_cvt_fp8_to_halfraw(v, __NV_E4M3);
    return hr.x;
}
__device__ __forceinline__ unsigned f8x2_to_h2(unsigned two) {
    return (unsigned)f8_to_h(two & 0xff) | ((unsigned)f8_to_h((two >> 8) & 0xff) << 16);
}

__device__ __forceinline__ void mma_f16(float& d0, float& d1, float& d2, float& d3,
                                        unsigned a0, unsigned a1, unsigned a2, unsigned a3,
                                        unsigned b0, unsigned b1) {
    asm volatile("mma.sync.aligned.m16n8k16.row.col.f32.f16.f16.f32 "
                 "{%0,%1,%2,%3}, {%4,%5,%6,%7}, {%8,%9}, {%0,%1,%2,%3};"
                 : "+f"(d0), "+f"(d1), "+f"(d2), "+f"(d3)
                 : "r"(a0), "r"(a1), "r"(a2), "r"(a3), "r"(b0), "r"(b1));
}
__device__ __forceinline__ void mma_f8(float& d0, float& d1, float& d2, float& d3,
                                       unsigned a0, unsigned a1, unsigned a2, unsigned a3,
                                       unsigned b0, unsigned b1) {
    asm volatile("mma.sync.aligned.m16n8k32.row.col.f32.e4m3.e4m3.f32 "
                 "{%0,%1,%2,%3}, {%4,%5,%6,%7}, {%8,%9}, {%0,%1,%2,%3};"
                 : "+f"(d0), "+f"(d1), "+f"(d2), "+f"(d3)
                 : "r"(a0), "r"(a1), "r"(a2), "r"(a3), "r"(b0), "r"(b1));
}
__device__ __forceinline__ void ldsm_x2_trans(unsigned& r0, unsigned& r1, const void* p) {
    unsigned addr = (unsigned)__cvta_generic_to_shared(p);
    asm volatile("ldmatrix.sync.aligned.m8n8.x2.trans.shared.b16 {%0,%1}, [%2];"
                 : "=r"(r0), "=r"(r1) : "r"(addr));
}
__device__ __forceinline__ void ldsm_x4(unsigned* r, const void* p) {
    unsigned addr = (unsigned)__cvta_generic_to_shared(p);
    asm volatile("ldmatrix.sync.aligned.m8n8.x4.shared.b16 {%0,%1,%2,%3}, [%4];"
                 : "=r"(r[0]), "=r"(r[1]), "=r"(r[2]), "=r"(r[3]) : "r"(addr));
}

#define SWZ(x) ((x) ^ (((x) >> 3) & 0x70))

__device__ __forceinline__ unsigned smem_u32(const void* p) {
    return (unsigned)__cvta_generic_to_shared(p);
}
__device__ __forceinline__ void cpa16(unsigned dst, const void* src) {
    asm volatile("cp.async.cg.shared.global [%0], [%1], 16;" :: "r"(dst), "l"(src));
}
__device__ __forceinline__ void cpa_commit() { asm volatile("cp.async.commit_group;" ::: "memory"); }
__device__ __forceinline__ void cpa_waitall() { asm volatile("cp.async.wait_group 0;" ::: "memory"); }

__global__ void zero_kernel() {
    if (threadIdx.x < 3) g_absmax[threadIdx.x] = 0u;
}

// ---------------- prep: elementwise fp32 -> fp16 hi/lo split ----------------
__global__ void split_kernel(const float* __restrict__ src, __half* __restrict__ dh,
                             __half* __restrict__ dl, int n4) {
    int i = blockIdx.x * blockDim.x + threadIdx.x;
    if (i >= n4) return;
    float4 v = ((const float4*)src)[i];
    float vv[4] = {v.x, v.y, v.z, v.w};
    __half h[4], l[4];
    #pragma unroll
    for (int j = 0; j < 4; ++j) {
        h[j] = __float2half_rn(vv[j]);
        l[j] = __float2half_rn(vv[j] - __half2float(h[j]));
    }
    ((__half2*)dh)[i * 2]     = __halves2half2(h[0], h[1]);
    ((__half2*)dh)[i * 2 + 1] = __halves2half2(h[2], h[3]);
    ((__half2*)dl)[i * 2]     = __halves2half2(l[0], l[1]);
    ((__half2*)dl)[i * 2 + 1] = __halves2half2(l[2], l[3]);
}

// ---------------- prep: transpose + split  W[K][N] -> T[N][K] hi/lo ----------------
__global__ void tsplit_kernel(const float* __restrict__ W, __half* __restrict__ Th,
                              __half* __restrict__ Tl, int K, int N) {
    __shared__ float tile[32][33];
    const int n0 = blockIdx.x * 32, k0 = blockIdx.y * 32;
    const int tid = threadIdx.x;
    const int tx = tid & 31, ty = tid >> 5;
    #pragma unroll
    for (int i = ty; i < 32; i += 8)
        tile[i][tx] = W[(size_t)(k0 + i) * N + n0 + tx];
    __syncthreads();
    const int j = tid >> 3, kg = (tid & 7) << 2;
    __half h[4], l[4];
    #pragma unroll
    for (int p = 0; p < 4; ++p) {
        float v = tile[kg + p][j];
        h[p] = __float2half_rn(v);
        l[p] = __float2half_rn(v - __half2float(h[p]));
    }
    uint2 uh, ul;
    __half2 t;
    t = __halves2half2(h[0], h[1]); uh.x = *(unsigned*)&t;
    t = __halves2half2(h[2], h[3]); uh.y = *(unsigned*)&t;
    t = __halves2half2(l[0], l[1]); ul.x = *(unsigned*)&t;
    t = __halves2half2(l[2], l[3]); ul.y = *(unsigned*)&t;
    *(uint2*)&Th[(size_t)(n0 + j) * K + k0 + kg] = uh;
    *(uint2*)&Tl[(size_t)(n0 + j) * K + k0 + kg] = ul;
}

// ============ fp16 split GEMM: 3-term (QKV) or 2-term (proj) ============
#define RG_SZ   16384
#define ST_SZ   65536
#define G2_SMEM 131072

__global__ __launch_bounds__(256, 1) void hgemm2(
    const __half* __restrict__ Agh, const __half* __restrict__ Agl,
    const __half* __restrict__ Bgh, const __half* __restrict__ Bgl,
    float* __restrict__ C, int M, int N, int K,
    const float* __restrict__ bias, int do_absmax, int three)
{
    extern __shared__ char smraw[];
    const unsigned sb = smem_u32(smraw);
    const int tid = threadIdx.x, wid = tid >> 5, lane = tid & 31;
    const int g = lane >> 2, tig = lane & 3;
    const int m0 = blockIdx.y * 128, n0 = blockIdx.x * 128;
    const int wm = (wid & 1) * 64, wn = (wid >> 1) * 32;

    const int rsel = (lane & 7) | (((lane >> 3) & 1) << 3);
    const int ksel = (lane >> 4) << 3;
    const int brow = lane & 7;
    const int bm   = lane >> 3;

    float acc[4][4][4] = {};

    const int fr = tid >> 1;
    const int fg = (tid & 1) << 2;

    auto fill = [&](int stage, int k0) {
        const __half* s0 = Agh + (size_t)(m0 + fr) * K + k0 + fg * 8;
        const __half* s2 = Bgh + (size_t)(n0 + fr) * K + k0 + fg * 8;
        const __half* s3 = Bgl + (size_t)(n0 + fr) * K + k0 + fg * 8;
        unsigned base = sb + stage * ST_SZ;
        #pragma unroll
        for (int p = 0; p < 4; ++p) {
            unsigned d = SWZ((unsigned)(fr * 128 + (fg + p) * 16));
            cpa16(base + 0 * RG_SZ + d, s0 + p * 8);
            cpa16(base + 2 * RG_SZ + d, s2 + p * 8);
            cpa16(base + 3 * RG_SZ + d, s3 + p * 8);
        }
        if (three) {
            const __half* s1 = Agl + (size_t)(m0 + fr) * K + k0 + fg * 8;
            #pragma unroll
            for (int p = 0; p < 4; ++p) {
                unsigned d = SWZ((unsigned)(fr * 128 + (fg + p) * 16));
                cpa16(base + 1 * RG_SZ + d, s1 + p * 8);
            }
        }
        cpa_commit();
    };

    fill(0, 0);
    cpa_waitall(); __syncthreads();

    const int T = K >> 6;
    for (int t = 0; t < T; ++t) {
        const int stage = t & 1;
        if (t + 1 < T) fill(stage ^ 1, (t + 1) << 6);

        const char* Ah = smraw + stage * ST_SZ;
        const char* Al = Ah + RG_SZ;
        const char* Bh = Ah + 2 * RG_SZ;
        const char* Bl = Ah + 3 * RG_SZ;

        #pragma unroll
        for (int ks = 0; ks < 4; ++ks) {
            const int kb = ks * 16;
            unsigned ah[4][4], al[4][4], bh[4][2], bl[4][2];
            #pragma unroll
            for (int mi = 0; mi < 4; ++mi) {
                unsigned off = SWZ((unsigned)((wm + mi * 16 + rsel) * 128 + (kb + ksel) * 2));
                ldsm_x4(ah[mi], Ah + off);
                if (three) ldsm_x4(al[mi], Al + off);
            }
            #pragma unroll
            for (int np = 0; np < 2; ++np) {
                unsigned off = SWZ((unsigned)((wn + (np * 2 + (bm >> 1)) * 8 + brow) * 128
                                              + (kb + (bm & 1) * 8) * 2));
                unsigned r[4];
                ldsm_x4(r, Bh + off);
                bh[2 * np][0] = r[0]; bh[2 * np][1] = r[1];
                bh[2 * np + 1][0] = r[2]; bh[2 * np + 1][1] = r[3];
                ldsm_x4(r, Bl + off);
                bl[2 * np][0] = r[0]; bl[2 * np][1] = r[1];
                bl[2 * np + 1][0] = r[2]; bl[2 * np + 1][1] = r[3];
            }
            #pragma unroll
            for (int mi = 0; mi < 4; ++mi)
                #pragma unroll
                for (int ni = 0; ni < 4; ++ni)
                    mma_f16(acc[mi][ni][0], acc[mi][ni][1], acc[mi][ni][2], acc[mi][ni][3],
                            ah[mi][0], ah[mi][1], ah[mi][2], ah[mi][3], bh[ni][0], bh[ni][1]);
            #pragma unroll
            for (int mi = 0; mi < 4; ++mi)
                #pragma unroll
                for (int ni = 0; ni < 4; ++ni)
                    mma_f16(acc[mi][ni][0], acc[mi][ni][1], acc[mi][ni][2], acc[mi][ni][3],
                            ah[mi][0], ah[mi][1], ah[mi][2], ah[mi][3], bl[ni][0], bl[ni][1]);
            if (three) {
                #pragma unroll
                for (int mi = 0; mi < 4; ++mi)
                    #pragma unroll
                    for (int ni = 0; ni < 4; ++ni)
                        mma_f16(acc[mi][ni][0], acc[mi][ni][1], acc[mi][ni][2], acc[mi][ni][3],
                                al[mi][0], al[mi][1], al[mi][2], al[mi][3], bh[ni][0], bh[ni][1]);
            }
        }

        if (t + 1 < T) { cpa_waitall(); __syncthreads(); }
    }

    float lmax = 0.0f;
    #pragma unroll
    for (int mi = 0; mi < 4; ++mi) {
        int r = m0 + wm + mi * 16 + g;
        #pragma unroll
        for (int ni = 0; ni < 4; ++ni) {
            int c = n0 + wn + ni * 8 + 2 * tig;
            float2 v0 = {acc[mi][ni][0], acc[mi][ni][1]};
            float2 v1 = {acc[mi][ni][2], acc[mi][ni][3]};
            if (bias) {
                float b0 = bias[c], b1 = bias[c + 1];
                v0.x += b0; v0.y += b1;
                v1.x += b0; v1.y += b1;
            }
            if (do_absmax) {
                lmax = fmaxf(lmax, fmaxf(fmaxf(fabsf(v0.x), fabsf(v0.y)),
                                         fmaxf(fabsf(v1.x), fabsf(v1.y))));
            }
            *(float2*)&C[(size_t)r * N + c] = v0;
            *(float2*)&C[(size_t)(r + 8) * N + c] = v1;
        }
    }
    if (do_absmax) {
        #pragma unroll
        for (int o = 16; o; o >>= 1)
            lmax = fmaxf(lmax, __shfl_xor_sync(0xffffffffu, lmax, o));
        if (lane == 0) atomicMax(&g_absmax[n0 >> 11], __float_as_uint(lmax));
    }
}

// ---------------- scales / quant (vectorized x4) ----------------
__global__ void scales_kernel() {
    if (threadIdx.x < 3)
        g_scales[threadIdx.x] = __uint_as_float(g_absmax[threadIdx.x]) / 448.0f;
}

__global__ void quant_kernel() {
    int i = blockIdx.x * blockDim.x + threadIdx.x;
    if (i >= 3 * PLANE / 4) return;
    int t   = i / (PLANE / 4);
    int rem = i - t * (PLANE / 4);
    int d4 = rem & 31;              // 4-wide d group
    int s  = (rem >> 5) & 2047;
    int bh = rem >> 16;
    int b = bh >> 4, h = bh & 15;
    const float sc = g_scales[t];
    float4 v = *(const float4*)&g_qkv[(size_t)(b * S_ + s) * H3 + t * H_ + h * HD + d4 * 4];
    uchar4 o;
    o.x = __nv_cvt_float_to_fp8(v.x / sc, __NV_SATFINITE, __NV_E4M3);
    o.y = __nv_cvt_float_to_fp8(v.y / sc, __NV_SATFINITE, __NV_E4M3);
    o.z = __nv_cvt_float_to_fp8(v.z / sc, __NV_SATFINITE, __NV_E4M3);
    o.w = __nv_cvt_float_to_fp8(v.w / sc, __NV_SATFINITE, __NV_E4M3);
    *(uchar4*)&g_q8[(size_t)t * PLANE + ((size_t)bh << 18) + (s << 7) + d4 * 4] = o;
}

// ============ fused flash attention: fp8 QK^T + fp16 PV ============
// smem: QB[128][144] bytes, KB[128][144] bytes, Vs/Ps fp16 [128][136], red[4][128]
#define QB_OFF 0
#define KB_OFF 18432
#define VS_OFF 36864
#define PS_OFF 71680
#define RED_OFF 106496
#define FLASH_SMEM 108544

__global__ __launch_bounds__(256, 1) void flash_kernel() {
    extern __shared__ char smraw[];
    char* QB = smraw + QB_OFF;                 // raw e4m3, row stride 144 B
    char* KB = smraw + KB_OFF;
    typedef __half HRow[136];
    HRow* Vs = (HRow*)(smraw + VS_OFF);
    HRow* Ps = (HRow*)(smraw + PS_OFF);
    float (*red)[128] = (float(*)[128])(smraw + RED_OFF);

    const int tid = threadIdx.x, lane = tid & 31, wid = tid >> 5;
    const int g = lane >> 2, tig = lane & 3;
    const int wm = (wid & 1) * 64, wn = (wid >> 1) * 32;
    const int wnid = wid >> 1;
    const int bh = blockIdx.y;
    const int b = bh >> 4, h = bh & 15;
    const int i0 = blockIdx.x * BQ;
    const unsigned char* qp = g_q8 + (size_t)bh * (S_ * HD);
    const unsigned char* kp = g_q8 + (size_t)PLANE + (size_t)bh * (S_ * HD);
    const unsigned char* vp = g_q8 + 2 * (size_t)PLANE + (size_t)bh * (S_ * HD);
    const float f = g_scales[0] * g_scales[1] * 0.08838834764831843f;

    const int rsel = (lane & 7) | (((lane >> 3) & 1) << 3);   // fp16 A-frag rows
    const int ksel = (lane >> 4) << 3;                        // fp16 A-frag k (halves)
    const int kselb = (lane >> 4) << 4;                       // fp8 A-frag k (bytes)
    const int b8row = (lane & 7);                             // fp8 B-frag
    const int b8sub = (lane >> 4);                            //   row-block selector
    const int b8k   = ((lane >> 3) & 1) << 4;                 //   k-byte selector

    // ---- Q tile: raw byte copy (uint4) ----
    #pragma unroll
    for (int p = 0; p < 4; ++p) {
        int lin = tid + p * 256;
        int r = lin >> 3, c = (lin & 7) << 4;
        *(uint4*)(QB + r * 144 + c) = *(const uint4*)&qp[(size_t)(i0 + r) * HD + c];
    }

    float o[4][4][4] = {};
    float mrow[4][2], lrow[4][2];
    #pragma unroll
    for (int mi = 0; mi < 4; ++mi) {
        mrow[mi][0] = mrow[mi][1] = -1e30f;
        lrow[mi][0] = lrow[mi][1] = 0.0f;
    }

    for (int kt = 0; kt < S_ / BQ; ++kt) {
        const unsigned char* kb8 = kp + (size_t)kt * BQ * HD;
        const unsigned char* vb8 = vp + (size_t)kt * BQ * HD;
        // K: raw byte copy
        #pragma unroll
        for (int p = 0; p < 4; ++p) {
            int lin = tid + p * 256;
            int r = lin >> 3, c = (lin & 7) << 4;
            *(uint4*)(KB + r * 144 + c) = *(const uint4*)&kb8[(size_t)r * HD + c];
        }
        // V: convert to fp16 (needed for PV fp16 MMA via ldmatrix.trans)
        #pragma unroll
        for (int p = 0; p < 16; ++p) {
            int lin = tid + p * 256;
            int r = lin >> 5, c = (lin & 31) << 2;
            unsigned vv = *(const unsigned*)&vb8[(size_t)r * HD + c];
            *(unsigned*)&Vs[r][c]     = f8x2_to_h2(vv);
            *(unsigned*)&Vs[r][c + 2] = f8x2_to_h2(vv >> 16);
        }
        __syncthreads();

        // ---- S = Q @ K^T via fp8 MMA (k32 per step, 4 steps) ----
        float s[4][4][4] = {};
        #pragma unroll
        for (int ks = 0; ks < 4; ++ks) {
            const int kb = ks * 32;           // bytes
            unsigned a[4][4], bb[4][2];
            #pragma unroll
            for (int mi = 0; mi < 4; ++mi)
                ldsm_x4(a[mi], QB + (wm + mi * 16 + rsel) * 144 + kb + kselb);
            #pragma unroll
            for (int np = 0; np < 2; ++np) {
                unsigned r[4];
                ldsm_x4(r, KB + (wn + (np * 2 + b8sub) * 8 + b8row) * 144 + kb + b8k);
                bb[2 * np][0] = r[0]; bb[2 * np][1] = r[1];
                bb[2 * np + 1][0] = r[2]; bb[2 * np + 1][1] = r[3];
            }
            #pragma unroll
            for (int mi = 0; mi < 4; ++mi)
                #pragma unroll
                for (int ni = 0; ni < 4; ++ni)
                    mma_f8(s[mi][ni][0], s[mi][ni][1], s[mi][ni][2], s[mi][ni][3],
                           a[mi][0], a[mi][1], a[mi][2], a[mi][3], bb[ni][0], bb[ni][1]);
        }
        #pragma unroll
        for (int mi = 0; mi < 4; ++mi)
            #pragma unroll
            for (int ni = 0; ni < 4; ++ni)
                #pragma unroll
                for (int j = 0; j < 4; ++j)
                    s[mi][ni][j] *= f;

        // ---- row max ----
        float tmax[4][2];
        #pragma unroll
        for (int mi = 0; mi < 4; ++mi) {
            float h0 = -1e30f, h1 = -1e30f;
            #pragma unroll
            for (int ni = 0; ni < 4; ++ni) {
                h0 = fmaxf(h0, fmaxf(s[mi][ni][0], s[mi][ni][1]));
                h1 = fmaxf(h1, fmaxf(s[mi][ni][2], s[mi][ni][3]));
            }
            tmax[mi][0] = h0; tmax[mi][1] = h1;
        }
        #pragma unroll
        for (int off = 1; off <= 2; off <<= 1)
            #pragma unroll
            for (int mi = 0; mi < 4; ++mi) {
                tmax[mi][0] = fmaxf(tmax[mi][0], __shfl_xor_sync(0xffffffffu, tmax[mi][0], off));
                tmax[mi][1] = fmaxf(tmax[mi][1], __shfl_xor_sync(0xffffffffu, tmax[mi][1], off));
            }
        if (tig == 0) {
            #pragma unroll
            for (int mi = 0; mi < 4; ++mi) {
                red[wnid][wm + mi * 16 + g]     = tmax[mi][0];
                red[wnid][wm + mi * 16 + g + 8] = tmax[mi][1];
            }
        }
        __syncthreads();

        // ---- online softmax update; write P (fp16) ----
        #pragma unroll
        for (int mi = 0; mi < 4; ++mi) {
            #pragma unroll
            for (int hh = 0; hh < 2; ++hh) {
                int row = wm + mi * 16 + g + hh * 8;
                float rm = fmaxf(fmaxf(red[0][row], red[1][row]),
                                 fmaxf(red[2][row], red[3][row]));
                float mnew = fmaxf(mrow[mi][hh], rm);
                float rs = expf(mrow[mi][hh] - mnew);
                mrow[mi][hh] = mnew;
                lrow[mi][hh] *= rs;
                #pragma unroll
                for (int ni = 0; ni < 4; ++ni) {
                    o[mi][ni][2 * hh]     *= rs;
                    o[mi][ni][2 * hh + 1] *= rs;
                }
            }
            #pragma unroll
            for (int ni = 0; ni < 4; ++ni) {
                float p0 = expf(s[mi][ni][0] - mrow[mi][0]);
                float p1 = expf(s[mi][ni][1] - mrow[mi][0]);
                float p2 = expf(s[mi][ni][2] - mrow[mi][1]);
                float p3 = expf(s[mi][ni][3] - mrow[mi][1]);
                lrow[mi][0] += p0 + p1;
                lrow[mi][1] += p2 + p3;
                int c = wn + ni * 8 + 2 * tig;
                *(__half2*)&Ps[wm + mi * 16 + g][c]     = __floats2half2_rn(p0, p1);
                *(__half2*)&Ps[wm + mi * 16 + g + 8][c] = __floats2half2_rn(p2, p3);
            }
        }
        __syncthreads();

        // ---- O += P @ V (fp16 MMA; V B-frags via ldmatrix.trans) ----
        #pragma unroll
        for (int ks = 0; ks < 8; ++ks) {
            const int kb = ks * 16;
            unsigned a[4][4], bb[4][2];
            #pragma unroll
            for (int mi = 0; mi < 4; ++mi)
                ldsm_x4(a[mi], &Ps[wm + mi * 16 + rsel][kb + ksel]);
            #pragma unroll
            for (int ni = 0; ni < 4; ++ni)
                ldsm_x2_trans(bb[ni][0], bb[ni][1], &Vs[kb + (lane & 15)][wn + ni * 8]);
            #pragma unroll
            for (int mi = 0; mi < 4; ++mi)
                #pragma unroll
                for (int ni = 0; ni < 4; ++ni)
                    mma_f16(o[mi][ni][0], o[mi][ni][1], o[mi][ni][2], o[mi][ni][3],
                            a[mi][0], a[mi][1], a[mi][2], a[mi][3], bb[ni][0], bb[ni][1]);
        }
        __syncthreads();
    }

    // ---- epilogue: combine l, write fp16 attnout ----
    #pragma unroll
    for (int off = 1; off <= 2; off <<= 1)
        #pragma unroll
        for (int mi = 0; mi < 4; ++mi) {
            lrow[mi][0] += __shfl_xor_sync(0xffffffffu, lrow[mi][0], off);
            lrow[mi][1] += __shfl_xor_sync(0xffffffffu, lrow[mi][1], off);
        }
    if (tig == 0) {
        #pragma unroll
        for (int mi = 0; mi < 4; ++mi) {
            red[wnid][wm + mi * 16 + g]     = lrow[mi][0];
            red[wnid][wm + mi * 16 + g + 8] = lrow[mi][1];
        }
    }
    __syncthreads();

    const float vsc = g_scales[2];
    #pragma unroll
    for (int mi = 0; mi < 4; ++mi) {
        #pragma unroll
        for (int hh = 0; hh < 2; ++hh) {
            int row = wm + mi * 16 + g + hh * 8;
            float lt = red[0][row] + red[1][row] + red[2][row] + red[3][row];
            float inv = vsc / lt;
            int srow = i0 + row;
            #pragma unroll
            for (int ni = 0; ni < 4; ++ni) {
                int d = wn + ni * 8 + 2 * tig;
                __half2 hv = __floats2half2_rn(o[mi][ni][2 * hh] * inv,
                                               o[mi][ni][2 * hh + 1] * inv);
                *(__half2*)&g_aoh[(size_t)(b * S_ + srow) * H_ + h * HD + d] = hv;
            }
        }
    }
}

// ---------------- launch ----------------
extern "C" void kernel_launch(void* const* d_in, const int* in_sizes, int n_in,
                              void* d_out, int out_size)
{
    const float* x    = (const float*)d_in[0];
    const float* Wqkv = (const float*)d_in[1];
    const float* Wout = (const float*)d_in[2];
    const float* bout = (const float*)d_in[3];
    float* y = (float*)d_out;

    float* qkv_ptr = nullptr;
    __half *xh, *xl, *wqh, *wql, *woh, *wol, *aoh;
    cudaGetSymbolAddress((void**)&qkv_ptr, g_qkv);
    cudaGetSymbolAddress((void**)&xh, g_xh);   cudaGetSymbolAddress((void**)&xl, g_xl);
    cudaGetSymbolAddress((void**)&wqh, g_wqh); cudaGetSymbolAddress((void**)&wql, g_wql);
    cudaGetSymbolAddress((void**)&woh, g_woh); cudaGetSymbolAddress((void**)&wol, g_wol);
    cudaGetSymbolAddress((void**)&aoh, g_aoh);

    static int attr_set = 0;
    if (!attr_set) {
        cudaFuncSetAttribute(flash_kernel,
                             cudaFuncAttributeMaxDynamicSharedMemorySize, FLASH_SMEM);
        cudaFuncSetAttribute(hgemm2,
                             cudaFuncAttributeMaxDynamicSharedMemorySize, G2_SMEM);
        attr_set = 1;
    }

    zero_kernel<<<1, 32>>>();

    split_kernel<<<(M1 * H_ / 4 + 255) / 256, 256>>>(x, xh, xl, M1 * H_ / 4);
    tsplit_kernel<<<dim3(H3 / 32, H_ / 32), 256>>>(Wqkv, wqh, wql, H_, H3);
    tsplit_kernel<<<dim3(H_ / 32, H_ / 32), 256>>>(Wout, woh, wol, H_, H_);

    // 1) qkv = x @ W_qkv  (fp16x3, absmax fused)
    hgemm2<<<dim3(H3 / 128, M1 / 128), 256, G2_SMEM>>>(
        xh, xl, wqh, wql, qkv_ptr, M1, H3, H_, nullptr, 1, 1);

    scales_kernel<<<1, 32>>>();
    quant_kernel<<<(3 * PLANE / 4 + 255) / 256, 256>>>();

    // 4-6) fused flash attention (fp8 QK^T); writes fp16 attnout
    flash_kernel<<<dim3(S_ / BQ, B_ * NH), 256, FLASH_SMEM>>>();

    // 7) y = attnout @ W_out + b_out  (fp16x2)
    hgemm2<<<dim3(H_ / 128, M1 / 128), 256, G2_SMEM>>>(
        aoh, nullptr, woh, wol, y, M1, H_, H_, bout, 0, 0);
}

// round 12
// speedup vs baseline: 4.3367x; 1.0049x over previous
#include <cuda_runtime.h>
#include <cuda_fp16.h>
#include <cuda_fp8.h>
#include <math.h>

// ---------------- problem constants ----------------
#define B_   2
#define S_   2048
#define H_   2048
#define NH   16
#define HD   128
#define H3   (3 * H_)
#define M1   (B_ * S_)
#define PLANE (B_ * NH * S_ * HD)
#define BQ   128

// ---------------- scratch ----------------
__device__ float         g_qkv[(size_t)M1 * H3];
__device__ unsigned char g_q8[(size_t)2 * PLANE];      // q, k as raw e4m3
__device__ __half        g_v16[(size_t)PLANE];         // v dequantized (e4m3 values in fp16)
__device__ unsigned int  g_absmax[3];
__device__ float         g_scales[3];
__device__ __half        g_xh[(size_t)M1 * H_],  g_xl[(size_t)M1 * H_];
__device__ __half        g_wqh[(size_t)H3 * H_], g_wql[(size_t)H3 * H_];
__device__ __half        g_woh[(size_t)H_ * H_], g_wol[(size_t)H_ * H_];
__device__ __half        g_aoh[(size_t)M1 * H_];

// ---------------- helpers ----------------
__device__ __forceinline__ unsigned short f8_to_h(unsigned char v) {
    __half_raw hr = __nv_cvt_fp8_to_halfraw(v, __NV_E4M3);
    return hr.x;
}

__device__ __forceinline__ void mma_f16(float& d0, float& d1, float& d2, float& d3,
                                        unsigned a0, unsigned a1, unsigned a2, unsigned a3,
                                        unsigned b0, unsigned b1) {
    asm volatile("mma.sync.aligned.m16n8k16.row.col.f32.f16.f16.f32 "
                 "{%0,%1,%2,%3}, {%4,%5,%6,%7}, {%8,%9}, {%0,%1,%2,%3};"
                 : "+f"(d0), "+f"(d1), "+f"(d2), "+f"(d3)
                 : "r"(a0), "r"(a1), "r"(a2), "r"(a3), "r"(b0), "r"(b1));
}
__device__ __forceinline__ void mma_f8(float& d0, float& d1, float& d2, float& d3,
                                       unsigned a0, unsigned a1, unsigned a2, unsigned a3,
                                       unsigned b0, unsigned b1) {
    asm volatile("mma.sync.aligned.m16n8k32.row.col.f32.e4m3.e4m3.f32 "
                 "{%0,%1,%2,%3}, {%4,%5,%6,%7}, {%8,%9}, {%0,%1,%2,%3};"
                 : "+f"(d0), "+f"(d1), "+f"(d2), "+f"(d3)
                 : "r"(a0), "r"(a1), "r"(a2), "r"(a3), "r"(b0), "r"(b1));
}
__device__ __forceinline__ void ldsm_x2_trans(unsigned& r0, unsigned& r1, const void* p) {
    unsigned addr = (unsigned)__cvta_generic_to_shared(p);
    asm volatile("ldmatrix.sync.aligned.m8n8.x2.trans.shared.b16 {%0,%1}, [%2];"
                 : "=r"(r0), "=r"(r1) : "r"(addr));
}
__device__ __forceinline__ void ldsm_x4(unsigned* r, const void* p) {
    unsigned addr = (unsigned)__cvta_generic_to_shared(p);
    asm volatile("ldmatrix.sync.aligned.m8n8.x4.shared.b16 {%0,%1,%2,%3}, [%4];"
                 : "=r"(r[0]), "=r"(r[1]), "=r"(r[2]), "=r"(r[3]) : "r"(addr));
}

#define SWZ(x) ((x) ^ (((x) >> 3) & 0x70))

__device__ __forceinline__ unsigned smem_u32(const void* p) {
    return (unsigned)__cvta_generic_to_shared(p);
}
__device__ __forceinline__ void cpa16(unsigned dst, const void* src) {
    asm volatile("cp.async.cg.shared.global [%0], [%1], 16;" :: "r"(dst), "l"(src));
}
__device__ __forceinline__ void cpa_commit() { asm volatile("cp.async.commit_group;" ::: "memory"); }
__device__ __forceinline__ void cpa_waitall() { asm volatile("cp.async.wait_group 0;" ::: "memory"); }

__global__ void zero_kernel() {
    if (threadIdx.x < 3) g_absmax[threadIdx.x] = 0u;
}

// ---------------- prep: elementwise fp32 -> fp16 hi/lo split ----------------
__global__ void split_kernel(const float* __restrict__ src, __half* __restrict__ dh,
                             __half* __restrict__ dl, int n4) {
    int i = blockIdx.x * blockDim.x + threadIdx.x;
    if (i >= n4) return;
    float4 v = ((const float4*)src)[i];
    float vv[4] = {v.x, v.y, v.z, v.w};
    __half h[4], l[4];
    #pragma unroll
    for (int j = 0; j < 4; ++j) {
        h[j] = __float2half_rn(vv[j]);
        l[j] = __float2half_rn(vv[j] - __half2float(h[j]));
    }
    ((__half2*)dh)[i * 2]     = __halves2half2(h[0], h[1]);
    ((__half2*)dh)[i * 2 + 1] = __halves2half2(h[2], h[3]);
    ((__half2*)dl)[i * 2]     = __halves2half2(l[0], l[1]);
    ((__half2*)dl)[i * 2 + 1] = __halves2half2(l[2], l[3]);
}

// ---------------- prep: transpose + split  W[K][N] -> T[N][K] hi/lo ----------------
__global__ void tsplit_kernel(const float* __restrict__ W, __half* __restrict__ Th,
                              __half* __restrict__ Tl, int K, int N) {
    __shared__ float tile[32][33];
    const int n0 = blockIdx.x * 32, k0 = blockIdx.y * 32;
    const int tid = threadIdx.x;
    const int tx = tid & 31, ty = tid >> 5;
    #pragma unroll
    for (int i = ty; i < 32; i += 8)
        tile[i][tx] = W[(size_t)(k0 + i) * N + n0 + tx];
    __syncthreads();
    const int j = tid >> 3, kg = (tid & 7) << 2;
    __half h[4], l[4];
    #pragma unroll
    for (int p = 0; p < 4; ++p) {
        float v = tile[kg + p][j];
        h[p] = __float2half_rn(v);
        l[p] = __float2half_rn(v - __half2float(h[p]));
    }
    uint2 uh, ul;
    __half2 t;
    t = __halves2half2(h[0], h[1]); uh.x = *(unsigned*)&t;
    t = __halves2half2(h[2], h[3]); uh.y = *(unsigned*)&t;
    t = __halves2half2(l[0], l[1]); ul.x = *(unsigned*)&t;
    t = __halves2half2(l[2], l[3]); ul.y = *(unsigned*)&t;
    *(uint2*)&Th[(size_t)(n0 + j) * K + k0 + kg] = uh;
    *(uint2*)&Tl[(size_t)(n0 + j) * K + k0 + kg] = ul;
}

// ============ fp16 split GEMM: 3-term (QKV) or 2-term (proj) ============
#define RG_SZ   16384
#define ST_SZ   65536
#define G2_SMEM 131072

__global__ __launch_bounds__(256, 1) void hgemm2(
    const __half* __restrict__ Agh, const __half* __restrict__ Agl,
    const __half* __restrict__ Bgh, const __half* __restrict__ Bgl,
    float* __restrict__ C, int M, int N, int K,
    const float* __restrict__ bias, int do_absmax, int three)
{
    extern __shared__ char smraw[];
    const unsigned sb = smem_u32(smraw);
    const int tid = threadIdx.x, wid = tid >> 5, lane = tid & 31;
    const int g = lane >> 2, tig = lane & 3;
    const int m0 = blockIdx.y * 128, n0 = blockIdx.x * 128;
    const int wm = (wid & 1) * 64, wn = (wid >> 1) * 32;

    const int rsel = (lane & 7) | (((lane >> 3) & 1) << 3);
    const int ksel = (lane >> 4) << 3;
    const int brow = lane & 7;
    const int bm   = lane >> 3;

    float acc[4][4][4] = {};

    const int fr = tid >> 1;
    const int fg = (tid & 1) << 2;

    auto fill = [&](int stage, int k0) {
        const __half* s0 = Agh + (size_t)(m0 + fr) * K + k0 + fg * 8;
        const __half* s2 = Bgh + (size_t)(n0 + fr) * K + k0 + fg * 8;
        const __half* s3 = Bgl + (size_t)(n0 + fr) * K + k0 + fg * 8;
        unsigned base = sb + stage * ST_SZ;
        #pragma unroll
        for (int p = 0; p < 4; ++p) {
            unsigned d = SWZ((unsigned)(fr * 128 + (fg + p) * 16));
            cpa16(base + 0 * RG_SZ + d, s0 + p * 8);
            cpa16(base + 2 * RG_SZ + d, s2 + p * 8);
            cpa16(base + 3 * RG_SZ + d, s3 + p * 8);
        }
        if (three) {
            const __half* s1 = Agl + (size_t)(m0 + fr) * K + k0 + fg * 8;
            #pragma unroll
            for (int p = 0; p < 4; ++p) {
                unsigned d = SWZ((unsigned)(fr * 128 + (fg + p) * 16));
                cpa16(base + 1 * RG_SZ + d, s1 + p * 8);
            }
        }
        cpa_commit();
    };

    fill(0, 0);
    cpa_waitall(); __syncthreads();

    const int T = K >> 6;
    for (int t = 0; t < T; ++t) {
        const int stage = t & 1;
        if (t + 1 < T) fill(stage ^ 1, (t + 1) << 6);

        const char* Ah = smraw + stage * ST_SZ;
        const char* Al = Ah + RG_SZ;
        const char* Bh = Ah + 2 * RG_SZ;
        const char* Bl = Ah + 3 * RG_SZ;

        #pragma unroll
        for (int ks = 0; ks < 4; ++ks) {
            const int kb = ks * 16;
            unsigned ah[4][4], al[4][4], bh[4][2], bl[4][2];
            #pragma unroll
            for (int mi = 0; mi < 4; ++mi) {
                unsigned off = SWZ((unsigned)((wm + mi * 16 + rsel) * 128 + (kb + ksel) * 2));
                ldsm_x4(ah[mi], Ah + off);
                if (three) ldsm_x4(al[mi], Al + off);
            }
            #pragma unroll
            for (int np = 0; np < 2; ++np) {
                unsigned off = SWZ((unsigned)((wn + (np * 2 + (bm >> 1)) * 8 + brow) * 128
                                              + (kb + (bm & 1) * 8) * 2));
                unsigned r[4];
                ldsm_x4(r, Bh + off);
                bh[2 * np][0] = r[0]; bh[2 * np][1] = r[1];
                bh[2 * np + 1][0] = r[2]; bh[2 * np + 1][1] = r[3];
                ldsm_x4(r, Bl + off);
                bl[2 * np][0] = r[0]; bl[2 * np][1] = r[1];
                bl[2 * np + 1][0] = r[2]; bl[2 * np + 1][1] = r[3];
            }
            #pragma unroll
            for (int mi = 0; mi < 4; ++mi)
                #pragma unroll
                for (int ni = 0; ni < 4; ++ni)
                    mma_f16(acc[mi][ni][0], acc[mi][ni][1], acc[mi][ni][2], acc[mi][ni][3],
                            ah[mi][0], ah[mi][1], ah[mi][2], ah[mi][3], bh[ni][0], bh[ni][1]);
            #pragma unroll
            for (int mi = 0; mi < 4; ++mi)
                #pragma unroll
                for (int ni = 0; ni < 4; ++ni)
                    mma_f16(acc[mi][ni][0], acc[mi][ni][1], acc[mi][ni][2], acc[mi][ni][3],
                            ah[mi][0], ah[mi][1], ah[mi][2], ah[mi][3], bl[ni][0], bl[ni][1]);
            if (three) {
                #pragma unroll
                for (int mi = 0; mi < 4; ++mi)
                    #pragma unroll
                    for (int ni = 0; ni < 4; ++ni)
                        mma_f16(acc[mi][ni][0], acc[mi][ni][1], acc[mi][ni][2], acc[mi][ni][3],
                                al[mi][0], al[mi][1], al[mi][2], al[mi][3], bh[ni][0], bh[ni][1]);
            }
        }

        if (t + 1 < T) { cpa_waitall(); __syncthreads(); }
    }

    float lmax = 0.0f;
    #pragma unroll
    for (int mi = 0; mi < 4; ++mi) {
        int r = m0 + wm + mi * 16 + g;
        #pragma unroll
        for (int ni = 0; ni < 4; ++ni) {
            int c = n0 + wn + ni * 8 + 2 * tig;
            float2 v0 = {acc[mi][ni][0], acc[mi][ni][1]};
            float2 v1 = {acc[mi][ni][2], acc[mi][ni][3]};
            if (bias) {
                float b0 = bias[c], b1 = bias[c + 1];
                v0.x += b0; v0.y += b1;
                v1.x += b0; v1.y += b1;
            }
            if (do_absmax) {
                lmax = fmaxf(lmax, fmaxf(fmaxf(fabsf(v0.x), fabsf(v0.y)),
                                         fmaxf(fabsf(v1.x), fabsf(v1.y))));
            }
            *(float2*)&C[(size_t)r * N + c] = v0;
            *(float2*)&C[(size_t)(r + 8) * N + c] = v1;
        }
    }
    if (do_absmax) {
        #pragma unroll
        for (int o = 16; o; o >>= 1)
            lmax = fmaxf(lmax, __shfl_xor_sync(0xffffffffu, lmax, o));
        if (lane == 0) atomicMax(&g_absmax[n0 >> 11], __float_as_uint(lmax));
    }
}

// ---------------- scales / quant ----------------
__global__ void scales_kernel() {
    if (threadIdx.x < 3)
        g_scales[threadIdx.x] = __uint_as_float(g_absmax[threadIdx.x]) / 448.0f;
}

// q,k -> raw fp8 bytes; v -> e4m3-rounded values stored as fp16
__global__ void quant_kernel() {
    int i = blockIdx.x * blockDim.x + threadIdx.x;
    if (i >= 3 * PLANE / 4) return;
    int t   = i / (PLANE / 4);
    int rem = i - t * (PLANE / 4);
    int d4 = rem & 31;
    int s  = (rem >> 5) & 2047;
    int bh = rem >> 16;
    int b = bh >> 4, h = bh & 15;
    const float sc = g_scales[t];
    float4 v = *(const float4*)&g_qkv[(size_t)(b * S_ + s) * H3 + t * H_ + h * HD + d4 * 4];
    unsigned char q0 = __nv_cvt_float_to_fp8(v.x / sc, __NV_SATFINITE, __NV_E4M3);
    unsigned char q1 = __nv_cvt_float_to_fp8(v.y / sc, __NV_SATFINITE, __NV_E4M3);
    unsigned char q2 = __nv_cvt_float_to_fp8(v.z / sc, __NV_SATFINITE, __NV_E4M3);
    unsigned char q3 = __nv_cvt_float_to_fp8(v.w / sc, __NV_SATFINITE, __NV_E4M3);
    if (t < 2) {
        *(uchar4*)&g_q8[(size_t)t * PLANE + ((size_t)bh << 18) + (s << 7) + d4 * 4] =
            make_uchar4(q0, q1, q2, q3);
    } else {
        uint2 o;
        o.x = (unsigned)f8_to_h(q0) | ((unsigned)f8_to_h(q1) << 16);
        o.y = (unsigned)f8_to_h(q2) | ((unsigned)f8_to_h(q3) << 16);
        *(uint2*)&g_v16[((size_t)bh << 18) + (s << 7) + d4 * 4] = o;
    }
}

// ============ fused flash attention: fp8 QK^T + fp16 PV ============
#define QB_OFF 0
#define KB_OFF 18432
#define VS_OFF 36864
#define PS_OFF 71680
#define RED_OFF 106496
#define FLASH_SMEM 108544

__global__ __launch_bounds__(256, 1) void flash_kernel() {
    extern __shared__ char smraw[];
    char* QB = smraw + QB_OFF;                 // raw e4m3, row stride 144 B
    char* KB = smraw + KB_OFF;
    typedef __half HRow[136];
    HRow* Vs = (HRow*)(smraw + VS_OFF);
    HRow* Ps = (HRow*)(smraw + PS_OFF);
    float (*red)[128] = (float(*)[128])(smraw + RED_OFF);

    const int tid = threadIdx.x, lane = tid & 31, wid = tid >> 5;
    const int g = lane >> 2, tig = lane & 3;
    const int wm = (wid & 1) * 64, wn = (wid >> 1) * 32;
    const int wnid = wid >> 1;
    const int bh = blockIdx.y;
    const int b = bh >> 4, h = bh & 15;
    const int i0 = blockIdx.x * BQ;
    const unsigned char* qp = g_q8 + (size_t)bh * (S_ * HD);
    const unsigned char* kp = g_q8 + (size_t)PLANE + (size_t)bh * (S_ * HD);
    const __half* vp = g_v16 + (size_t)bh * (S_ * HD);
    const float f = g_scales[0] * g_scales[1] * 0.08838834764831843f;

    const int rsel = (lane & 7) | (((lane >> 3) & 1) << 3);
    const int ksel = (lane >> 4) << 3;
    const int kselb = (lane >> 4) << 4;
    const int b8row = (lane & 7);
    const int b8sub = (lane >> 4);
    const int b8k   = ((lane >> 3) & 1) << 4;

    // ---- Q tile: raw byte copy ----
    #pragma unroll
    for (int p = 0; p < 4; ++p) {
        int lin = tid + p * 256;
        int r = lin >> 3, c = (lin & 7) << 4;
        *(uint4*)(QB + r * 144 + c) = *(const uint4*)&qp[(size_t)(i0 + r) * HD + c];
    }

    float o[4][4][4] = {};
    float mrow[4][2], lrow[4][2];
    #pragma unroll
    for (int mi = 0; mi < 4; ++mi) {
        mrow[mi][0] = mrow[mi][1] = -1e30f;
        lrow[mi][0] = lrow[mi][1] = 0.0f;
    }

    for (int kt = 0; kt < S_ / BQ; ++kt) {
        const unsigned char* kb8 = kp + (size_t)kt * BQ * HD;
        const __half* vb16 = vp + (size_t)kt * BQ * HD;
        // K: raw byte copy
        #pragma unroll
        for (int p = 0; p < 4; ++p) {
            int lin = tid + p * 256;
            int r = lin >> 3, c = (lin & 7) << 4;
            *(uint4*)(KB + r * 144 + c) = *(const uint4*)&kb8[(size_t)r * HD + c];
        }
        // V: pure fp16 copy (pre-converted in quant_kernel)
        #pragma unroll
        for (int p = 0; p < 8; ++p) {
            int lin = tid + p * 256;
            int r = lin >> 4, c = (lin & 15) << 3;    // 8 halves = 16 B
            *(uint4*)&Vs[r][c] = *(const uint4*)&vb16[(size_t)r * HD + c];
        }
        __syncthreads();

        // ---- S = Q @ K^T via fp8 MMA ----
        float s[4][4][4] = {};
        #pragma unroll
        for (int ks = 0; ks < 4; ++ks) {
            const int kb = ks * 32;
            unsigned a[4][4], bb[4][2];
            #pragma unroll
            for (int mi = 0; mi < 4; ++mi)
                ldsm_x4(a[mi], QB + (wm + mi * 16 + rsel) * 144 + kb + kselb);
            #pragma unroll
            for (int np = 0; np < 2; ++np) {
                unsigned r[4];
                ldsm_x4(r, KB + (wn + (np * 2 + b8sub) * 8 + b8row) * 144 + kb + b8k);
                bb[2 * np][0] = r[0]; bb[2 * np][1] = r[1];
                bb[2 * np + 1][0] = r[2]; bb[2 * np + 1][1] = r[3];
            }
            #pragma unroll
            for (int mi = 0; mi < 4; ++mi)
                #pragma unroll
                for (int ni = 0; ni < 4; ++ni)
                    mma_f8(s[mi][ni][0], s[mi][ni][1], s[mi][ni][2], s[mi][ni][3],
                           a[mi][0], a[mi][1], a[mi][2], a[mi][3], bb[ni][0], bb[ni][1]);
        }
        #pragma unroll
        for (int mi = 0; mi < 4; ++mi)
            #pragma unroll
            for (int ni = 0; ni < 4; ++ni)
                #pragma unroll
                for (int j = 0; j < 4; ++j)
                    s[mi][ni][j] *= f;

        // ---- row max ----
        float tmax[4][2];
        #pragma unroll
        for (int mi = 0; mi < 4; ++mi) {
            float h0 = -1e30f, h1 = -1e30f;
            #pragma unroll
            for (int ni = 0; ni < 4; ++ni) {
                h0 = fmaxf(h0, fmaxf(s[mi][ni][0], s[mi][ni][1]));
                h1 = fmaxf(h1, fmaxf(s[mi][ni][2], s[mi][ni][3]));
            }
            tmax[mi][0] = h0; tmax[mi][1] = h1;
        }
        #pragma unroll
        for (int off = 1; off <= 2; off <<= 1)
            #pragma unroll
            for (int mi = 0; mi < 4; ++mi) {
                tmax[mi][0] = fmaxf(tmax[mi][0], __shfl_xor_sync(0xffffffffu, tmax[mi][0], off));
                tmax[mi][1] = fmaxf(tmax[mi][1], __shfl_xor_sync(0xffffffffu, tmax[mi][1], off));
            }
        if (tig == 0) {
            #pragma unroll
            for (int mi = 0; mi < 4; ++mi) {
                red[wnid][wm + mi * 16 + g]     = tmax[mi][0];
                red[wnid][wm + mi * 16 + g + 8] = tmax[mi][1];
            }
        }
        __syncthreads();

        // ---- online softmax update; write P (fp16) ----
        #pragma unroll
        for (int mi = 0; mi < 4; ++mi) {
            #pragma unroll
            for (int hh = 0; hh < 2; ++hh) {
                int row = wm + mi * 16 + g + hh * 8;
                float rm = fmaxf(fmaxf(red[0][row], red[1][row]),
                                 fmaxf(red[2][row], red[3][row]));
                float mnew = fmaxf(mrow[mi][hh], rm);
                float rs = expf(mrow[mi][hh] - mnew);
                mrow[mi][hh] = mnew;
                lrow[mi][hh] *= rs;
                #pragma unroll
                for (int ni = 0; ni < 4; ++ni) {
                    o[mi][ni][2 * hh]     *= rs;
                    o[mi][ni][2 * hh + 1] *= rs;
                }
            }
            #pragma unroll
            for (int ni = 0; ni < 4; ++ni) {
                float p0 = expf(s[mi][ni][0] - mrow[mi][0]);
                float p1 = expf(s[mi][ni][1] - mrow[mi][0]);
                float p2 = expf(s[mi][ni][2] - mrow[mi][1]);
                float p3 = expf(s[mi][ni][3] - mrow[mi][1]);
                lrow[mi][0] += p0 + p1;
                lrow[mi][1] += p2 + p3;
                int c = wn + ni * 8 + 2 * tig;
                *(__half2*)&Ps[wm + mi * 16 + g][c]     = __floats2half2_rn(p0, p1);
                *(__half2*)&Ps[wm + mi * 16 + g + 8][c] = __floats2half2_rn(p2, p3);
            }
        }
        __syncthreads();

        // ---- O += P @ V ----
        #pragma unroll
        for (int ks = 0; ks < 8; ++ks) {
            const int kb = ks * 16;
            unsigned a[4][4], bb[4][2];
            #pragma unroll
            for (int mi = 0; mi < 4; ++mi)
                ldsm_x4(a[mi], &Ps[wm + mi * 16 + rsel][kb + ksel]);
            #pragma unroll
            for (int ni = 0; ni < 4; ++ni)
                ldsm_x2_trans(bb[ni][0], bb[ni][1], &Vs[kb + (lane & 15)][wn + ni * 8]);
            #pragma unroll
            for (int mi = 0; mi < 4; ++mi)
                #pragma unroll
                for (int ni = 0; ni < 4; ++ni)
                    mma_f16(o[mi][ni][0], o[mi][ni][1], o[mi][ni][2], o[mi][ni][3],
                            a[mi][0], a[mi][1], a[mi][2], a[mi][3], bb[ni][0], bb[ni][1]);
        }
        __syncthreads();
    }

    // ---- epilogue ----
    #pragma unroll
    for (int off = 1; off <= 2; off <<= 1)
        #pragma unroll
        for (int mi = 0; mi < 4; ++mi) {
            lrow[mi][0] += __shfl_xor_sync(0xffffffffu, lrow[mi][0], off);
            lrow[mi][1] += __shfl_xor_sync(0xffffffffu, lrow[mi][1], off);
        }
    if (tig == 0) {
        #pragma unroll
        for (int mi = 0; mi < 4; ++mi) {
            red[wnid][wm + mi * 16 + g]     = lrow[mi][0];
            red[wnid][wm + mi * 16 + g + 8] = lrow[mi][1];
        }
    }
    __syncthreads();

    const float vsc = g_scales[2];
    #pragma unroll
    for (int mi = 0; mi < 4; ++mi) {
        #pragma unroll
        for (int hh = 0; hh < 2; ++hh) {
            int row = wm + mi * 16 + g + hh * 8;
            float lt = red[0][row] + red[1][row] + red[2][row] + red[3][row];
            float inv = vsc / lt;
            int srow = i0 + row;
            #pragma unroll
            for (int ni = 0; ni < 4; ++ni) {
                int d = wn + ni * 8 + 2 * tig;
                __half2 hv = __floats2half2_rn(o[mi][ni][2 * hh] * inv,
                                               o[mi][ni][2 * hh + 1] * inv);
                *(__half2*)&g_aoh[(size_t)(b * S_ + srow) * H_ + h * HD + d] = hv;
            }
        }
    }
}

// ---------------- launch ----------------
extern "C" void kernel_launch(void* const* d_in, const int* in_sizes, int n_in,
                              void* d_out, int out_size)
{
    const float* x    = (const float*)d_in[0];
    const float* Wqkv = (const float*)d_in[1];
    const float* Wout = (const float*)d_in[2];
    const float* bout = (const float*)d_in[3];
    float* y = (float*)d_out;

    float* qkv_ptr = nullptr;
    __half *xh, *xl, *wqh, *wql, *woh, *wol, *aoh;
    cudaGetSymbolAddress((void**)&qkv_ptr, g_qkv);
    cudaGetSymbolAddress((void**)&xh, g_xh);   cudaGetSymbolAddress((void**)&xl, g_xl);
    cudaGetSymbolAddress((void**)&wqh, g_wqh); cudaGetSymbolAddress((void**)&wql, g_wql);
    cudaGetSymbolAddress((void**)&woh, g_woh); cudaGetSymbolAddress((void**)&wol, g_wol);
    cudaGetSymbolAddress((void**)&aoh, g_aoh);

    static int attr_set = 0;
    if (!attr_set) {
        cudaFuncSetAttribute(flash_kernel,
                             cudaFuncAttributeMaxDynamicSharedMemorySize, FLASH_SMEM);
        cudaFuncSetAttribute(hgemm2,
                             cudaFuncAttributeMaxDynamicSharedMemorySize, G2_SMEM);
        attr_set = 1;
    }

    zero_kernel<<<1, 32>>>();

    split_kernel<<<(M1 * H_ / 4 + 255) / 256, 256>>>(x, xh, xl, M1 * H_ / 4);
    tsplit_kernel<<<dim3(H3 / 32, H_ / 32), 256>>>(Wqkv, wqh, wql, H_, H3);
    tsplit_kernel<<<dim3(H_ / 32, H_ / 32), 256>>>(Wout, woh, wol, H_, H_);

    // 1) qkv = x @ W_qkv  (fp16x3, absmax fused)
    hgemm2<<<dim3(H3 / 128, M1 / 128), 256, G2_SMEM>>>(
        xh, xl, wqh, wql, qkv_ptr, M1, H3, H_, nullptr, 1, 1);

    scales_kernel<<<1, 32>>>();
    quant_kernel<<<(3 * PLANE / 4 + 255) / 256, 256>>>();

    // 4-6) fused flash attention (fp8 QK^T, pre-converted fp16 V)
    flash_kernel<<<dim3(S_ / BQ, B_ * NH), 256, FLASH_SMEM>>>();

    // 7) y = attnout @ W_out + b_out  (fp16x2)
    hgemm2<<<dim3(H_ / 128, M1 / 128), 256, G2_SMEM>>>(
        aoh, nullptr, woh, wol, y, M1, H_, H_, bout, 0, 0);
}

// round 13
// speedup vs baseline: 4.3849x; 1.0111x over previous
#include <cuda_runtime.h>
#include <cuda_fp16.h>
#include <cuda_fp8.h>
#include <math.h>

// ---------------- problem constants ----------------
#define B_   2
#define S_   2048
#define H_   2048
#define NH   16
#define HD   128
#define H3   (3 * H_)
#define M1   (B_ * S_)
#define PLANE (B_ * NH * S_ * HD)
#define BQ   128

// ---------------- scratch ----------------
__device__ float         g_qkv[(size_t)M1 * H3];
__device__ unsigned char g_q8[(size_t)2 * PLANE];      // q, k as raw e4m3
__device__ __half        g_v16[(size_t)PLANE];         // v dequantized (e4m3 values in fp16)
__device__ unsigned int  g_absmax[3];
__device__ float         g_scales[3];
__device__ float         g_iscales[3];
__device__ __half        g_xh[(size_t)M1 * H_],  g_xl[(size_t)M1 * H_];
__device__ __half        g_wqh[(size_t)H3 * H_], g_wql[(size_t)H3 * H_];
__device__ __half        g_woh[(size_t)H_ * H_], g_wol[(size_t)H_ * H_];
__device__ __half        g_aoh[(size_t)M1 * H_];

// ---------------- helpers ----------------
__device__ __forceinline__ unsigned short f8_to_h(unsigned char v) {
    __half_raw hr = __nv_cvt_fp8_to_halfraw(v, __NV_E4M3);
    return hr.x;
}

__device__ __forceinline__ void mma_f16(float& d0, float& d1, float& d2, float& d3,
                                        unsigned a0, unsigned a1, unsigned a2, unsigned a3,
                                        unsigned b0, unsigned b1) {
    asm volatile("mma.sync.aligned.m16n8k16.row.col.f32.f16.f16.f32 "
                 "{%0,%1,%2,%3}, {%4,%5,%6,%7}, {%8,%9}, {%0,%1,%2,%3};"
                 : "+f"(d0), "+f"(d1), "+f"(d2), "+f"(d3)
                 : "r"(a0), "r"(a1), "r"(a2), "r"(a3), "r"(b0), "r"(b1));
}
__device__ __forceinline__ void mma_f8(float& d0, float& d1, float& d2, float& d3,
                                       unsigned a0, unsigned a1, unsigned a2, unsigned a3,
                                       unsigned b0, unsigned b1) {
    asm volatile("mma.sync.aligned.m16n8k32.row.col.f32.e4m3.e4m3.f32 "
                 "{%0,%1,%2,%3}, {%4,%5,%6,%7}, {%8,%9}, {%0,%1,%2,%3};"
                 : "+f"(d0), "+f"(d1), "+f"(d2), "+f"(d3)
                 : "r"(a0), "r"(a1), "r"(a2), "r"(a3), "r"(b0), "r"(b1));
}
__device__ __forceinline__ void ldsm_x2_trans(unsigned& r0, unsigned& r1, const void* p) {
    unsigned addr = (unsigned)__cvta_generic_to_shared(p);
    asm volatile("ldmatrix.sync.aligned.m8n8.x2.trans.shared.b16 {%0,%1}, [%2];"
                 : "=r"(r0), "=r"(r1) : "r"(addr));
}
__device__ __forceinline__ void ldsm_x4(unsigned* r, const void* p) {
    unsigned addr = (unsigned)__cvta_generic_to_shared(p);
    asm volatile("ldmatrix.sync.aligned.m8n8.x4.shared.b16 {%0,%1,%2,%3}, [%4];"
                 : "=r"(r[0]), "=r"(r[1]), "=r"(r[2]), "=r"(r[3]) : "r"(addr));
}

#define SWZ(x) ((x) ^ (((x) >> 3) & 0x70))

__device__ __forceinline__ unsigned smem_u32(const void* p) {
    return (unsigned)__cvta_generic_to_shared(p);
}
__device__ __forceinline__ void cpa16(unsigned dst, const void* src) {
    asm volatile("cp.async.cg.shared.global [%0], [%1], 16;" :: "r"(dst), "l"(src));
}
__device__ __forceinline__ void cpa_commit() { asm volatile("cp.async.commit_group;" ::: "memory"); }
__device__ __forceinline__ void cpa_waitall() { asm volatile("cp.async.wait_group 0;" ::: "memory"); }

__global__ void zero_kernel() {
    if (threadIdx.x < 3) g_absmax[threadIdx.x] = 0u;
}

// ---------------- prep: elementwise fp32 -> fp16 hi/lo split ----------------
__global__ void split_kernel(const float* __restrict__ src, __half* __restrict__ dh,
                             __half* __restrict__ dl, int n4) {
    int i = blockIdx.x * blockDim.x + threadIdx.x;
    if (i >= n4) return;
    float4 v = ((const float4*)src)[i];
    float vv[4] = {v.x, v.y, v.z, v.w};
    __half h[4], l[4];
    #pragma unroll
    for (int j = 0; j < 4; ++j) {
        h[j] = __float2half_rn(vv[j]);
        l[j] = __float2half_rn(vv[j] - __half2float(h[j]));
    }
    ((__half2*)dh)[i * 2]     = __halves2half2(h[0], h[1]);
    ((__half2*)dh)[i * 2 + 1] = __halves2half2(h[2], h[3]);
    ((__half2*)dl)[i * 2]     = __halves2half2(l[0], l[1]);
    ((__half2*)dl)[i * 2 + 1] = __halves2half2(l[2], l[3]);
}

// ---------------- prep: transpose + split  W[K][N] -> T[N][K] hi/lo ----------------
__global__ void tsplit_kernel(const float* __restrict__ W, __half* __restrict__ Th,
                              __half* __restrict__ Tl, int K, int N) {
    __shared__ float tile[32][33];
    const int n0 = blockIdx.x * 32, k0 = blockIdx.y * 32;
    const int tid = threadIdx.x;
    const int tx = tid & 31, ty = tid >> 5;
    #pragma unroll
    for (int i = ty; i < 32; i += 8)
        tile[i][tx] = W[(size_t)(k0 + i) * N + n0 + tx];
    __syncthreads();
    const int j = tid >> 3, kg = (tid & 7) << 2;
    __half h[4], l[4];
    #pragma unroll
    for (int p = 0; p < 4; ++p) {
        float v = tile[kg + p][j];
        h[p] = __float2half_rn(v);
        l[p] = __float2half_rn(v - __half2float(h[p]));
    }
    uint2 uh, ul;
    __half2 t;
    t = __halves2half2(h[0], h[1]); uh.x = *(unsigned*)&t;
    t = __halves2half2(h[2], h[3]); uh.y = *(unsigned*)&t;
    t = __halves2half2(l[0], l[1]); ul.x = *(unsigned*)&t;
    t = __halves2half2(l[2], l[3]); ul.y = *(unsigned*)&t;
    *(uint2*)&Th[(size_t)(n0 + j) * K + k0 + kg] = uh;
    *(uint2*)&Tl[(size_t)(n0 + j) * K + k0 + kg] = ul;
}

// ============ fp16 split GEMM: 3-term (QKV) or 2-term (proj) ============
#define RG_SZ   16384
#define ST_SZ   65536
#define G2_SMEM 131072

__global__ __launch_bounds__(256, 1) void hgemm2(
    const __half* __restrict__ Agh, const __half* __restrict__ Agl,
    const __half* __restrict__ Bgh, const __half* __restrict__ Bgl,
    float* __restrict__ C, int M, int N, int K,
    const float* __restrict__ bias, int do_absmax, int three)
{
    extern __shared__ char smraw[];
    const unsigned sb = smem_u32(smraw);
    const int tid = threadIdx.x, wid = tid >> 5, lane = tid & 31;
    const int g = lane >> 2, tig = lane & 3;
    const int m0 = blockIdx.y * 128, n0 = blockIdx.x * 128;
    const int wm = (wid & 1) * 64, wn = (wid >> 1) * 32;

    const int rsel = (lane & 7) | (((lane >> 3) & 1) << 3);
    const int ksel = (lane >> 4) << 3;
    const int brow = lane & 7;
    const int bm   = lane >> 3;

    float acc[4][4][4] = {};

    const int fr = tid >> 1;
    const int fg = (tid & 1) << 2;

    auto fill = [&](int stage, int k0) {
        const __half* s0 = Agh + (size_t)(m0 + fr) * K + k0 + fg * 8;
        const __half* s2 = Bgh + (size_t)(n0 + fr) * K + k0 + fg * 8;
        const __half* s3 = Bgl + (size_t)(n0 + fr) * K + k0 + fg * 8;
        unsigned base = sb + stage * ST_SZ;
        #pragma unroll
        for (int p = 0; p < 4; ++p) {
            unsigned d = SWZ((unsigned)(fr * 128 + (fg + p) * 16));
            cpa16(base + 0 * RG_SZ + d, s0 + p * 8);
            cpa16(base + 2 * RG_SZ + d, s2 + p * 8);
            cpa16(base + 3 * RG_SZ + d, s3 + p * 8);
        }
        if (three) {
            const __half* s1 = Agl + (size_t)(m0 + fr) * K + k0 + fg * 8;
            #pragma unroll
            for (int p = 0; p < 4; ++p) {
                unsigned d = SWZ((unsigned)(fr * 128 + (fg + p) * 16));
                cpa16(base + 1 * RG_SZ + d, s1 + p * 8);
            }
        }
        cpa_commit();
    };

    fill(0, 0);
    cpa_waitall(); __syncthreads();

    const int T = K >> 6;
    for (int t = 0; t < T; ++t) {
        const int stage = t & 1;
        if (t + 1 < T) fill(stage ^ 1, (t + 1) << 6);

        const char* Ah = smraw + stage * ST_SZ;
        const char* Al = Ah + RG_SZ;
        const char* Bh = Ah + 2 * RG_SZ;
        const char* Bl = Ah + 3 * RG_SZ;

        #pragma unroll
        for (int ks = 0; ks < 4; ++ks) {
            const int kb = ks * 16;
            unsigned ah[4][4], al[4][4], bh[4][2], bl[4][2];
            #pragma unroll
            for (int mi = 0; mi < 4; ++mi) {
                unsigned off = SWZ((unsigned)((wm + mi * 16 + rsel) * 128 + (kb + ksel) * 2));
                ldsm_x4(ah[mi], Ah + off);
                if (three) ldsm_x4(al[mi], Al + off);
            }
            #pragma unroll
            for (int np = 0; np < 2; ++np) {
                unsigned off = SWZ((unsigned)((wn + (np * 2 + (bm >> 1)) * 8 + brow) * 128
                                              + (kb + (bm & 1) * 8) * 2));
                unsigned r[4];
                ldsm_x4(r, Bh + off);
                bh[2 * np][0] = r[0]; bh[2 * np][1] = r[1];
                bh[2 * np + 1][0] = r[2]; bh[2 * np + 1][1] = r[3];
                ldsm_x4(r, Bl + off);
                bl[2 * np][0] = r[0]; bl[2 * np][1] = r[1];
                bl[2 * np + 1][0] = r[2]; bl[2 * np + 1][1] = r[3];
            }
            #pragma unroll
            for (int mi = 0; mi < 4; ++mi)
                #pragma unroll
                for (int ni = 0; ni < 4; ++ni)
                    mma_f16(acc[mi][ni][0], acc[mi][ni][1], acc[mi][ni][2], acc[mi][ni][3],
                            ah[mi][0], ah[mi][1], ah[mi][2], ah[mi][3], bh[ni][0], bh[ni][1]);
            #pragma unroll
            for (int mi = 0; mi < 4; ++mi)
                #pragma unroll
                for (int ni = 0; ni < 4; ++ni)
                    mma_f16(acc[mi][ni][0], acc[mi][ni][1], acc[mi][ni][2], acc[mi][ni][3],
                            ah[mi][0], ah[mi][1], ah[mi][2], ah[mi][3], bl[ni][0], bl[ni][1]);
            if (three) {
                #pragma unroll
                for (int mi = 0; mi < 4; ++mi)
                    #pragma unroll
                    for (int ni = 0; ni < 4; ++ni)
                        mma_f16(acc[mi][ni][0], acc[mi][ni][1], acc[mi][ni][2], acc[mi][ni][3],
                                al[mi][0], al[mi][1], al[mi][2], al[mi][3], bh[ni][0], bh[ni][1]);
            }
        }

        if (t + 1 < T) { cpa_waitall(); __syncthreads(); }
    }

    float lmax = 0.0f;
    #pragma unroll
    for (int mi = 0; mi < 4; ++mi) {
        int r = m0 + wm + mi * 16 + g;
        #pragma unroll
        for (int ni = 0; ni < 4; ++ni) {
            int c = n0 + wn + ni * 8 + 2 * tig;
            float2 v0 = {acc[mi][ni][0], acc[mi][ni][1]};
            float2 v1 = {acc[mi][ni][2], acc[mi][ni][3]};
            if (bias) {
                float b0 = bias[c], b1 = bias[c + 1];
                v0.x += b0; v0.y += b1;
                v1.x += b0; v1.y += b1;
            }
            if (do_absmax) {
                lmax = fmaxf(lmax, fmaxf(fmaxf(fabsf(v0.x), fabsf(v0.y)),
                                         fmaxf(fabsf(v1.x), fabsf(v1.y))));
            }
            *(float2*)&C[(size_t)r * N + c] = v0;
            *(float2*)&C[(size_t)(r + 8) * N + c] = v1;
        }
    }
    if (do_absmax) {
        #pragma unroll
        for (int o = 16; o; o >>= 1)
            lmax = fmaxf(lmax, __shfl_xor_sync(0xffffffffu, lmax, o));
        if (lane == 0) atomicMax(&g_absmax[n0 >> 11], __float_as_uint(lmax));
    }
}

// ---------------- scales / quant ----------------
__global__ void scales_kernel() {
    if (threadIdx.x < 3) {
        float sc = __uint_as_float(g_absmax[threadIdx.x]) / 448.0f;
        g_scales[threadIdx.x]  = sc;
        g_iscales[threadIdx.x] = 1.0f / sc;
    }
}

// q,k -> raw fp8 bytes; v -> e4m3-rounded values stored as fp16.
// Division replaced by multiply-by-reciprocal (<=1ulp difference; ~1e-6 effect).
__global__ void quant_kernel() {
    int i = blockIdx.x * blockDim.x + threadIdx.x;
    if (i >= 3 * PLANE / 4) return;
    int t   = i / (PLANE / 4);
    int rem = i - t * (PLANE / 4);
    int d4 = rem & 31;
    int s  = (rem >> 5) & 2047;
    int bh = rem >> 16;
    int b = bh >> 4, h = bh & 15;
    const float isc = g_iscales[t];
    float4 v = *(const float4*)&g_qkv[(size_t)(b * S_ + s) * H3 + t * H_ + h * HD + d4 * 4];
    unsigned char q0 = __nv_cvt_float_to_fp8(v.x * isc, __NV_SATFINITE, __NV_E4M3);
    unsigned char q1 = __nv_cvt_float_to_fp8(v.y * isc, __NV_SATFINITE, __NV_E4M3);
    unsigned char q2 = __nv_cvt_float_to_fp8(v.z * isc, __NV_SATFINITE, __NV_E4M3);
    unsigned char q3 = __nv_cvt_float_to_fp8(v.w * isc, __NV_SATFINITE, __NV_E4M3);
    if (t < 2) {
        *(uchar4*)&g_q8[(size_t)t * PLANE + ((size_t)bh << 18) + (s << 7) + d4 * 4] =
            make_uchar4(q0, q1, q2, q3);
    } else {
        uint2 o;
        o.x = (unsigned)f8_to_h(q0) | ((unsigned)f8_to_h(q1) << 16);
        o.y = (unsigned)f8_to_h(q2) | ((unsigned)f8_to_h(q3) << 16);
        *(uint2*)&g_v16[((size_t)bh << 18) + (s << 7) + d4 * 4] = o;
    }
}

// ============ fused flash attention: fp8 QK^T + fp16 PV ============
#define QB_OFF 0
#define KB_OFF 18432
#define VS_OFF 36864
#define PS_OFF 71680
#define RED_OFF 106496
#define FLASH_SMEM 108544

__global__ __launch_bounds__(256, 1) void flash_kernel() {
    extern __shared__ char smraw[];
    char* QB = smraw + QB_OFF;
    char* KB = smraw + KB_OFF;
    typedef __half HRow[136];
    HRow* Vs = (HRow*)(smraw + VS_OFF);
    HRow* Ps = (HRow*)(smraw + PS_OFF);
    float (*red)[128] = (float(*)[128])(smraw + RED_OFF);

    const int tid = threadIdx.x, lane = tid & 31, wid = tid >> 5;
    const int g = lane >> 2, tig = lane & 3;
    const int wm = (wid & 1) * 64, wn = (wid >> 1) * 32;
    const int wnid = wid >> 1;
    const int bh = blockIdx.y;
    const int b = bh >> 4, h = bh & 15;
    const int i0 = blockIdx.x * BQ;
    const unsigned char* qp = g_q8 + (size_t)bh * (S_ * HD);
    const unsigned char* kp = g_q8 + (size_t)PLANE + (size_t)bh * (S_ * HD);
    const __half* vp = g_v16 + (size_t)bh * (S_ * HD);
    const float f = g_scales[0] * g_scales[1] * 0.08838834764831843f;

    const int rsel = (lane & 7) | (((lane >> 3) & 1) << 3);
    const int ksel = (lane >> 4) << 3;
    const int kselb = (lane >> 4) << 4;
    const int b8row = (lane & 7);
    const int b8sub = (lane >> 4);
    const int b8k   = ((lane >> 3) & 1) << 4;

    #pragma unroll
    for (int p = 0; p < 4; ++p) {
        int lin = tid + p * 256;
        int r = lin >> 3, c = (lin & 7) << 4;
        *(uint4*)(QB + r * 144 + c) = *(const uint4*)&qp[(size_t)(i0 + r) * HD + c];
    }

    float o[4][4][4] = {};
    float mrow[4][2], lrow[4][2];
    #pragma unroll
    for (int mi = 0; mi < 4; ++mi) {
        mrow[mi][0] = mrow[mi][1] = -1e30f;
        lrow[mi][0] = lrow[mi][1] = 0.0f;
    }

    for (int kt = 0; kt < S_ / BQ; ++kt) {
        const unsigned char* kb8 = kp + (size_t)kt * BQ * HD;
        const __half* vb16 = vp + (size_t)kt * BQ * HD;
        #pragma unroll
        for (int p = 0; p < 4; ++p) {
            int lin = tid + p * 256;
            int r = lin >> 3, c = (lin & 7) << 4;
            *(uint4*)(KB + r * 144 + c) = *(const uint4*)&kb8[(size_t)r * HD + c];
        }
        #pragma unroll
        for (int p = 0; p < 8; ++p) {
            int lin = tid + p * 256;
            int r = lin >> 4, c = (lin & 15) << 3;
            *(uint4*)&Vs[r][c] = *(const uint4*)&vb16[(size_t)r * HD + c];
        }
        __syncthreads();

        // ---- S = Q @ K^T via fp8 MMA ----
        float s[4][4][4] = {};
        #pragma unroll
        for (int ks = 0; ks < 4; ++ks) {
            const int kb = ks * 32;
            unsigned a[4][4], bb[4][2];
            #pragma unroll
            for (int mi = 0; mi < 4; ++mi)
                ldsm_x4(a[mi], QB + (wm + mi * 16 + rsel) * 144 + kb + kselb);
            #pragma unroll
            for (int np = 0; np < 2; ++np) {
                unsigned r[4];
                ldsm_x4(r, KB + (wn + (np * 2 + b8sub) * 8 + b8row) * 144 + kb + b8k);
                bb[2 * np][0] = r[0]; bb[2 * np][1] = r[1];
                bb[2 * np + 1][0] = r[2]; bb[2 * np + 1][1] = r[3];
            }
            #pragma unroll
            for (int mi = 0; mi < 4; ++mi)
                #pragma unroll
                for (int ni = 0; ni < 4; ++ni)
                    mma_f8(s[mi][ni][0], s[mi][ni][1], s[mi][ni][2], s[mi][ni][3],
                           a[mi][0], a[mi][1], a[mi][2], a[mi][3], bb[ni][0], bb[ni][1]);
        }
        #pragma unroll
        for (int mi = 0; mi < 4; ++mi)
            #pragma unroll
            for (int ni = 0; ni < 4; ++ni)
                #pragma unroll
                for (int j = 0; j < 4; ++j)
                    s[mi][ni][j] *= f;

        // ---- row max ----
        float tmax[4][2];
        #pragma unroll
        for (int mi = 0; mi < 4; ++mi) {
            float h0 = -1e30f, h1 = -1e30f;
            #pragma unroll
            for (int ni = 0; ni < 4; ++ni) {
                h0 = fmaxf(h0, fmaxf(s[mi][ni][0], s[mi][ni][1]));
                h1 = fmaxf(h1, fmaxf(s[mi][ni][2], s[mi][ni][3]));
            }
            tmax[mi][0] = h0; tmax[mi][1] = h1;
        }
        #pragma unroll
        for (int off = 1; off <= 2; off <<= 1)
            #pragma unroll
            for (int mi = 0; mi < 4; ++mi) {
                tmax[mi][0] = fmaxf(tmax[mi][0], __shfl_xor_sync(0xffffffffu, tmax[mi][0], off));
                tmax[mi][1] = fmaxf(tmax[mi][1], __shfl_xor_sync(0xffffffffu, tmax[mi][1], off));
            }
        if (tig == 0) {
            #pragma unroll
            for (int mi = 0; mi < 4; ++mi) {
                red[wnid][wm + mi * 16 + g]     = tmax[mi][0];
                red[wnid][wm + mi * 16 + g + 8] = tmax[mi][1];
            }
        }
        __syncthreads();

        // ---- online softmax update; write P (fp16); __expf (HW EX2) ----
        #pragma unroll
        for (int mi = 0; mi < 4; ++mi) {
            #pragma unroll
            for (int hh = 0; hh < 2; ++hh) {
                int row = wm + mi * 16 + g + hh * 8;
                float rm = fmaxf(fmaxf(red[0][row], red[1][row]),
                                 fmaxf(red[2][row], red[3][row]));
                float mnew = fmaxf(mrow[mi][hh], rm);
                float rs = __expf(mrow[mi][hh] - mnew);
                mrow[mi][hh] = mnew;
                lrow[mi][hh] *= rs;
                #pragma unroll
                for (int ni = 0; ni < 4; ++ni) {
                    o[mi][ni][2 * hh]     *= rs;
                    o[mi][ni][2 * hh + 1] *= rs;
                }
            }
            #pragma unroll
            for (int ni = 0; ni < 4; ++ni) {
                float p0 = __expf(s[mi][ni][0] - mrow[mi][0]);
                float p1 = __expf(s[mi][ni][1] - mrow[mi][0]);
                float p2 = __expf(s[mi][ni][2] - mrow[mi][1]);
                float p3 = __expf(s[mi][ni][3] - mrow[mi][1]);
                lrow[mi][0] += p0 + p1;
                lrow[mi][1] += p2 + p3;
                int c = wn + ni * 8 + 2 * tig;
                *(__half2*)&Ps[wm + mi * 16 + g][c]     = __floats2half2_rn(p0, p1);
                *(__half2*)&Ps[wm + mi * 16 + g + 8][c] = __floats2half2_rn(p2, p3);
            }
        }
        __syncthreads();

        // ---- O += P @ V ----
        #pragma unroll
        for (int ks = 0; ks < 8; ++ks) {
            const int kb = ks * 16;
            unsigned a[4][4], bb[4][2];
            #pragma unroll
            for (int mi = 0; mi < 4; ++mi)
                ldsm_x4(a[mi], &Ps[wm + mi * 16 + rsel][kb + ksel]);
            #pragma unroll
            for (int ni = 0; ni < 4; ++ni)
                ldsm_x2_trans(bb[ni][0], bb[ni][1], &Vs[kb + (lane & 15)][wn + ni * 8]);
            #pragma unroll
            for (int mi = 0; mi < 4; ++mi)
                #pragma unroll
                for (int ni = 0; ni < 4; ++ni)
                    mma_f16(o[mi][ni][0], o[mi][ni][1], o[mi][ni][2], o[mi][ni][3],
                            a[mi][0], a[mi][1], a[mi][2], a[mi][3], bb[ni][0], bb[ni][1]);
        }
        __syncthreads();
    }

    // ---- epilogue ----
    #pragma unroll
    for (int off = 1; off <= 2; off <<= 1)
        #pragma unroll
        for (int mi = 0; mi < 4; ++mi) {
            lrow[mi][0] += __shfl_xor_sync(0xffffffffu, lrow[mi][0], off);
            lrow[mi][1] += __shfl_xor_sync(0xffffffffu, lrow[mi][1], off);
        }
    if (tig == 0) {
        #pragma unroll
        for (int mi = 0; mi < 4; ++mi) {
            red[wnid][wm + mi * 16 + g]     = lrow[mi][0];
            red[wnid][wm + mi * 16 + g + 8] = lrow[mi][1];
        }
    }
    __syncthreads();

    const float vsc = g_scales[2];
    #pragma unroll
    for (int mi = 0; mi < 4; ++mi) {
        #pragma unroll
        for (int hh = 0; hh < 2; ++hh) {
            int row = wm + mi * 16 + g + hh * 8;
            float lt = red[0][row] + red[1][row] + red[2][row] + red[3][row];
            float inv = vsc / lt;
            int srow = i0 + row;
            #pragma unroll
            for (int ni = 0; ni < 4; ++ni) {
                int d = wn + ni * 8 + 2 * tig;
                __half2 hv = __floats2half2_rn(o[mi][ni][2 * hh] * inv,
                                               o[mi][ni][2 * hh + 1] * inv);
                *(__half2*)&g_aoh[(size_t)(b * S_ + srow) * H_ + h * HD + d] = hv;
            }
        }
    }
}

// ---------------- launch ----------------
extern "C" void kernel_launch(void* const* d_in, const int* in_sizes, int n_in,
                              void* d_out, int out_size)
{
    const float* x    = (const float*)d_in[0];
    const float* Wqkv = (const float*)d_in[1];
    const float* Wout = (const float*)d_in[2];
    const float* bout = (const float*)d_in[3];
    float* y = (float*)d_out;

    float* qkv_ptr = nullptr;
    __half *xh, *xl, *wqh, *wql, *woh, *wol, *aoh;
    cudaGetSymbolAddress((void**)&qkv_ptr, g_qkv);
    cudaGetSymbolAddress((void**)&xh, g_xh);   cudaGetSymbolAddress((void**)&xl, g_xl);
    cudaGetSymbolAddress((void**)&wqh, g_wqh); cudaGetSymbolAddress((void**)&wql, g_wql);
    cudaGetSymbolAddress((void**)&woh, g_woh); cudaGetSymbolAddress((void**)&wol, g_wol);
    cudaGetSymbolAddress((void**)&aoh, g_aoh);

    static int attr_set = 0;
    if (!attr_set) {
        cudaFuncSetAttribute(flash_kernel,
                             cudaFuncAttributeMaxDynamicSharedMemorySize, FLASH_SMEM);
        cudaFuncSetAttribute(hgemm2,
                             cudaFuncAttributeMaxDynamicSharedMemorySize, G2_SMEM);
        attr_set = 1;
    }

    zero_kernel<<<1, 32>>>();

    split_kernel<<<(M1 * H_ / 4 + 255) / 256, 256>>>(x, xh, xl, M1 * H_ / 4);
    tsplit_kernel<<<dim3(H3 / 32, H_ / 32), 256>>>(Wqkv, wqh, wql, H_, H3);
    tsplit_kernel<<<dim3(H_ / 32, H_ / 32), 256>>>(Wout, woh, wol, H_, H_);

    // 1) qkv = x @ W_qkv  (fp16x3, absmax fused)
    hgemm2<<<dim3(H3 / 128, M1 / 128), 256, G2_SMEM>>>(
        xh, xl, wqh, wql, qkv_ptr, M1, H3, H_, nullptr, 1, 1);

    scales_kernel<<<1, 32>>>();
    quant_kernel<<<(3 * PLANE / 4 + 255) / 256, 256>>>();

    // 4-6) fused flash attention (fp8 QK^T, pre-converted fp16 V)
    flash_kernel<<<dim3(S_ / BQ, B_ * NH), 256, FLASH_SMEM>>>();

    // 7) y = attnout @ W_out + b_out  (fp16x2)
    hgemm2<<<dim3(H_ / 128, M1 / 128), 256, G2_SMEM>>>(
        aoh, nullptr, woh, wol, y, M1, H_, H_, bout, 0, 0);
}

// round 14
// speedup vs baseline: 4.7341x; 1.0796x over previous
#include <cuda_runtime.h>
#include <cuda_fp16.h>
#include <cuda_fp8.h>
#include <math.h>

// ---------------- problem constants ----------------
#define B_   2
#define S_   2048
#define H_   2048
#define NH   16
#define HD   128
#define H3   (3 * H_)
#define M1   (B_ * S_)
#define PLANE (B_ * NH * S_ * HD)
#define BQ   128

// ---------------- scratch ----------------
__device__ float         g_qkv[(size_t)M1 * H3];
__device__ unsigned char g_q8[(size_t)2 * PLANE];      // q, k as raw e4m3
__device__ __half        g_v16[(size_t)PLANE];         // v dequantized (e4m3 values in fp16)
__device__ unsigned int  g_absmax[3];
__device__ float         g_scales[3];
__device__ float         g_iscales[3];
__device__ __half        g_xh[(size_t)M1 * H_],  g_xl[(size_t)M1 * H_];
__device__ __half        g_wqh[(size_t)H3 * H_], g_wql[(size_t)H3 * H_];
__device__ __half        g_woh[(size_t)H_ * H_], g_wol[(size_t)H_ * H_];
__device__ __half        g_aoh[(size_t)M1 * H_];

// ---------------- helpers ----------------
__device__ __forceinline__ unsigned short f8_to_h(unsigned char v) {
    __half_raw hr = __nv_cvt_fp8_to_halfraw(v, __NV_E4M3);
    return hr.x;
}

__device__ __forceinline__ void mma_f16(float& d0, float& d1, float& d2, float& d3,
                                        unsigned a0, unsigned a1, unsigned a2, unsigned a3,
                                        unsigned b0, unsigned b1) {
    asm volatile("mma.sync.aligned.m16n8k16.row.col.f32.f16.f16.f32 "
                 "{%0,%1,%2,%3}, {%4,%5,%6,%7}, {%8,%9}, {%0,%1,%2,%3};"
                 : "+f"(d0), "+f"(d1), "+f"(d2), "+f"(d3)
                 : "r"(a0), "r"(a1), "r"(a2), "r"(a3), "r"(b0), "r"(b1));
}
__device__ __forceinline__ void mma_f8(float& d0, float& d1, float& d2, float& d3,
                                       unsigned a0, unsigned a1, unsigned a2, unsigned a3,
                                       unsigned b0, unsigned b1) {
    asm volatile("mma.sync.aligned.m16n8k32.row.col.f32.e4m3.e4m3.f32 "
                 "{%0,%1,%2,%3}, {%4,%5,%6,%7}, {%8,%9}, {%0,%1,%2,%3};"
                 : "+f"(d0), "+f"(d1), "+f"(d2), "+f"(d3)
                 : "r"(a0), "r"(a1), "r"(a2), "r"(a3), "r"(b0), "r"(b1));
}
__device__ __forceinline__ void ldsm_x2_trans(unsigned& r0, unsigned& r1, const void* p) {
    unsigned addr = (unsigned)__cvta_generic_to_shared(p);
    asm volatile("ldmatrix.sync.aligned.m8n8.x2.trans.shared.b16 {%0,%1}, [%2];"
                 : "=r"(r0), "=r"(r1) : "r"(addr));
}
__device__ __forceinline__ void ldsm_x4(unsigned* r, const void* p) {
    unsigned addr = (unsigned)__cvta_generic_to_shared(p);
    asm volatile("ldmatrix.sync.aligned.m8n8.x4.shared.b16 {%0,%1,%2,%3}, [%4];"
                 : "=r"(r[0]), "=r"(r[1]), "=r"(r[2]), "=r"(r[3]) : "r"(addr));
}

#define SWZ(x) ((x) ^ (((x) >> 3) & 0x70))

__device__ __forceinline__ unsigned smem_u32(const void* p) {
    return (unsigned)__cvta_generic_to_shared(p);
}
__device__ __forceinline__ void cpa16(unsigned dst, const void* src) {
    asm volatile("cp.async.cg.shared.global [%0], [%1], 16;" :: "r"(dst), "l"(src));
}
__device__ __forceinline__ void cpa_commit() { asm volatile("cp.async.commit_group;" ::: "memory"); }
__device__ __forceinline__ void cpa_waitall() { asm volatile("cp.async.wait_group 0;" ::: "memory"); }

__global__ void zero_kernel() {
    if (threadIdx.x < 3) g_absmax[threadIdx.x] = 0u;
}

// ---------------- prep: elementwise fp32 -> fp16 hi/lo split ----------------
__global__ void split_kernel(const float* __restrict__ src, __half* __restrict__ dh,
                             __half* __restrict__ dl, int n4) {
    int i = blockIdx.x * blockDim.x + threadIdx.x;
    if (i >= n4) return;
    float4 v = ((const float4*)src)[i];
    float vv[4] = {v.x, v.y, v.z, v.w};
    __half h[4], l[4];
    #pragma unroll
    for (int j = 0; j < 4; ++j) {
        h[j] = __float2half_rn(vv[j]);
        l[j] = __float2half_rn(vv[j] - __half2float(h[j]));
    }
    ((__half2*)dh)[i * 2]     = __halves2half2(h[0], h[1]);
    ((__half2*)dh)[i * 2 + 1] = __halves2half2(h[2], h[3]);
    ((__half2*)dl)[i * 2]     = __halves2half2(l[0], l[1]);
    ((__half2*)dl)[i * 2 + 1] = __halves2half2(l[2], l[3]);
}

// ---------------- prep: transpose + split  W[K][N] -> T[N][K] hi (+opt lo) ------
__global__ void tsplit_kernel(const float* __restrict__ W, __half* __restrict__ Th,
                              __half* __restrict__ Tl, int K, int N) {
    __shared__ float tile[32][33];
    const int n0 = blockIdx.x * 32, k0 = blockIdx.y * 32;
    const int tid = threadIdx.x;
    const int tx = tid & 31, ty = tid >> 5;
    #pragma unroll
    for (int i = ty; i < 32; i += 8)
        tile[i][tx] = W[(size_t)(k0 + i) * N + n0 + tx];
    __syncthreads();
    const int j = tid >> 3, kg = (tid & 7) << 2;
    __half h[4], l[4];
    #pragma unroll
    for (int p = 0; p < 4; ++p) {
        float v = tile[kg + p][j];
        h[p] = __float2half_rn(v);
        l[p] = __float2half_rn(v - __half2float(h[p]));
    }
    uint2 uh, ul;
    __half2 t;
    t = __halves2half2(h[0], h[1]); uh.x = *(unsigned*)&t;
    t = __halves2half2(h[2], h[3]); uh.y = *(unsigned*)&t;
    *(uint2*)&Th[(size_t)(n0 + j) * K + k0 + kg] = uh;
    if (Tl) {
        t = __halves2half2(l[0], l[1]); ul.x = *(unsigned*)&t;
        t = __halves2half2(l[2], l[3]); ul.y = *(unsigned*)&t;
        *(uint2*)&Tl[(size_t)(n0 + j) * K + k0 + kg] = ul;
    }
}

// ============ fp16 split GEMM: 3-term (QKV) or 1-term (proj) ============
#define RG_SZ   16384
#define ST_SZ   65536
#define G2_SMEM 131072

__global__ __launch_bounds__(256, 1) void hgemm2(
    const __half* __restrict__ Agh, const __half* __restrict__ Agl,
    const __half* __restrict__ Bgh, const __half* __restrict__ Bgl,
    float* __restrict__ C, int M, int N, int K,
    const float* __restrict__ bias, int do_absmax, int three)
{
    extern __shared__ char smraw[];
    const unsigned sb = smem_u32(smraw);
    const int tid = threadIdx.x, wid = tid >> 5, lane = tid & 31;
    const int g = lane >> 2, tig = lane & 3;
    const int m0 = blockIdx.y * 128, n0 = blockIdx.x * 128;
    const int wm = (wid & 1) * 64, wn = (wid >> 1) * 32;

    const int rsel = (lane & 7) | (((lane >> 3) & 1) << 3);
    const int ksel = (lane >> 4) << 3;
    const int brow = lane & 7;
    const int bm   = lane >> 3;

    float acc[4][4][4] = {};

    const int fr = tid >> 1;
    const int fg = (tid & 1) << 2;

    auto fill = [&](int stage, int k0) {
        const __half* s0 = Agh + (size_t)(m0 + fr) * K + k0 + fg * 8;
        const __half* s2 = Bgh + (size_t)(n0 + fr) * K + k0 + fg * 8;
        unsigned base = sb + stage * ST_SZ;
        #pragma unroll
        for (int p = 0; p < 4; ++p) {
            unsigned d = SWZ((unsigned)(fr * 128 + (fg + p) * 16));
            cpa16(base + 0 * RG_SZ + d, s0 + p * 8);
            cpa16(base + 2 * RG_SZ + d, s2 + p * 8);
        }
        if (three) {
            const __half* s1 = Agl + (size_t)(m0 + fr) * K + k0 + fg * 8;
            const __half* s3 = Bgl + (size_t)(n0 + fr) * K + k0 + fg * 8;
            #pragma unroll
            for (int p = 0; p < 4; ++p) {
                unsigned d = SWZ((unsigned)(fr * 128 + (fg + p) * 16));
                cpa16(base + 1 * RG_SZ + d, s1 + p * 8);
                cpa16(base + 3 * RG_SZ + d, s3 + p * 8);
            }
        }
        cpa_commit();
    };

    fill(0, 0);
    cpa_waitall(); __syncthreads();

    const int T = K >> 6;
    for (int t = 0; t < T; ++t) {
        const int stage = t & 1;
        if (t + 1 < T) fill(stage ^ 1, (t + 1) << 6);

        const char* Ah = smraw + stage * ST_SZ;
        const char* Al = Ah + RG_SZ;
        const char* Bh = Ah + 2 * RG_SZ;
        const char* Bl = Ah + 3 * RG_SZ;

        #pragma unroll
        for (int ks = 0; ks < 4; ++ks) {
            const int kb = ks * 16;
            unsigned ah[4][4], al[4][4], bh[4][2], bl[4][2];
            #pragma unroll
            for (int mi = 0; mi < 4; ++mi) {
                unsigned off = SWZ((unsigned)((wm + mi * 16 + rsel) * 128 + (kb + ksel) * 2));
                ldsm_x4(ah[mi], Ah + off);
                if (three) ldsm_x4(al[mi], Al + off);
            }
            #pragma unroll
            for (int np = 0; np < 2; ++np) {
                unsigned off = SWZ((unsigned)((wn + (np * 2 + (bm >> 1)) * 8 + brow) * 128
                                              + (kb + (bm & 1) * 8) * 2));
                unsigned r[4];
                ldsm_x4(r, Bh + off);
                bh[2 * np][0] = r[0]; bh[2 * np][1] = r[1];
                bh[2 * np + 1][0] = r[2]; bh[2 * np + 1][1] = r[3];
                if (three) {
                    ldsm_x4(r, Bl + off);
                    bl[2 * np][0] = r[0]; bl[2 * np][1] = r[1];
                    bl[2 * np + 1][0] = r[2]; bl[2 * np + 1][1] = r[3];
                }
            }
            #pragma unroll
            for (int mi = 0; mi < 4; ++mi)
                #pragma unroll
                for (int ni = 0; ni < 4; ++ni)
                    mma_f16(acc[mi][ni][0], acc[mi][ni][1], acc[mi][ni][2], acc[mi][ni][3],
                            ah[mi][0], ah[mi][1], ah[mi][2], ah[mi][3], bh[ni][0], bh[ni][1]);
            if (three) {
                #pragma unroll
                for (int mi = 0; mi < 4; ++mi)
                    #pragma unroll
                    for (int ni = 0; ni < 4; ++ni)
                        mma_f16(acc[mi][ni][0], acc[mi][ni][1], acc[mi][ni][2], acc[mi][ni][3],
                                ah[mi][0], ah[mi][1], ah[mi][2], ah[mi][3], bl[ni][0], bl[ni][1]);
                #pragma unroll
                for (int mi = 0; mi < 4; ++mi)
                    #pragma unroll
                    for (int ni = 0; ni < 4; ++ni)
                        mma_f16(acc[mi][ni][0], acc[mi][ni][1], acc[mi][ni][2], acc[mi][ni][3],
                                al[mi][0], al[mi][1], al[mi][2], al[mi][3], bh[ni][0], bh[ni][1]);
            }
        }

        if (t + 1 < T) { cpa_waitall(); __syncthreads(); }
    }

    float lmax = 0.0f;
    #pragma unroll
    for (int mi = 0; mi < 4; ++mi) {
        int r = m0 + wm + mi * 16 + g;
        #pragma unroll
        for (int ni = 0; ni < 4; ++ni) {
            int c = n0 + wn + ni * 8 + 2 * tig;
            float2 v0 = {acc[mi][ni][0], acc[mi][ni][1]};
            float2 v1 = {acc[mi][ni][2], acc[mi][ni][3]};
            if (bias) {
                float b0 = bias[c], b1 = bias[c + 1];
                v0.x += b0; v0.y += b1;
                v1.x += b0; v1.y += b1;
            }
            if (do_absmax) {
                lmax = fmaxf(lmax, fmaxf(fmaxf(fabsf(v0.x), fabsf(v0.y)),
                                         fmaxf(fabsf(v1.x), fabsf(v1.y))));
            }
            *(float2*)&C[(size_t)r * N + c] = v0;
            *(float2*)&C[(size_t)(r + 8) * N + c] = v1;
        }
    }
    if (do_absmax) {
        #pragma unroll
        for (int o = 16; o; o >>= 1)
            lmax = fmaxf(lmax, __shfl_xor_sync(0xffffffffu, lmax, o));
        if (lane == 0) atomicMax(&g_absmax[n0 >> 11], __float_as_uint(lmax));
    }
}

// ---------------- scales / quant ----------------
__global__ void scales_kernel() {
    if (threadIdx.x < 3) {
        float sc = __uint_as_float(g_absmax[threadIdx.x]) / 448.0f;
        g_scales[threadIdx.x]  = sc;
        g_iscales[threadIdx.x] = 1.0f / sc;
    }
}

__global__ void quant_kernel() {
    int i = blockIdx.x * blockDim.x + threadIdx.x;
    if (i >= 3 * PLANE / 4) return;
    int t   = i / (PLANE / 4);
    int rem = i - t * (PLANE / 4);
    int d4 = rem & 31;
    int s  = (rem >> 5) & 2047;
    int bh = rem >> 16;
    int b = bh >> 4, h = bh & 15;
    const float isc = g_iscales[t];
    float4 v = *(const float4*)&g_qkv[(size_t)(b * S_ + s) * H3 + t * H_ + h * HD + d4 * 4];
    unsigned char q0 = __nv_cvt_float_to_fp8(v.x * isc, __NV_SATFINITE, __NV_E4M3);
    unsigned char q1 = __nv_cvt_float_to_fp8(v.y * isc, __NV_SATFINITE, __NV_E4M3);
    unsigned char q2 = __nv_cvt_float_to_fp8(v.z * isc, __NV_SATFINITE, __NV_E4M3);
    unsigned char q3 = __nv_cvt_float_to_fp8(v.w * isc, __NV_SATFINITE, __NV_E4M3);
    if (t < 2) {
        *(uchar4*)&g_q8[(size_t)t * PLANE + ((size_t)bh << 18) + (s << 7) + d4 * 4] =
            make_uchar4(q0, q1, q2, q3);
    } else {
        uint2 o;
        o.x = (unsigned)f8_to_h(q0) | ((unsigned)f8_to_h(q1) << 16);
        o.y = (unsigned)f8_to_h(q2) | ((unsigned)f8_to_h(q3) << 16);
        *(uint2*)&g_v16[((size_t)bh << 18) + (s << 7) + d4 * 4] = o;
    }
}

// ============ fused flash attention: fp8 QK^T + fp16 PV ============
#define QB_OFF 0
#define KB_OFF 18432
#define VS_OFF 36864
#define PS_OFF 71680
#define RED_OFF 106496
#define FLASH_SMEM 108544

__global__ __launch_bounds__(256, 1) void flash_kernel() {
    extern __shared__ char smraw[];
    char* QB = smraw + QB_OFF;
    char* KB = smraw + KB_OFF;
    typedef __half HRow[136];
    HRow* Vs = (HRow*)(smraw + VS_OFF);
    HRow* Ps = (HRow*)(smraw + PS_OFF);
    float (*red)[128] = (float(*)[128])(smraw + RED_OFF);

    const int tid = threadIdx.x, lane = tid & 31, wid = tid >> 5;
    const int g = lane >> 2, tig = lane & 3;
    const int wm = (wid & 1) * 64, wn = (wid >> 1) * 32;
    const int wnid = wid >> 1;
    const int bh = blockIdx.y;
    const int b = bh >> 4, h = bh & 15;
    const int i0 = blockIdx.x * BQ;
    const unsigned char* qp = g_q8 + (size_t)bh * (S_ * HD);
    const unsigned char* kp = g_q8 + (size_t)PLANE + (size_t)bh * (S_ * HD);
    const __half* vp = g_v16 + (size_t)bh * (S_ * HD);
    const float f = g_scales[0] * g_scales[1] * 0.08838834764831843f;

    const int rsel = (lane & 7) | (((lane >> 3) & 1) << 3);
    const int ksel = (lane >> 4) << 3;
    const int kselb = (lane >> 4) << 4;
    const int b8row = (lane & 7);
    const int b8sub = (lane >> 4);
    const int b8k   = ((lane >> 3) & 1) << 4;

    #pragma unroll
    for (int p = 0; p < 4; ++p) {
        int lin = tid + p * 256;
        int r = lin >> 3, c = (lin & 7) << 4;
        *(uint4*)(QB + r * 144 + c) = *(const uint4*)&qp[(size_t)(i0 + r) * HD + c];
    }

    float o[4][4][4] = {};
    float mrow[4][2], lrow[4][2];
    #pragma unroll
    for (int mi = 0; mi < 4; ++mi) {
        mrow[mi][0] = mrow[mi][1] = -1e30f;
        lrow[mi][0] = lrow[mi][1] = 0.0f;
    }

    for (int kt = 0; kt < S_ / BQ; ++kt) {
        const unsigned char* kb8 = kp + (size_t)kt * BQ * HD;
        const __half* vb16 = vp + (size_t)kt * BQ * HD;
        #pragma unroll
        for (int p = 0; p < 4; ++p) {
            int lin = tid + p * 256;
            int r = lin >> 3, c = (lin & 7) << 4;
            *(uint4*)(KB + r * 144 + c) = *(const uint4*)&kb8[(size_t)r * HD + c];
        }
        #pragma unroll
        for (int p = 0; p < 8; ++p) {
            int lin = tid + p * 256;
            int r = lin >> 4, c = (lin & 15) << 3;
            *(uint4*)&Vs[r][c] = *(const uint4*)&vb16[(size_t)r * HD + c];
        }
        __syncthreads();

        float s[4][4][4] = {};
        #pragma unroll
        for (int ks = 0; ks < 4; ++ks) {
            const int kb = ks * 32;
            unsigned a[4][4], bb[4][2];
            #pragma unroll
            for (int mi = 0; mi < 4; ++mi)
                ldsm_x4(a[mi], QB + (wm + mi * 16 + rsel) * 144 + kb + kselb);
            #pragma unroll
            for (int np = 0; np < 2; ++np) {
                unsigned r[4];
                ldsm_x4(r, KB + (wn + (np * 2 + b8sub) * 8 + b8row) * 144 + kb + b8k);
                bb[2 * np][0] = r[0]; bb[2 * np][1] = r[1];
                bb[2 * np + 1][0] = r[2]; bb[2 * np + 1][1] = r[3];
            }
            #pragma unroll
            for (int mi = 0; mi < 4; ++mi)
                #pragma unroll
                for (int ni = 0; ni < 4; ++ni)
                    mma_f8(s[mi][ni][0], s[mi][ni][1], s[mi][ni][2], s[mi][ni][3],
                           a[mi][0], a[mi][1], a[mi][2], a[mi][3], bb[ni][0], bb[ni][1]);
        }
        #pragma unroll
        for (int mi = 0; mi < 4; ++mi)
            #pragma unroll
            for (int ni = 0; ni < 4; ++ni)
                #pragma unroll
                for (int j = 0; j < 4; ++j)
                    s[mi][ni][j] *= f;

        float tmax[4][2];
        #pragma unroll
        for (int mi = 0; mi < 4; ++mi) {
            float h0 = -1e30f, h1 = -1e30f;
            #pragma unroll
            for (int ni = 0; ni < 4; ++ni) {
                h0 = fmaxf(h0, fmaxf(s[mi][ni][0], s[mi][ni][1]));
                h1 = fmaxf(h1, fmaxf(s[mi][ni][2], s[mi][ni][3]));
            }
            tmax[mi][0] = h0; tmax[mi][1] = h1;
        }
        #pragma unroll
        for (int off = 1; off <= 2; off <<= 1)
            #pragma unroll
            for (int mi = 0; mi < 4; ++mi) {
                tmax[mi][0] = fmaxf(tmax[mi][0], __shfl_xor_sync(0xffffffffu, tmax[mi][0], off));
                tmax[mi][1] = fmaxf(tmax[mi][1], __shfl_xor_sync(0xffffffffu, tmax[mi][1], off));
            }
        if (tig == 0) {
            #pragma unroll
            for (int mi = 0; mi < 4; ++mi) {
                red[wnid][wm + mi * 16 + g]     = tmax[mi][0];
                red[wnid][wm + mi * 16 + g + 8] = tmax[mi][1];
            }
        }
        __syncthreads();

        #pragma unroll
        for (int mi = 0; mi < 4; ++mi) {
            #pragma unroll
            for (int hh = 0; hh < 2; ++hh) {
                int row = wm + mi * 16 + g + hh * 8;
                float rm = fmaxf(fmaxf(red[0][row], red[1][row]),
                                 fmaxf(red[2][row], red[3][row]));
                float mnew = fmaxf(mrow[mi][hh], rm);
                float rs = __expf(mrow[mi][hh] - mnew);
                mrow[mi][hh] = mnew;
                lrow[mi][hh] *= rs;
                #pragma unroll
                for (int ni = 0; ni < 4; ++ni) {
                    o[mi][ni][2 * hh]     *= rs;
                    o[mi][ni][2 * hh + 1] *= rs;
                }
            }
            #pragma unroll
            for (int ni = 0; ni < 4; ++ni) {
                float p0 = __expf(s[mi][ni][0] - mrow[mi][0]);
                float p1 = __expf(s[mi][ni][1] - mrow[mi][0]);
                float p2 = __expf(s[mi][ni][2] - mrow[mi][1]);
                float p3 = __expf(s[mi][ni][3] - mrow[mi][1]);
                lrow[mi][0] += p0 + p1;
                lrow[mi][1] += p2 + p3;
                int c = wn + ni * 8 + 2 * tig;
                *(__half2*)&Ps[wm + mi * 16 + g][c]     = __floats2half2_rn(p0, p1);
                *(__half2*)&Ps[wm + mi * 16 + g + 8][c] = __floats2half2_rn(p2, p3);
            }
        }
        __syncthreads();

        #pragma unroll
        for (int ks = 0; ks < 8; ++ks) {
            const int kb = ks * 16;
            unsigned a[4][4], bb[4][2];
            #pragma unroll
            for (int mi = 0; mi < 4; ++mi)
                ldsm_x4(a[mi], &Ps[wm + mi * 16 + rsel][kb + ksel]);
            #pragma unroll
            for (int ni = 0; ni < 4; ++ni)
                ldsm_x2_trans(bb[ni][0], bb[ni][1], &Vs[kb + (lane & 15)][wn + ni * 8]);
            #pragma unroll
            for (int mi = 0; mi < 4; ++mi)
                #pragma unroll
                for (int ni = 0; ni < 4; ++ni)
                    mma_f16(o[mi][ni][0], o[mi][ni][1], o[mi][ni][2], o[mi][ni][3],
                            a[mi][0], a[mi][1], a[mi][2], a[mi][3], bb[ni][0], bb[ni][1]);
        }
        __syncthreads();
    }

    #pragma unroll
    for (int off = 1; off <= 2; off <<= 1)
        #pragma unroll
        for (int mi = 0; mi < 4; ++mi) {
            lrow[mi][0] += __shfl_xor_sync(0xffffffffu, lrow[mi][0], off);
            lrow[mi][1] += __shfl_xor_sync(0xffffffffu, lrow[mi][1], off);
        }
    if (tig == 0) {
        #pragma unroll
        for (int mi = 0; mi < 4; ++mi) {
            red[wnid][wm + mi * 16 + g]     = lrow[mi][0];
            red[wnid][wm + mi * 16 + g + 8] = lrow[mi][1];
        }
    }
    __syncthreads();

    const float vsc = g_scales[2];
    #pragma unroll
    for (int mi = 0; mi < 4; ++mi) {
        #pragma unroll
        for (int hh = 0; hh < 2; ++hh) {
            int row = wm + mi * 16 + g + hh * 8;
            float lt = red[0][row] + red[1][row] + red[2][row] + red[3][row];
            float inv = vsc / lt;
            int srow = i0 + row;
            #pragma unroll
            for (int ni = 0; ni < 4; ++ni) {
                int d = wn + ni * 8 + 2 * tig;
                __half2 hv = __floats2half2_rn(o[mi][ni][2 * hh] * inv,
                                               o[mi][ni][2 * hh + 1] * inv);
                *(__half2*)&g_aoh[(size_t)(b * S_ + srow) * H_ + h * HD + d] = hv;
            }
        }
    }
}

// ---------------- launch ----------------
extern "C" void kernel_launch(void* const* d_in, const int* in_sizes, int n_in,
                              void* d_out, int out_size)
{
    const float* x    = (const float*)d_in[0];
    const float* Wqkv = (const float*)d_in[1];
    const float* Wout = (const float*)d_in[2];
    const float* bout = (const float*)d_in[3];
    float* y = (float*)d_out;

    float* qkv_ptr = nullptr;
    __half *xh, *xl, *wqh, *wql, *woh, *aoh;
    cudaGetSymbolAddress((void**)&qkv_ptr, g_qkv);
    cudaGetSymbolAddress((void**)&xh, g_xh);   cudaGetSymbolAddress((void**)&xl, g_xl);
    cudaGetSymbolAddress((void**)&wqh, g_wqh); cudaGetSymbolAddress((void**)&wql, g_wql);
    cudaGetSymbolAddress((void**)&woh, g_woh);
    cudaGetSymbolAddress((void**)&aoh, g_aoh);

    static int attr_set = 0;
    if (!attr_set) {
        cudaFuncSetAttribute(flash_kernel,
                             cudaFuncAttributeMaxDynamicSharedMemorySize, FLASH_SMEM);
        cudaFuncSetAttribute(hgemm2,
                             cudaFuncAttributeMaxDynamicSharedMemorySize, G2_SMEM);
        attr_set = 1;
    }

    zero_kernel<<<1, 32>>>();

    split_kernel<<<(M1 * H_ / 4 + 255) / 256, 256>>>(x, xh, xl, M1 * H_ / 4);
    tsplit_kernel<<<dim3(H3 / 32, H_ / 32), 256>>>(Wqkv, wqh, wql, H_, H3);
    tsplit_kernel<<<dim3(H_ / 32, H_ / 32), 256>>>(Wout, woh, nullptr, H_, H_);

    // 1) qkv = x @ W_qkv  (fp16x3, absmax fused)
    hgemm2<<<dim3(H3 / 128, M1 / 128), 256, G2_SMEM>>>(
        xh, xl, wqh, wql, qkv_ptr, M1, H3, H_, nullptr, 1, 1);

    scales_kernel<<<1, 32>>>();
    quant_kernel<<<(3 * PLANE / 4 + 255) / 256, 256>>>();

    // 4-6) fused flash attention (fp8 QK^T, pre-converted fp16 V)
    flash_kernel<<<dim3(S_ / BQ, B_ * NH), 256, FLASH_SMEM>>>();

    // 7) y = attnout @ W_out + b_out  (fp16x1)
    hgemm2<<<dim3(H_ / 128, M1 / 128), 256, G2_SMEM>>>(
        aoh, nullptr, woh, nullptr, y, M1, H_, H_, bout, 0, 0);
}

// round 15
// speedup vs baseline: 5.0547x; 1.0677x over previous
#include <cuda_runtime.h>
#include <cuda_fp16.h>
#include <cuda_fp8.h>
#include <math.h>

// ---------------- problem constants ----------------
#define B_   2
#define S_   2048
#define H_   2048
#define NH   16
#define HD   128
#define H3   (3 * H_)
#define M1   (B_ * S_)
#define PLANE (B_ * NH * S_ * HD)
#define BQ   64

// ---------------- scratch ----------------
__device__ float         g_qkv[(size_t)M1 * H3];
__device__ unsigned char g_q8[(size_t)2 * PLANE];
__device__ __half        g_v16[(size_t)PLANE];
__device__ unsigned int  g_absmax[3];
__device__ __half        g_xh[(size_t)M1 * H_],  g_xl[(size_t)M1 * H_];
__device__ __half        g_wqh[(size_t)H3 * H_], g_wql[(size_t)H3 * H_];
__device__ __half        g_woh[(size_t)H_ * H_];
__device__ __half        g_aoh[(size_t)M1 * H_];

// ---------------- helpers ----------------
__device__ __forceinline__ unsigned short f8_to_h(unsigned char v) {
    __half_raw hr = __nv_cvt_fp8_to_halfraw(v, __NV_E4M3);
    return hr.x;
}

__device__ __forceinline__ void mma_f16(float& d0, float& d1, float& d2, float& d3,
                                        unsigned a0, unsigned a1, unsigned a2, unsigned a3,
                                        unsigned b0, unsigned b1) {
    asm volatile("mma.sync.aligned.m16n8k16.row.col.f32.f16.f16.f32 "
                 "{%0,%1,%2,%3}, {%4,%5,%6,%7}, {%8,%9}, {%0,%1,%2,%3};"
                 : "+f"(d0), "+f"(d1), "+f"(d2), "+f"(d3)
                 : "r"(a0), "r"(a1), "r"(a2), "r"(a3), "r"(b0), "r"(b1));
}
__device__ __forceinline__ void mma_f8(float& d0, float& d1, float& d2, float& d3,
                                       unsigned a0, unsigned a1, unsigned a2, unsigned a3,
                                       unsigned b0, unsigned b1) {
    asm volatile("mma.sync.aligned.m16n8k32.row.col.f32.e4m3.e4m3.f32 "
                 "{%0,%1,%2,%3}, {%4,%5,%6,%7}, {%8,%9}, {%0,%1,%2,%3};"
                 : "+f"(d0), "+f"(d1), "+f"(d2), "+f"(d3)
                 : "r"(a0), "r"(a1), "r"(a2), "r"(a3), "r"(b0), "r"(b1));
}
__device__ __forceinline__ void ldsm_x2_trans(unsigned& r0, unsigned& r1, const void* p) {
    unsigned addr = (unsigned)__cvta_generic_to_shared(p);
    asm volatile("ldmatrix.sync.aligned.m8n8.x2.trans.shared.b16 {%0,%1}, [%2];"
                 : "=r"(r0), "=r"(r1) : "r"(addr));
}
__device__ __forceinline__ void ldsm_x4(unsigned* r, const void* p) {
    unsigned addr = (unsigned)__cvta_generic_to_shared(p);
    asm volatile("ldmatrix.sync.aligned.m8n8.x4.shared.b16 {%0,%1,%2,%3}, [%4];"
                 : "=r"(r[0]), "=r"(r[1]), "=r"(r[2]), "=r"(r[3]) : "r"(addr));
}

#define SWZ(x) ((x) ^ (((x) >> 3) & 0x70))

__device__ __forceinline__ unsigned smem_u32(const void* p) {
    return (unsigned)__cvta_generic_to_shared(p);
}
__device__ __forceinline__ void cpa16(unsigned dst, const void* src) {
    asm volatile("cp.async.cg.shared.global [%0], [%1], 16;" :: "r"(dst), "l"(src));
}
__device__ __forceinline__ void cpa_commit() { asm volatile("cp.async.commit_group;" ::: "memory"); }
__device__ __forceinline__ void cpa_waitall() { asm volatile("cp.async.wait_group 0;" ::: "memory"); }

// ============ merged prep: zero + split(x) + tsplit(Wqkv) + tsplit(Wout) ========
#define NB_SPLIT 8192           // (M1*H_/4)/256
#define NB_TSQ   12288          // (H3/32)*(H_/32) = 192*64
#define NB_TSO   4096           // (H_/32)*(H_/32) = 64*64

__global__ void prep_kernel(const float* __restrict__ x,
                            const float* __restrict__ Wqkv,
                            const float* __restrict__ Wout) {
    __shared__ float tile[32][33];
    const int b = blockIdx.x;
    const int tid = threadIdx.x;
    if (b == 0 && tid < 3) g_absmax[tid] = 0u;

    if (b < NB_SPLIT) {
        // fp32 -> fp16 hi/lo split of x
        int i = b * 256 + tid;
        float4 v = ((const float4*)x)[i];
        float vv[4] = {v.x, v.y, v.z, v.w};
        __half h[4], l[4];
        #pragma unroll
        for (int j = 0; j < 4; ++j) {
            h[j] = __float2half_rn(vv[j]);
            l[j] = __float2half_rn(vv[j] - __half2float(h[j]));
        }
        ((__half2*)g_xh)[i * 2]     = __halves2half2(h[0], h[1]);
        ((__half2*)g_xh)[i * 2 + 1] = __halves2half2(h[2], h[3]);
        ((__half2*)g_xl)[i * 2]     = __halves2half2(l[0], l[1]);
        ((__half2*)g_xl)[i * 2 + 1] = __halves2half2(l[2], l[3]);
        return;
    }

    const float* W;
    __half *Th, *Tl;
    int K, N, n0, k0;
    if (b < NB_SPLIT + NB_TSQ) {
        int bb = b - NB_SPLIT;
        W = Wqkv; Th = g_wqh; Tl = g_wql;
        K = H_; N = H3;
        n0 = (bb % (H3 / 32)) * 32; k0 = (bb / (H3 / 32)) * 32;
    } else {
        int bb = b - NB_SPLIT - NB_TSQ;
        W = Wout; Th = g_woh; Tl = nullptr;
        K = H_; N = H_;
        n0 = (bb % (H_ / 32)) * 32; k0 = (bb / (H_ / 32)) * 32;
    }
    const int tx = tid & 31, ty = tid >> 5;
    #pragma unroll
    for (int i = ty; i < 32; i += 8)
        tile[i][tx] = W[(size_t)(k0 + i) * N + n0 + tx];
    __syncthreads();
    const int j = tid >> 3, kg = (tid & 7) << 2;
    __half h[4], l[4];
    #pragma unroll
    for (int p = 0; p < 4; ++p) {
        float v = tile[kg + p][j];
        h[p] = __float2half_rn(v);
        l[p] = __float2half_rn(v - __half2float(h[p]));
    }
    uint2 uh, ul; __half2 t;
    t = __halves2half2(h[0], h[1]); uh.x = *(unsigned*)&t;
    t = __halves2half2(h[2], h[3]); uh.y = *(unsigned*)&t;
    *(uint2*)&Th[(size_t)(n0 + j) * K + k0 + kg] = uh;
    if (Tl) {
        t = __halves2half2(l[0], l[1]); ul.x = *(unsigned*)&t;
        t = __halves2half2(l[2], l[3]); ul.y = *(unsigned*)&t;
        *(uint2*)&Tl[(size_t)(n0 + j) * K + k0 + kg] = ul;
    }
}

// ============ fp16 split GEMM, 64x128 tile: 3-term (QKV) or 1-term (proj) =======
#define AH_OFF  0
#define AL_OFF  8192
#define BH_OFF  16384
#define BL_OFF  32768
#define STAGE_SZ 49152
#define G2_SMEM  98304

__global__ __launch_bounds__(256) void hgemm2(
    const __half* __restrict__ Agh, const __half* __restrict__ Agl,
    const __half* __restrict__ Bgh, const __half* __restrict__ Bgl,
    float* __restrict__ C, int M, int N, int K,
    const float* __restrict__ bias, int do_absmax, int three)
{
    extern __shared__ char smraw[];
    const unsigned sb = smem_u32(smraw);
    const int tid = threadIdx.x, wid = tid >> 5, lane = tid & 31;
    const int g = lane >> 2, tig = lane & 3;
    const int m0 = blockIdx.y * 64, n0 = blockIdx.x * 128;
    const int wm = (wid & 1) * 32, wn = (wid >> 1) * 32;

    const int rsel = (lane & 7) | (((lane >> 3) & 1) << 3);
    const int ksel = (lane >> 4) << 3;
    const int brow = lane & 7;
    const int bm   = lane >> 3;

    float acc[2][4][4] = {};

    // A fill: 64 rows x 8 granules = 512; 2/thread.  B fill: 128 rows x 8 = 1024; 4/thread.
    const int afr = tid >> 2, afg = (tid & 3) << 1;
    const int bfr = tid >> 1, bfg = (tid & 1) << 2;

    auto fill = [&](int stage, int k0) {
        unsigned base = sb + stage * STAGE_SZ;
        #pragma unroll
        for (int p = 0; p < 2; ++p) {
            unsigned d = SWZ((unsigned)(afr * 128 + (afg + p) * 16));
            cpa16(base + AH_OFF + d, Agh + (size_t)(m0 + afr) * K + k0 + (afg + p) * 8);
        }
        #pragma unroll
        for (int p = 0; p < 4; ++p) {
            unsigned d = SWZ((unsigned)(bfr * 128 + (bfg + p) * 16));
            cpa16(base + BH_OFF + d, Bgh + (size_t)(n0 + bfr) * K + k0 + (bfg + p) * 8);
        }
        if (three) {
            #pragma unroll
            for (int p = 0; p < 2; ++p) {
                unsigned d = SWZ((unsigned)(afr * 128 + (afg + p) * 16));
                cpa16(base + AL_OFF + d, Agl + (size_t)(m0 + afr) * K + k0 + (afg + p) * 8);
            }
            #pragma unroll
            for (int p = 0; p < 4; ++p) {
                unsigned d = SWZ((unsigned)(bfr * 128 + (bfg + p) * 16));
                cpa16(base + BL_OFF + d, Bgl + (size_t)(n0 + bfr) * K + k0 + (bfg + p) * 8);
            }
        }
        cpa_commit();
    };

    fill(0, 0);
    cpa_waitall(); __syncthreads();

    const int T = K >> 6;
    for (int t = 0; t < T; ++t) {
        const int stage = t & 1;
        if (t + 1 < T) fill(stage ^ 1, (t + 1) << 6);

        const char* base = smraw + stage * STAGE_SZ;
        const char* Ah = base + AH_OFF;
        const char* Al = base + AL_OFF;
        const char* Bh = base + BH_OFF;
        const char* Bl = base + BL_OFF;

        #pragma unroll
        for (int ks = 0; ks < 4; ++ks) {
            const int kb = ks * 16;
            unsigned ah[2][4], al[2][4], bh[4][2], bl[4][2];
            #pragma unroll
            for (int mi = 0; mi < 2; ++mi) {
                unsigned off = SWZ((unsigned)((wm + mi * 16 + rsel) * 128 + (kb + ksel) * 2));
                ldsm_x4(ah[mi], Ah + off);
                if (three) ldsm_x4(al[mi], Al + off);
            }
            #pragma unroll
            for (int np = 0; np < 2; ++np) {
                unsigned off = SWZ((unsigned)((wn + (np * 2 + (bm >> 1)) * 8 + brow) * 128
                                              + (kb + (bm & 1) * 8) * 2));
                unsigned r[4];
                ldsm_x4(r, Bh + off);
                bh[2 * np][0] = r[0]; bh[2 * np][1] = r[1];
                bh[2 * np + 1][0] = r[2]; bh[2 * np + 1][1] = r[3];
                if (three) {
                    ldsm_x4(r, Bl + off);
                    bl[2 * np][0] = r[0]; bl[2 * np][1] = r[1];
                    bl[2 * np + 1][0] = r[2]; bl[2 * np + 1][1] = r[3];
                }
            }
            #pragma unroll
            for (int mi = 0; mi < 2; ++mi)
                #pragma unroll
                for (int ni = 0; ni < 4; ++ni)
                    mma_f16(acc[mi][ni][0], acc[mi][ni][1], acc[mi][ni][2], acc[mi][ni][3],
                            ah[mi][0], ah[mi][1], ah[mi][2], ah[mi][3], bh[ni][0], bh[ni][1]);
            if (three) {
                #pragma unroll
                for (int mi = 0; mi < 2; ++mi)
                    #pragma unroll
                    for (int ni = 0; ni < 4; ++ni)
                        mma_f16(acc[mi][ni][0], acc[mi][ni][1], acc[mi][ni][2], acc[mi][ni][3],
                                ah[mi][0], ah[mi][1], ah[mi][2], ah[mi][3], bl[ni][0], bl[ni][1]);
                #pragma unroll
                for (int mi = 0; mi < 2; ++mi)
                    #pragma unroll
                    for (int ni = 0; ni < 4; ++ni)
                        mma_f16(acc[mi][ni][0], acc[mi][ni][1], acc[mi][ni][2], acc[mi][ni][3],
                                al[mi][0], al[mi][1], al[mi][2], al[mi][3], bh[ni][0], bh[ni][1]);
            }
        }

        if (t + 1 < T) { cpa_waitall(); __syncthreads(); }
    }

    float lmax = 0.0f;
    #pragma unroll
    for (int mi = 0; mi < 2; ++mi) {
        int r = m0 + wm + mi * 16 + g;
        #pragma unroll
        for (int ni = 0; ni < 4; ++ni) {
            int c = n0 + wn + ni * 8 + 2 * tig;
            float2 v0 = {acc[mi][ni][0], acc[mi][ni][1]};
            float2 v1 = {acc[mi][ni][2], acc[mi][ni][3]};
            if (bias) {
                float b0 = bias[c], b1 = bias[c + 1];
                v0.x += b0; v0.y += b1;
                v1.x += b0; v1.y += b1;
            }
            if (do_absmax) {
                lmax = fmaxf(lmax, fmaxf(fmaxf(fabsf(v0.x), fabsf(v0.y)),
                                         fmaxf(fabsf(v1.x), fabsf(v1.y))));
            }
            *(float2*)&C[(size_t)r * N + c] = v0;
            *(float2*)&C[(size_t)(r + 8) * N + c] = v1;
        }
    }
    if (do_absmax) {
        #pragma unroll
        for (int o = 16; o; o >>= 1)
            lmax = fmaxf(lmax, __shfl_xor_sync(0xffffffffu, lmax, o));
        if (lane == 0) atomicMax(&g_absmax[n0 >> 11], __float_as_uint(lmax));
    }
}

// ---------------- quant (scales computed inline from g_absmax) ----------------
__global__ void quant_kernel() {
    int i = blockIdx.x * blockDim.x + threadIdx.x;
    if (i >= 3 * PLANE / 4) return;
    int t   = i / (PLANE / 4);
    int rem = i - t * (PLANE / 4);
    int d4 = rem & 31;
    int s  = (rem >> 5) & 2047;
    int bh = rem >> 16;
    int b = bh >> 4, h = bh & 15;
    const float sc  = __uint_as_float(g_absmax[t]) / 448.0f;
    const float isc = 1.0f / sc;
    float4 v = *(const float4*)&g_qkv[(size_t)(b * S_ + s) * H3 + t * H_ + h * HD + d4 * 4];
    unsigned char q0 = __nv_cvt_float_to_fp8(v.x * isc, __NV_SATFINITE, __NV_E4M3);
    unsigned char q1 = __nv_cvt_float_to_fp8(v.y * isc, __NV_SATFINITE, __NV_E4M3);
    unsigned char q2 = __nv_cvt_float_to_fp8(v.z * isc, __NV_SATFINITE, __NV_E4M3);
    unsigned char q3 = __nv_cvt_float_to_fp8(v.w * isc, __NV_SATFINITE, __NV_E4M3);
    if (t < 2) {
        *(uchar4*)&g_q8[(size_t)t * PLANE + ((size_t)bh << 18) + (s << 7) + d4 * 4] =
            make_uchar4(q0, q1, q2, q3);
    } else {
        uint2 o;
        o.x = (unsigned)f8_to_h(q0) | ((unsigned)f8_to_h(q1) << 16);
        o.y = (unsigned)f8_to_h(q2) | ((unsigned)f8_to_h(q3) << 16);
        *(uint2*)&g_v16[((size_t)bh << 18) + (s << 7) + d4 * 4] = o;
    }
}

// ============ fused flash attention, 64-query tiles: fp8 QK^T + fp16 PV =========
#define QB_OFF 0
#define KB_OFF 9216
#define VS_OFF 27648
#define PS_OFF 62464
#define RED_OFF 79872
#define FLASH_SMEM 80896

__global__ __launch_bounds__(256) void flash_kernel() {
    extern __shared__ char smraw[];
    char* QB = smraw + QB_OFF;                 // 64 x 144 B (raw e4m3)
    char* KB = smraw + KB_OFF;                 // 128 x 144 B
    typedef __half HRow[136];
    HRow* Vs = (HRow*)(smraw + VS_OFF);        // 128 x 136 halves
    HRow* Ps = (HRow*)(smraw + PS_OFF);        // 64 x 136 halves
    float (*red)[64] = (float(*)[64])(smraw + RED_OFF);

    const int tid = threadIdx.x, lane = tid & 31, wid = tid >> 5;
    const int g = lane >> 2, tig = lane & 3;
    const int wm = (wid & 1) * 32, wn = (wid >> 1) * 32;
    const int wnid = wid >> 1;
    const int bh = blockIdx.y;
    const int b = bh >> 4, h = bh & 15;
    const int i0 = blockIdx.x * BQ;
    const unsigned char* qp = g_q8 + (size_t)bh * (S_ * HD);
    const unsigned char* kp = g_q8 + (size_t)PLANE + (size_t)bh * (S_ * HD);
    const __half* vp = g_v16 + (size_t)bh * (S_ * HD);
    const float f = (__uint_as_float(g_absmax[0]) / 448.0f)
                  * (__uint_as_float(g_absmax[1]) / 448.0f) * 0.08838834764831843f;

    const int rsel = (lane & 7) | (((lane >> 3) & 1) << 3);
    const int ksel = (lane >> 4) << 3;
    const int kselb = (lane >> 4) << 4;
    const int b8row = (lane & 7);
    const int b8sub = (lane >> 4);
    const int b8k   = ((lane >> 3) & 1) << 4;

    // Q tile: 64 rows x 128 B raw copy
    #pragma unroll
    for (int p = 0; p < 2; ++p) {
        int lin = tid + p * 256;
        int r = lin >> 3, c = (lin & 7) << 4;
        *(uint4*)(QB + r * 144 + c) = *(const uint4*)&qp[(size_t)(i0 + r) * HD + c];
    }

    float o[2][4][4] = {};
    float mrow[2][2], lrow[2][2];
    #pragma unroll
    for (int mi = 0; mi < 2; ++mi) {
        mrow[mi][0] = mrow[mi][1] = -1e30f;
        lrow[mi][0] = lrow[mi][1] = 0.0f;
    }

    for (int kt = 0; kt < S_ / 128; ++kt) {
        const unsigned char* kb8 = kp + (size_t)kt * 128 * HD;
        const __half* vb16 = vp + (size_t)kt * 128 * HD;
        #pragma unroll
        for (int p = 0; p < 4; ++p) {
            int lin = tid + p * 256;
            int r = lin >> 3, c = (lin & 7) << 4;
            *(uint4*)(KB + r * 144 + c) = *(const uint4*)&kb8[(size_t)r * HD + c];
        }
        #pragma unroll
        for (int p = 0; p < 8; ++p) {
            int lin = tid + p * 256;
            int r = lin >> 4, c = (lin & 15) << 3;
            *(uint4*)&Vs[r][c] = *(const uint4*)&vb16[(size_t)r * HD + c];
        }
        __syncthreads();

        // S = Q @ K^T (fp8)
        float s[2][4][4] = {};
        #pragma unroll
        for (int ks = 0; ks < 4; ++ks) {
            const int kb = ks * 32;
            unsigned a[2][4], bb[4][2];
            #pragma unroll
            for (int mi = 0; mi < 2; ++mi)
                ldsm_x4(a[mi], QB + (wm + mi * 16 + rsel) * 144 + kb + kselb);
            #pragma unroll
            for (int np = 0; np < 2; ++np) {
                unsigned r[4];
                ldsm_x4(r, KB + (wn + (np * 2 + b8sub) * 8 + b8row) * 144 + kb + b8k);
                bb[2 * np][0] = r[0]; bb[2 * np][1] = r[1];
                bb[2 * np + 1][0] = r[2]; bb[2 * np + 1][1] = r[3];
            }
            #pragma unroll
            for (int mi = 0; mi < 2; ++mi)
                #pragma unroll
                for (int ni = 0; ni < 4; ++ni)
                    mma_f8(s[mi][ni][0], s[mi][ni][1], s[mi][ni][2], s[mi][ni][3],
                           a[mi][0], a[mi][1], a[mi][2], a[mi][3], bb[ni][0], bb[ni][1]);
        }
        #pragma unroll
        for (int mi = 0; mi < 2; ++mi)
            #pragma unroll
            for (int ni = 0; ni < 4; ++ni)
                #pragma unroll
                for (int j = 0; j < 4; ++j)
                    s[mi][ni][j] *= f;

        // row max
        float tmax[2][2];
        #pragma unroll
        for (int mi = 0; mi < 2; ++mi) {
            float h0 = -1e30f, h1 = -1e30f;
            #pragma unroll
            for (int ni = 0; ni < 4; ++ni) {
                h0 = fmaxf(h0, fmaxf(s[mi][ni][0], s[mi][ni][1]));
                h1 = fmaxf(h1, fmaxf(s[mi][ni][2], s[mi][ni][3]));
            }
            tmax[mi][0] = h0; tmax[mi][1] = h1;
        }
        #pragma unroll
        for (int off = 1; off <= 2; off <<= 1)
            #pragma unroll
            for (int mi = 0; mi < 2; ++mi) {
                tmax[mi][0] = fmaxf(tmax[mi][0], __shfl_xor_sync(0xffffffffu, tmax[mi][0], off));
                tmax[mi][1] = fmaxf(tmax[mi][1], __shfl_xor_sync(0xffffffffu, tmax[mi][1], off));
            }
        if (tig == 0) {
            #pragma unroll
            for (int mi = 0; mi < 2; ++mi) {
                red[wnid][wm + mi * 16 + g]     = tmax[mi][0];
                red[wnid][wm + mi * 16 + g + 8] = tmax[mi][1];
            }
        }
        __syncthreads();

        // online softmax update; write P
        #pragma unroll
        for (int mi = 0; mi < 2; ++mi) {
            #pragma unroll
            for (int hh = 0; hh < 2; ++hh) {
                int row = wm + mi * 16 + g + hh * 8;
                float rm = fmaxf(fmaxf(red[0][row], red[1][row]),
                                 fmaxf(red[2][row], red[3][row]));
                float mnew = fmaxf(mrow[mi][hh], rm);
                float rs = __expf(mrow[mi][hh] - mnew);
                mrow[mi][hh] = mnew;
                lrow[mi][hh] *= rs;
                #pragma unroll
                for (int ni = 0; ni < 4; ++ni) {
                    o[mi][ni][2 * hh]     *= rs;
                    o[mi][ni][2 * hh + 1] *= rs;
                }
            }
            #pragma unroll
            for (int ni = 0; ni < 4; ++ni) {
                float p0 = __expf(s[mi][ni][0] - mrow[mi][0]);
                float p1 = __expf(s[mi][ni][1] - mrow[mi][0]);
                float p2 = __expf(s[mi][ni][2] - mrow[mi][1]);
                float p3 = __expf(s[mi][ni][3] - mrow[mi][1]);
                lrow[mi][0] += p0 + p1;
                lrow[mi][1] += p2 + p3;
                int c = wn + ni * 8 + 2 * tig;
                *(__half2*)&Ps[wm + mi * 16 + g][c]     = __floats2half2_rn(p0, p1);
                *(__half2*)&Ps[wm + mi * 16 + g + 8][c] = __floats2half2_rn(p2, p3);
            }
        }
        __syncthreads();

        // O += P @ V
        #pragma unroll
        for (int ks = 0; ks < 8; ++ks) {
            const int kb = ks * 16;
            unsigned a[2][4], bb[4][2];
            #pragma unroll
            for (int mi = 0; mi < 2; ++mi)
                ldsm_x4(a[mi], &Ps[wm + mi * 16 + rsel][kb + ksel]);
            #pragma unroll
            for (int ni = 0; ni < 4; ++ni)
                ldsm_x2_trans(bb[ni][0], bb[ni][1], &Vs[kb + (lane & 15)][wn + ni * 8]);
            #pragma unroll
            for (int mi = 0; mi < 2; ++mi)
                #pragma unroll
                for (int ni = 0; ni < 4; ++ni)
                    mma_f16(o[mi][ni][0], o[mi][ni][1], o[mi][ni][2], o[mi][ni][3],
                            a[mi][0], a[mi][1], a[mi][2], a[mi][3], bb[ni][0], bb[ni][1]);
        }
        __syncthreads();
    }

    // epilogue
    #pragma unroll
    for (int off = 1; off <= 2; off <<= 1)
        #pragma unroll
        for (int mi = 0; mi < 2; ++mi) {
            lrow[mi][0] += __shfl_xor_sync(0xffffffffu, lrow[mi][0], off);
            lrow[mi][1] += __shfl_xor_sync(0xffffffffu, lrow[mi][1], off);
        }
    if (tig == 0) {
        #pragma unroll
        for (int mi = 0; mi < 2; ++mi) {
            red[wnid][wm + mi * 16 + g]     = lrow[mi][0];
            red[wnid][wm + mi * 16 + g + 8] = lrow[mi][1];
        }
    }
    __syncthreads();

    const float vsc = __uint_as_float(g_absmax[2]) / 448.0f;
    #pragma unroll
    for (int mi = 0; mi < 2; ++mi) {
        #pragma unroll
        for (int hh = 0; hh < 2; ++hh) {
            int row = wm + mi * 16 + g + hh * 8;
            float lt = red[0][row] + red[1][row] + red[2][row] + red[3][row];
            float inv = vsc / lt;
            int srow = i0 + row;
            #pragma unroll
            for (int ni = 0; ni < 4; ++ni) {
                int d = wn + ni * 8 + 2 * tig;
                __half2 hv = __floats2half2_rn(o[mi][ni][2 * hh] * inv,
                                               o[mi][ni][2 * hh + 1] * inv);
                *(__half2*)&g_aoh[(size_t)(b * S_ + srow) * H_ + h * HD + d] = hv;
            }
        }
    }
}

// ---------------- launch ----------------
extern "C" void kernel_launch(void* const* d_in, const int* in_sizes, int n_in,
                              void* d_out, int out_size)
{
    const float* x    = (const float*)d_in[0];
    const float* Wqkv = (const float*)d_in[1];
    const float* Wout = (const float*)d_in[2];
    const float* bout = (const float*)d_in[3];
    float* y = (float*)d_out;

    float* qkv_ptr = nullptr;
    __half *xh, *xl, *wqh, *wql, *woh, *aoh;
    cudaGetSymbolAddress((void**)&qkv_ptr, g_qkv);
    cudaGetSymbolAddress((void**)&xh, g_xh);   cudaGetSymbolAddress((void**)&xl, g_xl);
    cudaGetSymbolAddress((void**)&wqh, g_wqh); cudaGetSymbolAddress((void**)&wql, g_wql);
    cudaGetSymbolAddress((void**)&woh, g_woh);
    cudaGetSymbolAddress((void**)&aoh, g_aoh);

    static int attr_set = 0;
    if (!attr_set) {
        cudaFuncSetAttribute(flash_kernel,
                             cudaFuncAttributeMaxDynamicSharedMemorySize, FLASH_SMEM);
        cudaFuncSetAttribute(hgemm2,
                             cudaFuncAttributeMaxDynamicSharedMemorySize, G2_SMEM);
        attr_set = 1;
    }

    // 0) merged prep: zero absmax + split(x) + tsplit(Wqkv) + tsplit(Wout)
    prep_kernel<<<NB_SPLIT + NB_TSQ + NB_TSO, 256>>>(x, Wqkv, Wout);

    // 1) qkv = x @ W_qkv  (fp16x3, 64x128 tiles, absmax fused)
    hgemm2<<<dim3(H3 / 128, M1 / 64), 256, G2_SMEM>>>(
        xh, xl, wqh, wql, qkv_ptr, M1, H3, H_, nullptr, 1, 1);

    // 2-3) quantize (scales inline)
    quant_kernel<<<(3 * PLANE / 4 + 255) / 256, 256>>>();

    // 4-6) fused flash attention (64-query tiles)
    flash_kernel<<<dim3(S_ / BQ, B_ * NH), 256, FLASH_SMEM>>>();

    // 7) y = attnout @ W_out + b_out  (fp16x1, 64x128 tiles)
    hgemm2<<<dim3(H_ / 128, M1 / 64), 256, G2_SMEM>>>(
        aoh, nullptr, woh, nullptr, y, M1, H_, H_, bout, 0, 0);
}

// round 16
// speedup vs baseline: 5.2475x; 1.0381x over previous
#include <cuda_runtime.h>
#include <cuda_fp16.h>
#include <cuda_fp8.h>
#include <math.h>

// ---------------- problem constants ----------------
#define B_   2
#define S_   2048
#define H_   2048
#define NH   16
#define HD   128
#define H3   (3 * H_)
#define M1   (B_ * S_)
#define PLANE (B_ * NH * S_ * HD)
#define BQ   64

// ---------------- scratch ----------------
__device__ float         g_qkv[(size_t)M1 * H3];
__device__ unsigned char g_q8[(size_t)2 * PLANE];
__device__ __half        g_v16[(size_t)PLANE];
__device__ unsigned int  g_absmax[3];
__device__ __half        g_xh[(size_t)M1 * H_],  g_xl[(size_t)M1 * H_];
__device__ __half        g_wqh[(size_t)H3 * H_], g_wql[(size_t)H3 * H_];
__device__ __half        g_woh[(size_t)H_ * H_];
__device__ __half        g_aoh[(size_t)M1 * H_];

// ---------------- helpers ----------------
__device__ __forceinline__ unsigned short f8_to_h(unsigned char v) {
    __half_raw hr = __nv_cvt_fp8_to_halfraw(v, __NV_E4M3);
    return hr.x;
}

__device__ __forceinline__ void mma_f16(float& d0, float& d1, float& d2, float& d3,
                                        unsigned a0, unsigned a1, unsigned a2, unsigned a3,
                                        unsigned b0, unsigned b1) {
    asm volatile("mma.sync.aligned.m16n8k16.row.col.f32.f16.f16.f32 "
                 "{%0,%1,%2,%3}, {%4,%5,%6,%7}, {%8,%9}, {%0,%1,%2,%3};"
                 : "+f"(d0), "+f"(d1), "+f"(d2), "+f"(d3)
                 : "r"(a0), "r"(a1), "r"(a2), "r"(a3), "r"(b0), "r"(b1));
}
__device__ __forceinline__ void mma_f8(float& d0, float& d1, float& d2, float& d3,
                                       unsigned a0, unsigned a1, unsigned a2, unsigned a3,
                                       unsigned b0, unsigned b1) {
    asm volatile("mma.sync.aligned.m16n8k32.row.col.f32.e4m3.e4m3.f32 "
                 "{%0,%1,%2,%3}, {%4,%5,%6,%7}, {%8,%9}, {%0,%1,%2,%3};"
                 : "+f"(d0), "+f"(d1), "+f"(d2), "+f"(d3)
                 : "r"(a0), "r"(a1), "r"(a2), "r"(a3), "r"(b0), "r"(b1));
}
__device__ __forceinline__ void ldsm_x2_trans(unsigned& r0, unsigned& r1, const void* p) {
    unsigned addr = (unsigned)__cvta_generic_to_shared(p);
    asm volatile("ldmatrix.sync.aligned.m8n8.x2.trans.shared.b16 {%0,%1}, [%2];"
                 : "=r"(r0), "=r"(r1) : "r"(addr));
}
__device__ __forceinline__ void ldsm_x4(unsigned* r, const void* p) {
    unsigned addr = (unsigned)__cvta_generic_to_shared(p);
    asm volatile("ldmatrix.sync.aligned.m8n8.x4.shared.b16 {%0,%1,%2,%3}, [%4];"
                 : "=r"(r[0]), "=r"(r[1]), "=r"(r[2]), "=r"(r[3]) : "r"(addr));
}

#define SWZ(x) ((x) ^ (((x) >> 3) & 0x70))

__device__ __forceinline__ unsigned smem_u32(const void* p) {
    return (unsigned)__cvta_generic_to_shared(p);
}
__device__ __forceinline__ void cpa16(unsigned dst, const void* src) {
    asm volatile("cp.async.cg.shared.global [%0], [%1], 16;" :: "r"(dst), "l"(src));
}
__device__ __forceinline__ void cpa_commit() { asm volatile("cp.async.commit_group;" ::: "memory"); }
__device__ __forceinline__ void cpa_waitall() { asm volatile("cp.async.wait_group 0;" ::: "memory"); }

// ============ merged prep: zero + split(x) + tsplit(Wqkv) + tsplit(Wout) ========
#define NB_SPLIT 8192
#define NB_TSQ   12288
#define NB_TSO   4096

__global__ void prep_kernel(const float* __restrict__ x,
                            const float* __restrict__ Wqkv,
                            const float* __restrict__ Wout) {
    __shared__ float tile[32][33];
    const int b = blockIdx.x;
    const int tid = threadIdx.x;
    if (b == 0 && tid < 3) g_absmax[tid] = 0u;

    if (b < NB_SPLIT) {
        int i = b * 256 + tid;
        float4 v = ((const float4*)x)[i];
        float vv[4] = {v.x, v.y, v.z, v.w};
        __half h[4], l[4];
        #pragma unroll
        for (int j = 0; j < 4; ++j) {
            h[j] = __float2half_rn(vv[j]);
            l[j] = __float2half_rn(vv[j] - __half2float(h[j]));
        }
        ((__half2*)g_xh)[i * 2]     = __halves2half2(h[0], h[1]);
        ((__half2*)g_xh)[i * 2 + 1] = __halves2half2(h[2], h[3]);
        ((__half2*)g_xl)[i * 2]     = __halves2half2(l[0], l[1]);
        ((__half2*)g_xl)[i * 2 + 1] = __halves2half2(l[2], l[3]);
        return;
    }

    const float* W;
    __half *Th, *Tl;
    int K, N, n0, k0;
    if (b < NB_SPLIT + NB_TSQ) {
        int bb = b - NB_SPLIT;
        W = Wqkv; Th = g_wqh; Tl = g_wql;
        K = H_; N = H3;
        n0 = (bb % (H3 / 32)) * 32; k0 = (bb / (H3 / 32)) * 32;
    } else {
        int bb = b - NB_SPLIT - NB_TSQ;
        W = Wout; Th = g_woh; Tl = nullptr;
        K = H_; N = H_;
        n0 = (bb % (H_ / 32)) * 32; k0 = (bb / (H_ / 32)) * 32;
    }
    const int tx = tid & 31, ty = tid >> 5;
    #pragma unroll
    for (int i = ty; i < 32; i += 8)
        tile[i][tx] = W[(size_t)(k0 + i) * N + n0 + tx];
    __syncthreads();
    const int j = tid >> 3, kg = (tid & 7) << 2;
    __half h[4], l[4];
    #pragma unroll
    for (int p = 0; p < 4; ++p) {
        float v = tile[kg + p][j];
        h[p] = __float2half_rn(v);
        l[p] = __float2half_rn(v - __half2float(h[p]));
    }
    uint2 uh, ul; __half2 t;
    t = __halves2half2(h[0], h[1]); uh.x = *(unsigned*)&t;
    t = __halves2half2(h[2], h[3]); uh.y = *(unsigned*)&t;
    *(uint2*)&Th[(size_t)(n0 + j) * K + k0 + kg] = uh;
    if (Tl) {
        t = __halves2half2(l[0], l[1]); ul.x = *(unsigned*)&t;
        t = __halves2half2(l[2], l[3]); ul.y = *(unsigned*)&t;
        *(uint2*)&Tl[(size_t)(n0 + j) * K + k0 + kg] = ul;
    }
}

// ============ fp16 split GEMM, 64x128 tile: 3-term (QKV) or 1-term (proj) =======
#define AH_OFF  0
#define AL_OFF  8192
#define BH_OFF  16384
#define BL_OFF  32768
#define STAGE_SZ 49152
#define G2_SMEM  98304

__global__ __launch_bounds__(256) void hgemm2(
    const __half* __restrict__ Agh, const __half* __restrict__ Agl,
    const __half* __restrict__ Bgh, const __half* __restrict__ Bgl,
    float* __restrict__ C, int M, int N, int K,
    const float* __restrict__ bias, int do_absmax, int three)
{
    extern __shared__ char smraw[];
    const unsigned sb = smem_u32(smraw);
    const int tid = threadIdx.x, wid = tid >> 5, lane = tid & 31;
    const int g = lane >> 2, tig = lane & 3;
    const int m0 = blockIdx.y * 64, n0 = blockIdx.x * 128;
    const int wm = (wid & 1) * 32, wn = (wid >> 1) * 32;

    const int rsel = (lane & 7) | (((lane >> 3) & 1) << 3);
    const int ksel = (lane >> 4) << 3;
    const int brow = lane & 7;
    const int bm   = lane >> 3;

    float acc[2][4][4] = {};

    const int afr = tid >> 2, afg = (tid & 3) << 1;
    const int bfr = tid >> 1, bfg = (tid & 1) << 2;

    auto fill = [&](int stage, int k0) {
        unsigned base = sb + stage * STAGE_SZ;
        #pragma unroll
        for (int p = 0; p < 2; ++p) {
            unsigned d = SWZ((unsigned)(afr * 128 + (afg + p) * 16));
            cpa16(base + AH_OFF + d, Agh + (size_t)(m0 + afr) * K + k0 + (afg + p) * 8);
        }
        #pragma unroll
        for (int p = 0; p < 4; ++p) {
            unsigned d = SWZ((unsigned)(bfr * 128 + (bfg + p) * 16));
            cpa16(base + BH_OFF + d, Bgh + (size_t)(n0 + bfr) * K + k0 + (bfg + p) * 8);
        }
        if (three) {
            #pragma unroll
            for (int p = 0; p < 2; ++p) {
                unsigned d = SWZ((unsigned)(afr * 128 + (afg + p) * 16));
                cpa16(base + AL_OFF + d, Agl + (size_t)(m0 + afr) * K + k0 + (afg + p) * 8);
            }
            #pragma unroll
            for (int p = 0; p < 4; ++p) {
                unsigned d = SWZ((unsigned)(bfr * 128 + (bfg + p) * 16));
                cpa16(base + BL_OFF + d, Bgl + (size_t)(n0 + bfr) * K + k0 + (bfg + p) * 8);
            }
        }
        cpa_commit();
    };

    fill(0, 0);
    cpa_waitall(); __syncthreads();

    const int T = K >> 6;
    for (int t = 0; t < T; ++t) {
        const int stage = t & 1;
        if (t + 1 < T) fill(stage ^ 1, (t + 1) << 6);

        const char* base = smraw + stage * STAGE_SZ;
        const char* Ah = base + AH_OFF;
        const char* Al = base + AL_OFF;
        const char* Bh = base + BH_OFF;
        const char* Bl = base + BL_OFF;

        #pragma unroll
        for (int ks = 0; ks < 4; ++ks) {
            const int kb = ks * 16;
            unsigned ah[2][4], al[2][4], bh[4][2], bl[4][2];
            #pragma unroll
            for (int mi = 0; mi < 2; ++mi) {
                unsigned off = SWZ((unsigned)((wm + mi * 16 + rsel) * 128 + (kb + ksel) * 2));
                ldsm_x4(ah[mi], Ah + off);
                if (three) ldsm_x4(al[mi], Al + off);
            }
            #pragma unroll
            for (int np = 0; np < 2; ++np) {
                unsigned off = SWZ((unsigned)((wn + (np * 2 + (bm >> 1)) * 8 + brow) * 128
                                              + (kb + (bm & 1) * 8) * 2));
                unsigned r[4];
                ldsm_x4(r, Bh + off);
                bh[2 * np][0] = r[0]; bh[2 * np][1] = r[1];
                bh[2 * np + 1][0] = r[2]; bh[2 * np + 1][1] = r[3];
                if (three) {
                    ldsm_x4(r, Bl + off);
                    bl[2 * np][0] = r[0]; bl[2 * np][1] = r[1];
                    bl[2 * np + 1][0] = r[2]; bl[2 * np + 1][1] = r[3];
                }
            }
            #pragma unroll
            for (int mi = 0; mi < 2; ++mi)
                #pragma unroll
                for (int ni = 0; ni < 4; ++ni)
                    mma_f16(acc[mi][ni][0], acc[mi][ni][1], acc[mi][ni][2], acc[mi][ni][3],
                            ah[mi][0], ah[mi][1], ah[mi][2], ah[mi][3], bh[ni][0], bh[ni][1]);
            if (three) {
                #pragma unroll
                for (int mi = 0; mi < 2; ++mi)
                    #pragma unroll
                    for (int ni = 0; ni < 4; ++ni)
                        mma_f16(acc[mi][ni][0], acc[mi][ni][1], acc[mi][ni][2], acc[mi][ni][3],
                                ah[mi][0], ah[mi][1], ah[mi][2], ah[mi][3], bl[ni][0], bl[ni][1]);
                #pragma unroll
                for (int mi = 0; mi < 2; ++mi)
                    #pragma unroll
                    for (int ni = 0; ni < 4; ++ni)
                        mma_f16(acc[mi][ni][0], acc[mi][ni][1], acc[mi][ni][2], acc[mi][ni][3],
                                al[mi][0], al[mi][1], al[mi][2], al[mi][3], bh[ni][0], bh[ni][1]);
            }
        }

        if (t + 1 < T) { cpa_waitall(); __syncthreads(); }
    }

    float lmax = 0.0f;
    #pragma unroll
    for (int mi = 0; mi < 2; ++mi) {
        int r = m0 + wm + mi * 16 + g;
        #pragma unroll
        for (int ni = 0; ni < 4; ++ni) {
            int c = n0 + wn + ni * 8 + 2 * tig;
            float2 v0 = {acc[mi][ni][0], acc[mi][ni][1]};
            float2 v1 = {acc[mi][ni][2], acc[mi][ni][3]};
            if (bias) {
                float b0 = bias[c], b1 = bias[c + 1];
                v0.x += b0; v0.y += b1;
                v1.x += b0; v1.y += b1;
            }
            if (do_absmax) {
                lmax = fmaxf(lmax, fmaxf(fmaxf(fabsf(v0.x), fabsf(v0.y)),
                                         fmaxf(fabsf(v1.x), fabsf(v1.y))));
            }
            *(float2*)&C[(size_t)r * N + c] = v0;
            *(float2*)&C[(size_t)(r + 8) * N + c] = v1;
        }
    }
    if (do_absmax) {
        #pragma unroll
        for (int o = 16; o; o >>= 1)
            lmax = fmaxf(lmax, __shfl_xor_sync(0xffffffffu, lmax, o));
        if (lane == 0) atomicMax(&g_absmax[n0 >> 11], __float_as_uint(lmax));
    }
}

// ---------------- quant ----------------
__global__ void quant_kernel() {
    int i = blockIdx.x * blockDim.x + threadIdx.x;
    if (i >= 3 * PLANE / 4) return;
    int t   = i / (PLANE / 4);
    int rem = i - t * (PLANE / 4);
    int d4 = rem & 31;
    int s  = (rem >> 5) & 2047;
    int bh = rem >> 16;
    int b = bh >> 4, h = bh & 15;
    const float sc  = __uint_as_float(g_absmax[t]) / 448.0f;
    const float isc = 1.0f / sc;
    float4 v = *(const float4*)&g_qkv[(size_t)(b * S_ + s) * H3 + t * H_ + h * HD + d4 * 4];
    unsigned char q0 = __nv_cvt_float_to_fp8(v.x * isc, __NV_SATFINITE, __NV_E4M3);
    unsigned char q1 = __nv_cvt_float_to_fp8(v.y * isc, __NV_SATFINITE, __NV_E4M3);
    unsigned char q2 = __nv_cvt_float_to_fp8(v.z * isc, __NV_SATFINITE, __NV_E4M3);
    unsigned char q3 = __nv_cvt_float_to_fp8(v.w * isc, __NV_SATFINITE, __NV_E4M3);
    if (t < 2) {
        *(uchar4*)&g_q8[(size_t)t * PLANE + ((size_t)bh << 18) + (s << 7) + d4 * 4] =
            make_uchar4(q0, q1, q2, q3);
    } else {
        uint2 o;
        o.x = (unsigned)f8_to_h(q0) | ((unsigned)f8_to_h(q1) << 16);
        o.y = (unsigned)f8_to_h(q2) | ((unsigned)f8_to_h(q3) << 16);
        *(uint2*)&g_v16[((size_t)bh << 18) + (s << 7) + d4 * 4] = o;
    }
}

// ============ fused flash attention, 64-query tiles, 2 CTAs/SM ============
#define QB_OFF 0
#define KB_OFF 9216
#define VS_OFF 27648
#define PS_OFF 62464
#define RED_OFF 79872
#define FLASH_SMEM 80896

__global__ __launch_bounds__(256, 2) void flash_kernel() {
    extern __shared__ char smraw[];
    char* QB = smraw + QB_OFF;
    char* KB = smraw + KB_OFF;
    typedef __half HRow[136];
    HRow* Vs = (HRow*)(smraw + VS_OFF);
    HRow* Ps = (HRow*)(smraw + PS_OFF);
    float (*red)[64] = (float(*)[64])(smraw + RED_OFF);

    const int tid = threadIdx.x, lane = tid & 31, wid = tid >> 5;
    const int g = lane >> 2, tig = lane & 3;
    const int wm = (wid & 1) * 32, wn = (wid >> 1) * 32;
    const int wnid = wid >> 1;
    const int bh = blockIdx.y;
    const int b = bh >> 4, h = bh & 15;
    const int i0 = blockIdx.x * BQ;
    const unsigned char* qp = g_q8 + (size_t)bh * (S_ * HD);
    const unsigned char* kp = g_q8 + (size_t)PLANE + (size_t)bh * (S_ * HD);
    const __half* vp = g_v16 + (size_t)bh * (S_ * HD);
    const float f = (__uint_as_float(g_absmax[0]) / 448.0f)
                  * (__uint_as_float(g_absmax[1]) / 448.0f) * 0.08838834764831843f;

    const int rsel = (lane & 7) | (((lane >> 3) & 1) << 3);
    const int ksel = (lane >> 4) << 3;
    const int kselb = (lane >> 4) << 4;
    const int b8row = (lane & 7);
    const int b8sub = (lane >> 4);
    const int b8k   = ((lane >> 3) & 1) << 4;

    #pragma unroll
    for (int p = 0; p < 2; ++p) {
        int lin = tid + p * 256;
        int r = lin >> 3, c = (lin & 7) << 4;
        *(uint4*)(QB + r * 144 + c) = *(const uint4*)&qp[(size_t)(i0 + r) * HD + c];
    }

    float o[2][4][4] = {};
    float mrow[2][2], lrow[2][2];
    #pragma unroll
    for (int mi = 0; mi < 2; ++mi) {
        mrow[mi][0] = mrow[mi][1] = -1e30f;
        lrow[mi][0] = lrow[mi][1] = 0.0f;
    }

    for (int kt = 0; kt < S_ / 128; ++kt) {
        const unsigned char* kb8 = kp + (size_t)kt * 128 * HD;
        const __half* vb16 = vp + (size_t)kt * 128 * HD;
        #pragma unroll
        for (int p = 0; p < 4; ++p) {
            int lin = tid + p * 256;
            int r = lin >> 3, c = (lin & 7) << 4;
            *(uint4*)(KB + r * 144 + c) = *(const uint4*)&kb8[(size_t)r * HD + c];
        }
        #pragma unroll
        for (int p = 0; p < 8; ++p) {
            int lin = tid + p * 256;
            int r = lin >> 4, c = (lin & 15) << 3;
            *(uint4*)&Vs[r][c] = *(const uint4*)&vb16[(size_t)r * HD + c];
        }
        __syncthreads();

        float s[2][4][4] = {};
        #pragma unroll
        for (int ks = 0; ks < 4; ++ks) {
            const int kb = ks * 32;
            unsigned a[2][4], bb[4][2];
            #pragma unroll
            for (int mi = 0; mi < 2; ++mi)
                ldsm_x4(a[mi], QB + (wm + mi * 16 + rsel) * 144 + kb + kselb);
            #pragma unroll
            for (int np = 0; np < 2; ++np) {
                unsigned r[4];
                ldsm_x4(r, KB + (wn + (np * 2 + b8sub) * 8 + b8row) * 144 + kb + b8k);
                bb[2 * np][0] = r[0]; bb[2 * np][1] = r[1];
                bb[2 * np + 1][0] = r[2]; bb[2 * np + 1][1] = r[3];
            }
            #pragma unroll
            for (int mi = 0; mi < 2; ++mi)
                #pragma unroll
                for (int ni = 0; ni < 4; ++ni)
                    mma_f8(s[mi][ni][0], s[mi][ni][1], s[mi][ni][2], s[mi][ni][3],
                           a[mi][0], a[mi][1], a[mi][2], a[mi][3], bb[ni][0], bb[ni][1]);
        }
        #pragma unroll
        for (int mi = 0; mi < 2; ++mi)
            #pragma unroll
            for (int ni = 0; ni < 4; ++ni)
                #pragma unroll
                for (int j = 0; j < 4; ++j)
                    s[mi][ni][j] *= f;

        float tmax[2][2];
        #pragma unroll
        for (int mi = 0; mi < 2; ++mi) {
            float h0 = -1e30f, h1 = -1e30f;
            #pragma unroll
            for (int ni = 0; ni < 4; ++ni) {
                h0 = fmaxf(h0, fmaxf(s[mi][ni][0], s[mi][ni][1]));
                h1 = fmaxf(h1, fmaxf(s[mi][ni][2], s[mi][ni][3]));
            }
            tmax[mi][0] = h0; tmax[mi][1] = h1;
        }
        #pragma unroll
        for (int off = 1; off <= 2; off <<= 1)
            #pragma unroll
            for (int mi = 0; mi < 2; ++mi) {
                tmax[mi][0] = fmaxf(tmax[mi][0], __shfl_xor_sync(0xffffffffu, tmax[mi][0], off));
                tmax[mi][1] = fmaxf(tmax[mi][1], __shfl_xor_sync(0xffffffffu, tmax[mi][1], off));
            }
        if (tig == 0) {
            #pragma unroll
            for (int mi = 0; mi < 2; ++mi) {
                red[wnid][wm + mi * 16 + g]     = tmax[mi][0];
                red[wnid][wm + mi * 16 + g + 8] = tmax[mi][1];
            }
        }
        __syncthreads();

        #pragma unroll
        for (int mi = 0; mi < 2; ++mi) {
            #pragma unroll
            for (int hh = 0; hh < 2; ++hh) {
                int row = wm + mi * 16 + g + hh * 8;
                float rm = fmaxf(fmaxf(red[0][row], red[1][row]),
                                 fmaxf(red[2][row], red[3][row]));
                float mnew = fmaxf(mrow[mi][hh], rm);
                float rs = __expf(mrow[mi][hh] - mnew);
                mrow[mi][hh] = mnew;
                lrow[mi][hh] *= rs;
                #pragma unroll
                for (int ni = 0; ni < 4; ++ni) {
                    o[mi][ni][2 * hh]     *= rs;
                    o[mi][ni][2 * hh + 1] *= rs;
                }
            }
            #pragma unroll
            for (int ni = 0; ni < 4; ++ni) {
                float p0 = __expf(s[mi][ni][0] - mrow[mi][0]);
                float p1 = __expf(s[mi][ni][1] - mrow[mi][0]);
                float p2 = __expf(s[mi][ni][2] - mrow[mi][1]);
                float p3 = __expf(s[mi][ni][3] - mrow[mi][1]);
                lrow[mi][0] += p0 + p1;
                lrow[mi][1] += p2 + p3;
                int c = wn + ni * 8 + 2 * tig;
                *(__half2*)&Ps[wm + mi * 16 + g][c]     = __floats2half2_rn(p0, p1);
                *(__half2*)&Ps[wm + mi * 16 + g + 8][c] = __floats2half2_rn(p2, p3);
            }
        }
        __syncthreads();

        #pragma unroll
        for (int ks = 0; ks < 8; ++ks) {
            const int kb = ks * 16;
            unsigned a[2][4], bb[4][2];
            #pragma unroll
            for (int mi = 0; mi < 2; ++mi)
                ldsm_x4(a[mi], &Ps[wm + mi * 16 + rsel][kb + ksel]);
            #pragma unroll
            for (int ni = 0; ni < 4; ++ni)
                ldsm_x2_trans(bb[ni][0], bb[ni][1], &Vs[kb + (lane & 15)][wn + ni * 8]);
            #pragma unroll
            for (int mi = 0; mi < 2; ++mi)
                #pragma unroll
                for (int ni = 0; ni < 4; ++ni)
                    mma_f16(o[mi][ni][0], o[mi][ni][1], o[mi][ni][2], o[mi][ni][3],
                            a[mi][0], a[mi][1], a[mi][2], a[mi][3], bb[ni][0], bb[ni][1]);
        }
        __syncthreads();
    }

    #pragma unroll
    for (int off = 1; off <= 2; off <<= 1)
        #pragma unroll
        for (int mi = 0; mi < 2; ++mi) {
            lrow[mi][0] += __shfl_xor_sync(0xffffffffu, lrow[mi][0], off);
            lrow[mi][1] += __shfl_xor_sync(0xffffffffu, lrow[mi][1], off);
        }
    if (tig == 0) {
        #pragma unroll
        for (int mi = 0; mi < 2; ++mi) {
            red[wnid][wm + mi * 16 + g]     = lrow[mi][0];
            red[wnid][wm + mi * 16 + g + 8] = lrow[mi][1];
        }
    }
    __syncthreads();

    const float vsc = __uint_as_float(g_absmax[2]) / 448.0f;
    #pragma unroll
    for (int mi = 0; mi < 2; ++mi) {
        #pragma unroll
        for (int hh = 0; hh < 2; ++hh) {
            int row = wm + mi * 16 + g + hh * 8;
            float lt = red[0][row] + red[1][row] + red[2][row] + red[3][row];
            float inv = vsc / lt;
            int srow = i0 + row;
            #pragma unroll
            for (int ni = 0; ni < 4; ++ni) {
                int d = wn + ni * 8 + 2 * tig;
                __half2 hv = __floats2half2_rn(o[mi][ni][2 * hh] * inv,
                                               o[mi][ni][2 * hh + 1] * inv);
                *(__half2*)&g_aoh[(size_t)(b * S_ + srow) * H_ + h * HD + d] = hv;
            }
        }
    }
}

// ---------------- launch ----------------
extern "C" void kernel_launch(void* const* d_in, const int* in_sizes, int n_in,
                              void* d_out, int out_size)
{
    const float* x    = (const float*)d_in[0];
    const float* Wqkv = (const float*)d_in[1];
    const float* Wout = (const float*)d_in[2];
    const float* bout = (const float*)d_in[3];
    float* y = (float*)d_out;

    float* qkv_ptr = nullptr;
    __half *xh, *xl, *wqh, *wql, *woh, *aoh;
    cudaGetSymbolAddress((void**)&qkv_ptr, g_qkv);
    cudaGetSymbolAddress((void**)&xh, g_xh);   cudaGetSymbolAddress((void**)&xl, g_xl);
    cudaGetSymbolAddress((void**)&wqh, g_wqh); cudaGetSymbolAddress((void**)&wql, g_wql);
    cudaGetSymbolAddress((void**)&woh, g_woh);
    cudaGetSymbolAddress((void**)&aoh, g_aoh);

    static int attr_set = 0;
    if (!attr_set) {
        cudaFuncSetAttribute(flash_kernel,
                             cudaFuncAttributeMaxDynamicSharedMemorySize, FLASH_SMEM);
        cudaFuncSetAttribute(hgemm2,
                             cudaFuncAttributeMaxDynamicSharedMemorySize, G2_SMEM);
        attr_set = 1;
    }

    // 0) merged prep
    prep_kernel<<<NB_SPLIT + NB_TSQ + NB_TSO, 256>>>(x, Wqkv, Wout);

    // 1) qkv = x @ W_qkv  (fp16x3, 64x128 tiles, absmax fused)
    hgemm2<<<dim3(H3 / 128, M1 / 64), 256, G2_SMEM>>>(
        xh, xl, wqh, wql, qkv_ptr, M1, H3, H_, nullptr, 1, 1);

    // 2-3) quantize
    quant_kernel<<<(3 * PLANE / 4 + 255) / 256, 256>>>();

    // 4-6) fused flash attention (64-query tiles, 2 CTAs/SM)
    flash_kernel<<<dim3(S_ / BQ, B_ * NH), 256, FLASH_SMEM>>>();

    // 7) y = attnout @ W_out + b_out  (fp16x1)
    hgemm2<<<dim3(H_ / 128, M1 / 64), 256, G2_SMEM>>>(
        aoh, nullptr, woh, nullptr, y, M1, H_, H_, bout, 0, 0);
}

// round 17
// speedup vs baseline: 5.2682x; 1.0039x over previous
#include <cuda_runtime.h>
#include <cuda_fp16.h>
#include <cuda_fp8.h>
#include <math.h>

// ---------------- problem constants ----------------
#define B_   2
#define S_   2048
#define H_   2048
#define NH   16
#define HD   128
#define H3   (3 * H_)
#define M1   (B_ * S_)
#define PLANE (B_ * NH * S_ * HD)
#define BQ   64

// ---------------- scratch ----------------
__device__ float         g_qkv[(size_t)M1 * H3];
__device__ unsigned char g_q8[(size_t)2 * PLANE];
__device__ __half        g_v16[(size_t)PLANE];
__device__ unsigned int  g_absmax[3];
__device__ __half        g_xh[(size_t)M1 * H_],  g_xl[(size_t)M1 * H_];
__device__ __half        g_wqh[(size_t)H3 * H_], g_wql[(size_t)H3 * H_];
__device__ __half        g_woh[(size_t)H_ * H_];
__device__ __half        g_aoh[(size_t)M1 * H_];

// ---------------- helpers ----------------
__device__ __forceinline__ unsigned short f8_to_h(unsigned char v) {
    __half_raw hr = __nv_cvt_fp8_to_halfraw(v, __NV_E4M3);
    return hr.x;
}

__device__ __forceinline__ void mma_f16(float& d0, float& d1, float& d2, float& d3,
                                        unsigned a0, unsigned a1, unsigned a2, unsigned a3,
                                        unsigned b0, unsigned b1) {
    asm volatile("mma.sync.aligned.m16n8k16.row.col.f32.f16.f16.f32 "
                 "{%0,%1,%2,%3}, {%4,%5,%6,%7}, {%8,%9}, {%0,%1,%2,%3};"
                 : "+f"(d0), "+f"(d1), "+f"(d2), "+f"(d3)
                 : "r"(a0), "r"(a1), "r"(a2), "r"(a3), "r"(b0), "r"(b1));
}
__device__ __forceinline__ void mma_f8(float& d0, float& d1, float& d2, float& d3,
                                       unsigned a0, unsigned a1, unsigned a2, unsigned a3,
                                       unsigned b0, unsigned b1) {
    asm volatile("mma.sync.aligned.m16n8k32.row.col.f32.e4m3.e4m3.f32 "
                 "{%0,%1,%2,%3}, {%4,%5,%6,%7}, {%8,%9}, {%0,%1,%2,%3};"
                 : "+f"(d0), "+f"(d1), "+f"(d2), "+f"(d3)
                 : "r"(a0), "r"(a1), "r"(a2), "r"(a3), "r"(b0), "r"(b1));
}
__device__ __forceinline__ void ldsm_x4_trans(unsigned* r, const void* p) {
    unsigned addr = (unsigned)__cvta_generic_to_shared(p);
    asm volatile("ldmatrix.sync.aligned.m8n8.x4.trans.shared.b16 {%0,%1,%2,%3}, [%4];"
                 : "=r"(r[0]), "=r"(r[1]), "=r"(r[2]), "=r"(r[3]) : "r"(addr));
}
__device__ __forceinline__ void ldsm_x4(unsigned* r, const void* p) {
    unsigned addr = (unsigned)__cvta_generic_to_shared(p);
    asm volatile("ldmatrix.sync.aligned.m8n8.x4.shared.b16 {%0,%1,%2,%3}, [%4];"
                 : "=r"(r[0]), "=r"(r[1]), "=r"(r[2]), "=r"(r[3]) : "r"(addr));
}

#define SWZ(x) ((x) ^ (((x) >> 3) & 0x70))

__device__ __forceinline__ unsigned smem_u32(const void* p) {
    return (unsigned)__cvta_generic_to_shared(p);
}
__device__ __forceinline__ void cpa16(unsigned dst, const void* src) {
    asm volatile("cp.async.cg.shared.global [%0], [%1], 16;" :: "r"(dst), "l"(src));
}
__device__ __forceinline__ void cpa_commit() { asm volatile("cp.async.commit_group;" ::: "memory"); }
__device__ __forceinline__ void cpa_waitall() { asm volatile("cp.async.wait_group 0;" ::: "memory"); }

// ============ merged prep ============
#define NB_SPLIT 8192
#define NB_TSQ   12288
#define NB_TSO   4096

__global__ void prep_kernel(const float* __restrict__ x,
                            const float* __restrict__ Wqkv,
                            const float* __restrict__ Wout) {
    __shared__ float tile[32][33];
    const int b = blockIdx.x;
    const int tid = threadIdx.x;
    if (b == 0 && tid < 3) g_absmax[tid] = 0u;

    if (b < NB_SPLIT) {
        int i = b * 256 + tid;
        float4 v = ((const float4*)x)[i];
        float vv[4] = {v.x, v.y, v.z, v.w};
        __half h[4], l[4];
        #pragma unroll
        for (int j = 0; j < 4; ++j) {
            h[j] = __float2half_rn(vv[j]);
            l[j] = __float2half_rn(vv[j] - __half2float(h[j]));
        }
        ((__half2*)g_xh)[i * 2]     = __halves2half2(h[0], h[1]);
        ((__half2*)g_xh)[i * 2 + 1] = __halves2half2(h[2], h[3]);
        ((__half2*)g_xl)[i * 2]     = __halves2half2(l[0], l[1]);
        ((__half2*)g_xl)[i * 2 + 1] = __halves2half2(l[2], l[3]);
        return;
    }

    const float* W;
    __half *Th, *Tl;
    int K, N, n0, k0;
    if (b < NB_SPLIT + NB_TSQ) {
        int bb = b - NB_SPLIT;
        W = Wqkv; Th = g_wqh; Tl = g_wql;
        K = H_; N = H3;
        n0 = (bb % (H3 / 32)) * 32; k0 = (bb / (H3 / 32)) * 32;
    } else {
        int bb = b - NB_SPLIT - NB_TSQ;
        W = Wout; Th = g_woh; Tl = nullptr;
        K = H_; N = H_;
        n0 = (bb % (H_ / 32)) * 32; k0 = (bb / (H_ / 32)) * 32;
    }
    const int tx = tid & 31, ty = tid >> 5;
    #pragma unroll
    for (int i = ty; i < 32; i += 8)
        tile[i][tx] = W[(size_t)(k0 + i) * N + n0 + tx];
    __syncthreads();
    const int j = tid >> 3, kg = (tid & 7) << 2;
    __half h[4], l[4];
    #pragma unroll
    for (int p = 0; p < 4; ++p) {
        float v = tile[kg + p][j];
        h[p] = __float2half_rn(v);
        l[p] = __float2half_rn(v - __half2float(h[p]));
    }
    uint2 uh, ul; __half2 t;
    t = __halves2half2(h[0], h[1]); uh.x = *(unsigned*)&t;
    t = __halves2half2(h[2], h[3]); uh.y = *(unsigned*)&t;
    *(uint2*)&Th[(size_t)(n0 + j) * K + k0 + kg] = uh;
    if (Tl) {
        t = __halves2half2(l[0], l[1]); ul.x = *(unsigned*)&t;
        t = __halves2half2(l[2], l[3]); ul.y = *(unsigned*)&t;
        *(uint2*)&Tl[(size_t)(n0 + j) * K + k0 + kg] = ul;
    }
}

// ============ fp16 split GEMM, 64x128 tile ============
#define AH_OFF  0
#define AL_OFF  8192
#define BH_OFF  16384
#define BL_OFF  32768
#define STAGE_SZ 49152
#define G2_SMEM  98304

__global__ __launch_bounds__(256) void hgemm2(
    const __half* __restrict__ Agh, const __half* __restrict__ Agl,
    const __half* __restrict__ Bgh, const __half* __restrict__ Bgl,
    float* __restrict__ C, int M, int N, int K,
    const float* __restrict__ bias, int do_absmax, int three)
{
    extern __shared__ char smraw[];
    const unsigned sb = smem_u32(smraw);
    const int tid = threadIdx.x, wid = tid >> 5, lane = tid & 31;
    const int g = lane >> 2, tig = lane & 3;
    const int m0 = blockIdx.y * 64, n0 = blockIdx.x * 128;
    const int wm = (wid & 1) * 32, wn = (wid >> 1) * 32;

    const int rsel = (lane & 7) | (((lane >> 3) & 1) << 3);
    const int ksel = (lane >> 4) << 3;
    const int brow = lane & 7;
    const int bm   = lane >> 3;

    float acc[2][4][4] = {};

    const int afr = tid >> 2, afg = (tid & 3) << 1;
    const int bfr = tid >> 1, bfg = (tid & 1) << 2;

    auto fill = [&](int stage, int k0) {
        unsigned base = sb + stage * STAGE_SZ;
        #pragma unroll
        for (int p = 0; p < 2; ++p) {
            unsigned d = SWZ((unsigned)(afr * 128 + (afg + p) * 16));
            cpa16(base + AH_OFF + d, Agh + (size_t)(m0 + afr) * K + k0 + (afg + p) * 8);
        }
        #pragma unroll
        for (int p = 0; p < 4; ++p) {
            unsigned d = SWZ((unsigned)(bfr * 128 + (bfg + p) * 16));
            cpa16(base + BH_OFF + d, Bgh + (size_t)(n0 + bfr) * K + k0 + (bfg + p) * 8);
        }
        if (three) {
            #pragma unroll
            for (int p = 0; p < 2; ++p) {
                unsigned d = SWZ((unsigned)(afr * 128 + (afg + p) * 16));
                cpa16(base + AL_OFF + d, Agl + (size_t)(m0 + afr) * K + k0 + (afg + p) * 8);
            }
            #pragma unroll
            for (int p = 0; p < 4; ++p) {
                unsigned d = SWZ((unsigned)(bfr * 128 + (bfg + p) * 16));
                cpa16(base + BL_OFF + d, Bgl + (size_t)(n0 + bfr) * K + k0 + (bfg + p) * 8);
            }
        }
        cpa_commit();
    };

    fill(0, 0);
    cpa_waitall(); __syncthreads();

    const int T = K >> 6;
    for (int t = 0; t < T; ++t) {
        const int stage = t & 1;
        if (t + 1 < T) fill(stage ^ 1, (t + 1) << 6);

        const char* base = smraw + stage * STAGE_SZ;
        const char* Ah = base + AH_OFF;
        const char* Al = base + AL_OFF;
        const char* Bh = base + BH_OFF;
        const char* Bl = base + BL_OFF;

        #pragma unroll
        for (int ks = 0; ks < 4; ++ks) {
            const int kb = ks * 16;
            unsigned ah[2][4], al[2][4], bh[4][2], bl[4][2];
            #pragma unroll
            for (int mi = 0; mi < 2; ++mi) {
                unsigned off = SWZ((unsigned)((wm + mi * 16 + rsel) * 128 + (kb + ksel) * 2));
                ldsm_x4(ah[mi], Ah + off);
                if (three) ldsm_x4(al[mi], Al + off);
            }
            #pragma unroll
            for (int np = 0; np < 2; ++np) {
                unsigned off = SWZ((unsigned)((wn + (np * 2 + (bm >> 1)) * 8 + brow) * 128
                                              + (kb + (bm & 1) * 8) * 2));
                unsigned r[4];
                ldsm_x4(r, Bh + off);
                bh[2 * np][0] = r[0]; bh[2 * np][1] = r[1];
                bh[2 * np + 1][0] = r[2]; bh[2 * np + 1][1] = r[3];
                if (three) {
                    ldsm_x4(r, Bl + off);
                    bl[2 * np][0] = r[0]; bl[2 * np][1] = r[1];
                    bl[2 * np + 1][0] = r[2]; bl[2 * np + 1][1] = r[3];
                }
            }
            #pragma unroll
            for (int mi = 0; mi < 2; ++mi)
                #pragma unroll
                for (int ni = 0; ni < 4; ++ni)
                    mma_f16(acc[mi][ni][0], acc[mi][ni][1], acc[mi][ni][2], acc[mi][ni][3],
                            ah[mi][0], ah[mi][1], ah[mi][2], ah[mi][3], bh[ni][0], bh[ni][1]);
            if (three) {
                #pragma unroll
                for (int mi = 0; mi < 2; ++mi)
                    #pragma unroll
                    for (int ni = 0; ni < 4; ++ni)
                        mma_f16(acc[mi][ni][0], acc[mi][ni][1], acc[mi][ni][2], acc[mi][ni][3],
                                ah[mi][0], ah[mi][1], ah[mi][2], ah[mi][3], bl[ni][0], bl[ni][1]);
                #pragma unroll
                for (int mi = 0; mi < 2; ++mi)
                    #pragma unroll
                    for (int ni = 0; ni < 4; ++ni)
                        mma_f16(acc[mi][ni][0], acc[mi][ni][1], acc[mi][ni][2], acc[mi][ni][3],
                                al[mi][0], al[mi][1], al[mi][2], al[mi][3], bh[ni][0], bh[ni][1]);
            }
        }

        if (t + 1 < T) { cpa_waitall(); __syncthreads(); }
    }

    float lmax = 0.0f;
    #pragma unroll
    for (int mi = 0; mi < 2; ++mi) {
        int r = m0 + wm + mi * 16 + g;
        #pragma unroll
        for (int ni = 0; ni < 4; ++ni) {
            int c = n0 + wn + ni * 8 + 2 * tig;
            float2 v0 = {acc[mi][ni][0], acc[mi][ni][1]};
            float2 v1 = {acc[mi][ni][2], acc[mi][ni][3]};
            if (bias) {
                float b0 = bias[c], b1 = bias[c + 1];
                v0.x += b0; v0.y += b1;
                v1.x += b0; v1.y += b1;
            }
            if (do_absmax) {
                lmax = fmaxf(lmax, fmaxf(fmaxf(fabsf(v0.x), fabsf(v0.y)),
                                         fmaxf(fabsf(v1.x), fabsf(v1.y))));
            }
            *(float2*)&C[(size_t)r * N + c] = v0;
            *(float2*)&C[(size_t)(r + 8) * N + c] = v1;
        }
    }
    if (do_absmax) {
        #pragma unroll
        for (int o = 16; o; o >>= 1)
            lmax = fmaxf(lmax, __shfl_xor_sync(0xffffffffu, lmax, o));
        if (lane == 0) atomicMax(&g_absmax[n0 >> 11], __float_as_uint(lmax));
    }
}

// ---------------- quant ----------------
__global__ void quant_kernel() {
    int i = blockIdx.x * blockDim.x + threadIdx.x;
    if (i >= 3 * PLANE / 4) return;
    int t   = i / (PLANE / 4);
    int rem = i - t * (PLANE / 4);
    int d4 = rem & 31;
    int s  = (rem >> 5) & 2047;
    int bh = rem >> 16;
    int b = bh >> 4, h = bh & 15;
    const float sc  = __uint_as_float(g_absmax[t]) / 448.0f;
    const float isc = 1.0f / sc;
    float4 v = *(const float4*)&g_qkv[(size_t)(b * S_ + s) * H3 + t * H_ + h * HD + d4 * 4];
    unsigned char q0 = __nv_cvt_float_to_fp8(v.x * isc, __NV_SATFINITE, __NV_E4M3);
    unsigned char q1 = __nv_cvt_float_to_fp8(v.y * isc, __NV_SATFINITE, __NV_E4M3);
    unsigned char q2 = __nv_cvt_float_to_fp8(v.z * isc, __NV_SATFINITE, __NV_E4M3);
    unsigned char q3 = __nv_cvt_float_to_fp8(v.w * isc, __NV_SATFINITE, __NV_E4M3);
    if (t < 2) {
        *(uchar4*)&g_q8[(size_t)t * PLANE + ((size_t)bh << 18) + (s << 7) + d4 * 4] =
            make_uchar4(q0, q1, q2, q3);
    } else {
        uint2 o;
        o.x = (unsigned)f8_to_h(q0) | ((unsigned)f8_to_h(q1) << 16);
        o.y = (unsigned)f8_to_h(q2) | ((unsigned)f8_to_h(q3) << 16);
        *(uint2*)&g_v16[((size_t)bh << 18) + (s << 7) + d4 * 4] = o;
    }
}

// ============ fused flash attention, 64-query tiles, 2 CTAs/SM ============
#define QB_OFF 0
#define KB_OFF 9216
#define VS_OFF 27648
#define PS_OFF 62464
#define RED_OFF 79872
#define FLASH_SMEM 80896

__global__ __launch_bounds__(256, 2) void flash_kernel() {
    extern __shared__ char smraw[];
    char* QB = smraw + QB_OFF;
    char* KB = smraw + KB_OFF;
    typedef __half HRow[136];
    HRow* Vs = (HRow*)(smraw + VS_OFF);
    HRow* Ps = (HRow*)(smraw + PS_OFF);
    float (*red)[64] = (float(*)[64])(smraw + RED_OFF);

    const int tid = threadIdx.x, lane = tid & 31, wid = tid >> 5;
    const int g = lane >> 2, tig = lane & 3;
    const int wm = (wid & 1) * 32, wn = (wid >> 1) * 32;
    const int wnid = wid >> 1;
    const int bh = blockIdx.y;
    const int b = bh >> 4, h = bh & 15;
    const int i0 = blockIdx.x * BQ;
    const unsigned char* qp = g_q8 + (size_t)bh * (S_ * HD);
    const unsigned char* kp = g_q8 + (size_t)PLANE + (size_t)bh * (S_ * HD);
    const __half* vp = g_v16 + (size_t)bh * (S_ * HD);
    const float f = (__uint_as_float(g_absmax[0]) / 448.0f)
                  * (__uint_as_float(g_absmax[1]) / 448.0f) * 0.08838834764831843f;

    const int rsel = (lane & 7) | (((lane >> 3) & 1) << 3);
    const int ksel = (lane >> 4) << 3;
    const int kselb = (lane >> 4) << 4;
    const int b8row = (lane & 7);
    const int b8sub = (lane >> 4);
    const int b8k   = ((lane >> 3) & 1) << 4;
    const int vm = lane >> 3, vr = lane & 7;   // V x4-trans lane mapping

    #pragma unroll
    for (int p = 0; p < 2; ++p) {
        int lin = tid + p * 256;
        int r = lin >> 3, c = (lin & 7) << 4;
        *(uint4*)(QB + r * 144 + c) = *(const uint4*)&qp[(size_t)(i0 + r) * HD + c];
    }

    float o[2][4][4] = {};
    float mrow[2][2], lrow[2][2];
    #pragma unroll
    for (int mi = 0; mi < 2; ++mi) {
        mrow[mi][0] = mrow[mi][1] = -1e30f;
        lrow[mi][0] = lrow[mi][1] = 0.0f;
    }

    for (int kt = 0; kt < S_ / 128; ++kt) {
        const unsigned char* kb8 = kp + (size_t)kt * 128 * HD;
        const __half* vb16 = vp + (size_t)kt * 128 * HD;
        #pragma unroll
        for (int p = 0; p < 4; ++p) {
            int lin = tid + p * 256;
            int r = lin >> 3, c = (lin & 7) << 4;
            *(uint4*)(KB + r * 144 + c) = *(const uint4*)&kb8[(size_t)r * HD + c];
        }
        #pragma unroll
        for (int p = 0; p < 8; ++p) {
            int lin = tid + p * 256;
            int r = lin >> 4, c = (lin & 15) << 3;
            *(uint4*)&Vs[r][c] = *(const uint4*)&vb16[(size_t)r * HD + c];
        }
        __syncthreads();

        // S = Q @ K^T (fp8), raw (unscaled) scores
        float s[2][4][4] = {};
        #pragma unroll
        for (int ks = 0; ks < 4; ++ks) {
            const int kb = ks * 32;
            unsigned a[2][4], bb[4][2];
            #pragma unroll
            for (int mi = 0; mi < 2; ++mi)
                ldsm_x4(a[mi], QB + (wm + mi * 16 + rsel) * 144 + kb + kselb);
            #pragma unroll
            for (int np = 0; np < 2; ++np) {
                unsigned r[4];
                ldsm_x4(r, KB + (wn + (np * 2 + b8sub) * 8 + b8row) * 144 + kb + b8k);
                bb[2 * np][0] = r[0]; bb[2 * np][1] = r[1];
                bb[2 * np + 1][0] = r[2]; bb[2 * np + 1][1] = r[3];
            }
            #pragma unroll
            for (int mi = 0; mi < 2; ++mi)
                #pragma unroll
                for (int ni = 0; ni < 4; ++ni)
                    mma_f8(s[mi][ni][0], s[mi][ni][1], s[mi][ni][2], s[mi][ni][3],
                           a[mi][0], a[mi][1], a[mi][2], a[mi][3], bb[ni][0], bb[ni][1]);
        }

        // row max over raw scores (f > 0 so order is preserved)
        float tmax[2][2];
        #pragma unroll
        for (int mi = 0; mi < 2; ++mi) {
            float h0 = -1e30f, h1 = -1e30f;
            #pragma unroll
            for (int ni = 0; ni < 4; ++ni) {
                h0 = fmaxf(h0, fmaxf(s[mi][ni][0], s[mi][ni][1]));
                h1 = fmaxf(h1, fmaxf(s[mi][ni][2], s[mi][ni][3]));
            }
            tmax[mi][0] = h0; tmax[mi][1] = h1;
        }
        #pragma unroll
        for (int off = 1; off <= 2; off <<= 1)
            #pragma unroll
            for (int mi = 0; mi < 2; ++mi) {
                tmax[mi][0] = fmaxf(tmax[mi][0], __shfl_xor_sync(0xffffffffu, tmax[mi][0], off));
                tmax[mi][1] = fmaxf(tmax[mi][1], __shfl_xor_sync(0xffffffffu, tmax[mi][1], off));
            }
        if (tig == 0) {
            #pragma unroll
            for (int mi = 0; mi < 2; ++mi) {
                red[wnid][wm + mi * 16 + g]     = tmax[mi][0];
                red[wnid][wm + mi * 16 + g + 8] = tmax[mi][1];
            }
        }
        __syncthreads();

        // online softmax update with scale folded into exp
        #pragma unroll
        for (int mi = 0; mi < 2; ++mi) {
            #pragma unroll
            for (int hh = 0; hh < 2; ++hh) {
                int row = wm + mi * 16 + g + hh * 8;
                float rm = fmaxf(fmaxf(red[0][row], red[1][row]),
                                 fmaxf(red[2][row], red[3][row]));
                float mnew = fmaxf(mrow[mi][hh], rm);
                float rs = __expf((mrow[mi][hh] - mnew) * f);
                mrow[mi][hh] = mnew;
                lrow[mi][hh] *= rs;
                #pragma unroll
                for (int ni = 0; ni < 4; ++ni) {
                    o[mi][ni][2 * hh]     *= rs;
                    o[mi][ni][2 * hh + 1] *= rs;
                }
            }
            #pragma unroll
            for (int ni = 0; ni < 4; ++ni) {
                float p0 = __expf((s[mi][ni][0] - mrow[mi][0]) * f);
                float p1 = __expf((s[mi][ni][1] - mrow[mi][0]) * f);
                float p2 = __expf((s[mi][ni][2] - mrow[mi][1]) * f);
                float p3 = __expf((s[mi][ni][3] - mrow[mi][1]) * f);
                lrow[mi][0] += p0 + p1;
                lrow[mi][1] += p2 + p3;
                int c = wn + ni * 8 + 2 * tig;
                *(__half2*)&Ps[wm + mi * 16 + g][c]     = __floats2half2_rn(p0, p1);
                *(__half2*)&Ps[wm + mi * 16 + g + 8][c] = __floats2half2_rn(p2, p3);
            }
        }
        __syncthreads();

        // O += P @ V (V B-frags via single ldmatrix.x4.trans per ni-pair)
        #pragma unroll
        for (int ks = 0; ks < 8; ++ks) {
            const int kb = ks * 16;
            unsigned a[2][4], bb[4][2];
            #pragma unroll
            for (int mi = 0; mi < 2; ++mi)
                ldsm_x4(a[mi], &Ps[wm + mi * 16 + rsel][kb + ksel]);
            #pragma unroll
            for (int np = 0; np < 2; ++np) {
                unsigned r[4];
                ldsm_x4_trans(r, &Vs[kb + (vm & 1) * 8 + vr][wn + np * 16 + (vm >> 1) * 8]);
                bb[2 * np][0] = r[0]; bb[2 * np][1] = r[1];
                bb[2 * np + 1][0] = r[2]; bb[2 * np + 1][1] = r[3];
            }
            #pragma unroll
            for (int mi = 0; mi < 2; ++mi)
                #pragma unroll
                for (int ni = 0; ni < 4; ++ni)
                    mma_f16(o[mi][ni][0], o[mi][ni][1], o[mi][ni][2], o[mi][ni][3],
                            a[mi][0], a[mi][1], a[mi][2], a[mi][3], bb[ni][0], bb[ni][1]);
        }
        __syncthreads();
    }

    // epilogue
    #pragma unroll
    for (int off = 1; off <= 2; off <<= 1)
        #pragma unroll
        for (int mi = 0; mi < 2; ++mi) {
            lrow[mi][0] += __shfl_xor_sync(0xffffffffu, lrow[mi][0], off);
            lrow[mi][1] += __shfl_xor_sync(0xffffffffu, lrow[mi][1], off);
        }
    if (tig == 0) {
        #pragma unroll
        for (int mi = 0; mi < 2; ++mi) {
            red[wnid][wm + mi * 16 + g]     = lrow[mi][0];
            red[wnid][wm + mi * 16 + g + 8] = lrow[mi][1];
        }
    }
    __syncthreads();

    const float vsc = __uint_as_float(g_absmax[2]) / 448.0f;
    #pragma unroll
    for (int mi = 0; mi < 2; ++mi) {
        #pragma unroll
        for (int hh = 0; hh < 2; ++hh) {
            int row = wm + mi * 16 + g + hh * 8;
            float lt = red[0][row] + red[1][row] + red[2][row] + red[3][row];
            float inv = vsc / lt;
            int srow = i0 + row;
            #pragma unroll
            for (int ni = 0; ni < 4; ++ni) {
                int d = wn + ni * 8 + 2 * tig;
                __half2 hv = __floats2half2_rn(o[mi][ni][2 * hh] * inv,
                                               o[mi][ni][2 * hh + 1] * inv);
                *(__half2*)&g_aoh[(size_t)(b * S_ + srow) * H_ + h * HD + d] = hv;
            }
        }
    }
}

// ---------------- launch ----------------
extern "C" void kernel_launch(void* const* d_in, const int* in_sizes, int n_in,
                              void* d_out, int out_size)
{
    const float* x    = (const float*)d_in[0];
    const float* Wqkv = (const float*)d_in[1];
    const float* Wout = (const float*)d_in[2];
    const float* bout = (const float*)d_in[3];
    float* y = (float*)d_out;

    float* qkv_ptr = nullptr;
    __half *xh, *xl, *wqh, *wql, *woh, *aoh;
    cudaGetSymbolAddress((void**)&qkv_ptr, g_qkv);
    cudaGetSymbolAddress((void**)&xh, g_xh);   cudaGetSymbolAddress((void**)&xl, g_xl);
    cudaGetSymbolAddress((void**)&wqh, g_wqh); cudaGetSymbolAddress((void**)&wql, g_wql);
    cudaGetSymbolAddress((void**)&woh, g_woh);
    cudaGetSymbolAddress((void**)&aoh, g_aoh);

    static int attr_set = 0;
    if (!attr_set) {
        cudaFuncSetAttribute(flash_kernel,
                             cudaFuncAttributeMaxDynamicSharedMemorySize, FLASH_SMEM);
        cudaFuncSetAttribute(hgemm2,
                             cudaFuncAttributeMaxDynamicSharedMemorySize, G2_SMEM);
        attr_set = 1;
    }

    // 0) merged prep
    prep_kernel<<<NB_SPLIT + NB_TSQ + NB_TSO, 256>>>(x, Wqkv, Wout);

    // 1) qkv = x @ W_qkv  (fp16x3, 64x128 tiles, absmax fused)
    hgemm2<<<dim3(H3 / 128, M1 / 64), 256, G2_SMEM>>>(
        xh, xl, wqh, wql, qkv_ptr, M1, H3, H_, nullptr, 1, 1);

    // 2-3) quantize
    quant_kernel<<<(3 * PLANE / 4 + 255) / 256, 256>>>();

    // 4-6) fused flash attention (64-query tiles, 2 CTAs/SM)
    flash_kernel<<<dim3(S_ / BQ, B_ * NH), 256, FLASH_SMEM>>>();

    // 7) y = attnout @ W_out + b_out  (fp16x1)
    hgemm2<<<dim3(H_ / 128, M1 / 64), 256, G2_SMEM>>>(
        aoh, nullptr, woh, nullptr, y, M1, H_, H_, bout, 0, 0);
}